// round 1
// baseline (speedup 1.0000x reference)
#include <cuda_runtime.h>
#include <cuda_bf16.h>
#include <cstdint>
#include <cstddef>

// Problem constants
#define CBB 8
#define CSS 4096
#define CDD 512
#define CLL 4
#define CDI 768
#define CFF 2048
#define CMM (CBB*CSS)          // 32768 rows
#define CNC 8                  // scan chunks
#define CCS (CSS/CNC)          // 512 per chunk

// ---------------- scratch (device globals; no allocation allowed) ----------
static __device__ float g_xn [(size_t)CMM*CDD];     // layernorm output
static __device__ float g_hg [(size_t)CMM*2*CDI];   // minGRU pre-activations
static __device__ float g_h  [(size_t)CMM*CDI];     // scan output
static __device__ float g_y  [(size_t)CMM*CDD];     // post-mingru residual stream
static __device__ float g_x  [(size_t)CMM*CDD];     // layer output
static __device__ float g_ffh[(size_t)CMM*CFF];     // ff hidden
static __device__ float g_P    [CBB*CNC*CDI];
static __device__ float g_Hc   [CBB*CNC*CDI];
static __device__ float g_carry[CBB*CNC*CDI];

// ---------------- tf32 mma helpers -----------------------------------------
__device__ __forceinline__ uint32_t f2tf32(float f){
    uint32_t u; asm("cvt.rna.tf32.f32 %0, %1;" : "=r"(u) : "f"(f)); return u;
}

__device__ __forceinline__ void mma_tf32(float (&d)[4], const uint32_t (&a)[4],
                                         const uint32_t (&b)[2]){
    asm volatile(
        "mma.sync.aligned.m16n8k8.row.col.f32.tf32.tf32.f32 "
        "{%0,%1,%2,%3}, {%4,%5,%6,%7}, {%8,%9}, {%0,%1,%2,%3};\n"
        : "+f"(d[0]), "+f"(d[1]), "+f"(d[2]), "+f"(d[3])
        : "r"(a[0]), "r"(a[1]), "r"(a[2]), "r"(a[3]), "r"(b[0]), "r"(b[1]));
}

enum { EPI_NONE=0, EPI_ADD=1, EPI_BIAS_GELU=2, EPI_BIAS_ADD=3 };

// C[M,N] = A[M,K] @ W[N,K]^T, tf32 tensor cores, fp32 accum.
// Tiles: 128x128x16, 256 threads (8 warps = 2x4), warp tile 64x32.
// SMEM row-major [row][k] with +4 pad => conflict-free fragment loads.
template<int EPI>
__global__ __launch_bounds__(256, 2)
void gemm_tf32_kernel(const float* __restrict__ A, const float* __restrict__ W,
                      const float* __restrict__ bias, const float* __restrict__ add,
                      float* __restrict__ C, int M, int N, int K)
{
    __shared__ float As[2][128][20];
    __shared__ float Bs[2][128][20];

    const int bm   = blockIdx.y * 128;
    const int bn   = blockIdx.x * 128;
    const int tid  = threadIdx.x;
    const int lane = tid & 31;
    const int warp = tid >> 5;
    const int wm   = (warp >> 2) * 64;   // warp m offset (2 warps in m)
    const int wn   = (warp & 3) * 32;    // warp n offset (4 warps in n)
    const int g    = lane >> 2;          // groupID
    const int t    = lane & 3;           // threadID_in_group

    const int r0  = tid >> 2;            // load row (0..63), +64 second pass
    const int lc4 = (tid & 3) * 4;       // load k-col (float4 granularity)

    float acc[4][4][4];
    #pragma unroll
    for (int i=0;i<4;i++)
        #pragma unroll
        for (int j=0;j<4;j++)
            #pragma unroll
            for (int k=0;k<4;k++) acc[i][j][k] = 0.0f;

    float4 ra[2], rb[2];

    auto gload = [&](int kt){
        const int k0 = kt*16 + lc4;
        #pragma unroll
        for (int j=0;j<2;j++){
            const int row = r0 + j*64;
            ra[j] = *reinterpret_cast<const float4*>(A + (size_t)(bm+row)*K + k0);
            rb[j] = *reinterpret_cast<const float4*>(W + (size_t)(bn+row)*K + k0);
        }
    };
    auto sstore = [&](int buf){
        #pragma unroll
        for (int j=0;j<2;j++){
            const int row = r0 + j*64;
            *reinterpret_cast<float4*>(&As[buf][row][lc4]) = ra[j];
            *reinterpret_cast<float4*>(&Bs[buf][row][lc4]) = rb[j];
        }
    };
    auto compute = [&](int buf){
        #pragma unroll
        for (int ks=0; ks<16; ks+=8){
            uint32_t bf[4][2];
            #pragma unroll
            for (int ns=0; ns<4; ns++){
                const int n = wn + ns*8;
                bf[ns][0] = f2tf32(Bs[buf][n+g][ks+t  ]);
                bf[ns][1] = f2tf32(Bs[buf][n+g][ks+t+4]);
            }
            #pragma unroll
            for (int ms=0; ms<4; ms++){
                const int m = wm + ms*16;
                uint32_t af[4];
                af[0] = f2tf32(As[buf][m+g  ][ks+t  ]);
                af[1] = f2tf32(As[buf][m+g+8][ks+t  ]);
                af[2] = f2tf32(As[buf][m+g  ][ks+t+4]);
                af[3] = f2tf32(As[buf][m+g+8][ks+t+4]);
                #pragma unroll
                for (int ns=0; ns<4; ns++)
                    mma_tf32(acc[ms][ns], af, bf[ns]);
            }
        }
    };

    gload(0); sstore(0); __syncthreads();
    const int nk = K/16;
    for (int kt=0; kt<nk; kt++){
        const int buf = kt & 1;
        if (kt+1 < nk) gload(kt+1);
        compute(buf);
        if (kt+1 < nk){ sstore(buf^1); __syncthreads(); }
    }

    // epilogue
    #pragma unroll
    for (int ms=0; ms<4; ms++){
        const int rr = bm + wm + ms*16 + g;
        #pragma unroll
        for (int ns=0; ns<4; ns++){
            const int cc = bn + wn + ns*8 + 2*t;
            float v[4] = {acc[ms][ns][0], acc[ms][ns][1], acc[ms][ns][2], acc[ms][ns][3]};
            const int rows[2] = {rr, rr+8};
            #pragma unroll
            for (int h=0; h<2; h++){
                #pragma unroll
                for (int q=0; q<2; q++){
                    float val = v[h*2+q];
                    const int row = rows[h], col = cc + q;
                    if constexpr (EPI == EPI_ADD){
                        val += add[(size_t)row*N + col];
                    } else if constexpr (EPI == EPI_BIAS_GELU){
                        val += bias[col];
                        val = 0.5f * val * (1.0f + erff(val * 0.70710678118654752f));
                    } else if constexpr (EPI == EPI_BIAS_ADD){
                        val += bias[col] + add[(size_t)row*N + col];
                    }
                    v[h*2+q] = val;
                }
                float2 st = make_float2(v[h*2+0], v[h*2+1]);
                *reinterpret_cast<float2*>(C + (size_t)rows[h]*N + cc) = st;
            }
        }
    }
}

// ---------------- layernorm (D=512), one block/row, 128 threads ------------
__global__ void ln_kernel(const float* __restrict__ x, const float* __restrict__ gw,
                          const float* __restrict__ bw, float* __restrict__ y)
{
    const int row = blockIdx.x;
    const int tid = threadIdx.x;
    const float4 v = reinterpret_cast<const float4*>(x + (size_t)row*CDD)[tid];
    float s = (v.x+v.y)+(v.z+v.w);
    float q = v.x*v.x + v.y*v.y + v.z*v.z + v.w*v.w;
    __shared__ float sh[8];
    #pragma unroll
    for (int o=16;o>0;o>>=1){ s += __shfl_down_sync(0xffffffffu,s,o);
                              q += __shfl_down_sync(0xffffffffu,q,o); }
    const int warp = tid>>5, lane = tid&31;
    if (lane==0){ sh[warp]=s; sh[warp+4]=q; }
    __syncthreads();
    if (tid==0){
        float S = sh[0]+sh[1]+sh[2]+sh[3];
        float Q = sh[4]+sh[5]+sh[6]+sh[7];
        float mean = S * (1.0f/CDD);
        float var  = Q * (1.0f/CDD) - mean*mean;
        sh[0] = mean; sh[1] = rsqrtf(var + 1e-5f);
    }
    __syncthreads();
    const float mean = sh[0], rstd = sh[1];
    const float4 gg = reinterpret_cast<const float4*>(gw)[tid];
    const float4 bb = reinterpret_cast<const float4*>(bw)[tid];
    float4 o;
    o.x = (v.x-mean)*rstd*gg.x + bb.x;
    o.y = (v.y-mean)*rstd*gg.y + bb.y;
    o.z = (v.z-mean)*rstd*gg.z + bb.z;
    o.w = (v.w-mean)*rstd*gg.w + bb.w;
    reinterpret_cast<float4*>(y + (size_t)row*CDD)[tid] = o;
}

// ---------------- minGRU chunked scan --------------------------------------
__device__ __forceinline__ void gate_av(float hid, float gt, float& a, float& v){
    const float sg = 1.0f / (1.0f + expf(-gt));   // sigmoid(gate) = exp(-softplus(-g))
    a = 1.0f / (1.0f + expf(gt));                 // sigmoid(-gate) = exp(-softplus(g))
    const float gv = (hid >= 0.0f) ? (hid + 0.5f) : (1.0f / (1.0f + expf(-hid)));
    v = sg * gv;
}

__global__ void scan_phase1(const float* __restrict__ hg, float* __restrict__ P,
                            float* __restrict__ H)
{
    const int e = blockIdx.x*blockDim.x + threadIdx.x;   // 0..CDI-1
    const int c = blockIdx.y, b = blockIdx.z;
    const float* base = hg + ((size_t)b*CSS + (size_t)c*CCS)*(2*CDI);
    float p = 1.0f, hacc = 0.0f;
    #pragma unroll 4
    for (int s=0; s<CCS; s++){
        const float hid = base[(size_t)s*(2*CDI) + e];
        const float gt  = base[(size_t)s*(2*CDI) + CDI + e];
        float a, v; gate_av(hid, gt, a, v);
        hacc = fmaf(a, hacc, v);
        p *= a;
    }
    const int idx = (b*CNC + c)*CDI + e;
    P[idx] = p; H[idx] = hacc;
}

__global__ void scan_phase2(const float* __restrict__ P, const float* __restrict__ H,
                            float* __restrict__ carry)
{
    const int i = blockIdx.x*blockDim.x + threadIdx.x;
    if (i >= CBB*CDI) return;
    const int b = i / CDI, e = i % CDI;
    float T = 0.5f;   // h_0 = exp(log 0.5)
    #pragma unroll
    for (int c=0; c<CNC; c++){
        const int idx = (b*CNC + c)*CDI + e;
        carry[idx] = T;
        T = fmaf(P[idx], T, H[idx]);
    }
}

__global__ void scan_phase3(const float* __restrict__ hg, const float* __restrict__ carry,
                            float* __restrict__ hout)
{
    const int e = blockIdx.x*blockDim.x + threadIdx.x;
    const int c = blockIdx.y, b = blockIdx.z;
    const float* base = hg + ((size_t)b*CSS + (size_t)c*CCS)*(2*CDI);
    float* ob = hout + ((size_t)b*CSS + (size_t)c*CCS)*CDI;
    float h = carry[(b*CNC + c)*CDI + e];
    #pragma unroll 4
    for (int s=0; s<CCS; s++){
        const float hid = base[(size_t)s*(2*CDI) + e];
        const float gt  = base[(size_t)s*(2*CDI) + CDI + e];
        float a, v; gate_av(hid, gt, a, v);
        h = fmaf(a, h, v);
        ob[(size_t)s*CDI + e] = h;
    }
}

// ---------------- final LN + 2-logit head, one block/row, 256 threads ------
__global__ void logits_kernel(const float* __restrict__ x, const float* __restrict__ gw,
                              const float* __restrict__ bw, const float* __restrict__ Wl,
                              float* __restrict__ out)
{
    const int row = blockIdx.x;
    const int tid = threadIdx.x;
    const float2 v = reinterpret_cast<const float2*>(x + (size_t)row*CDD)[tid];
    float s = v.x + v.y;
    float q = v.x*v.x + v.y*v.y;
    __shared__ float sh[16];
    #pragma unroll
    for (int o=16;o>0;o>>=1){ s += __shfl_down_sync(0xffffffffu,s,o);
                              q += __shfl_down_sync(0xffffffffu,q,o); }
    const int warp = tid>>5, lane = tid&31;
    if (lane==0){ sh[warp]=s; sh[warp+8]=q; }
    __syncthreads();
    if (tid==0){
        float S=0.f, Q=0.f;
        #pragma unroll
        for (int w=0;w<8;w++){ S += sh[w]; Q += sh[w+8]; }
        float mean = S*(1.0f/CDD);
        float var  = Q*(1.0f/CDD) - mean*mean;
        sh[0]=mean; sh[1]=rsqrtf(var + 1e-5f);
    }
    __syncthreads();
    const float mean = sh[0], rstd = sh[1];
    __syncthreads();   // sh about to be reused

    const float2 gg = reinterpret_cast<const float2*>(gw)[tid];
    const float2 bb = reinterpret_cast<const float2*>(bw)[tid];
    const float n0 = (v.x-mean)*rstd*gg.x + bb.x;
    const float n1 = (v.y-mean)*rstd*gg.y + bb.y;
    const int c = tid*2;
    float a0 = n0*Wl[c]       + n1*Wl[c+1];
    float a1 = n0*Wl[CDD+c]   + n1*Wl[CDD+c+1];
    #pragma unroll
    for (int o=16;o>0;o>>=1){ a0 += __shfl_down_sync(0xffffffffu,a0,o);
                              a1 += __shfl_down_sync(0xffffffffu,a1,o); }
    if (lane==0){ sh[warp]=a0; sh[warp+8]=a1; }
    __syncthreads();
    if (tid==0){
        float r0=0.f, r1=0.f;
        #pragma unroll
        for (int w=0;w<8;w++){ r0 += sh[w]; r1 += sh[w+8]; }
        out[(size_t)row*2 + 0] = r0;
        out[(size_t)row*2 + 1] = r1;
    }
}

// ---------------- driver ----------------------------------------------------
extern "C" void kernel_launch(void* const* d_in, const int* in_sizes, int n_in,
                              void* d_out, int out_size)
{
    const float* input  = (const float*)d_in[0];
    const float* Whg    = (const float*)d_in[1];
    const float* Wout   = (const float*)d_in[2];
    const float* ln1_g  = (const float*)d_in[3];
    const float* ln1_b  = (const float*)d_in[4];
    const float* ln2_g  = (const float*)d_in[5];
    const float* ln2_b  = (const float*)d_in[6];
    const float* ffW1   = (const float*)d_in[7];
    const float* ffb1   = (const float*)d_in[8];
    const float* ffW2   = (const float*)d_in[9];
    const float* ffb2   = (const float*)d_in[10];
    const float* norm_g = (const float*)d_in[11];
    const float* norm_b = (const float*)d_in[12];
    const float* Wlog   = (const float*)d_in[13];
    float* out = (float*)d_out;

    float *xn, *hg, *h, *y, *x, *ffh, *P, *Hc, *carry;
    cudaGetSymbolAddress((void**)&xn,    g_xn);
    cudaGetSymbolAddress((void**)&hg,    g_hg);
    cudaGetSymbolAddress((void**)&h,     g_h);
    cudaGetSymbolAddress((void**)&y,     g_y);
    cudaGetSymbolAddress((void**)&x,     g_x);
    cudaGetSymbolAddress((void**)&ffh,   g_ffh);
    cudaGetSymbolAddress((void**)&P,     g_P);
    cudaGetSymbolAddress((void**)&Hc,    g_Hc);
    cudaGetSymbolAddress((void**)&carry, g_carry);

    const int M = CMM;
    const dim3 scan_grid(CDI/256, CNC, CBB);

    for (int i=0; i<CLL; i++){
        const float* cur = (i==0) ? input : x;

        // ln1
        ln_kernel<<<M, 128>>>(cur, ln1_g + i*CDD, ln1_b + i*CDD, xn);
        // hg = ln1(x) @ Whg^T   [M, 1536]
        gemm_tf32_kernel<EPI_NONE><<<dim3(2*CDI/128, M/128), 256>>>(
            xn, Whg + (size_t)i*2*CDI*CDD, nullptr, nullptr, hg, M, 2*CDI, CDD);
        // heinsen scan -> h [M, 768]
        scan_phase1<<<scan_grid, 256>>>(hg, P, Hc);
        scan_phase2<<<(CBB*CDI + 255)/256, 256>>>(P, Hc, carry);
        scan_phase3<<<scan_grid, 256>>>(hg, carry, h);
        // y = h @ Wout^T + x    [M, 512]
        gemm_tf32_kernel<EPI_ADD><<<dim3(CDD/128, M/128), 256>>>(
            h, Wout + (size_t)i*CDD*CDI, nullptr, cur, y, M, CDD, CDI);
        // ln2
        ln_kernel<<<M, 128>>>(y, ln2_g + i*CDD, ln2_b + i*CDD, xn);
        // ffh = gelu(ln2(y) @ ffW1^T + b1)   [M, 2048]
        gemm_tf32_kernel<EPI_BIAS_GELU><<<dim3(CFF/128, M/128), 256>>>(
            xn, ffW1 + (size_t)i*CFF*CDD, ffb1 + i*CFF, nullptr, ffh, M, CFF, CDD);
        // x = ffh @ ffW2^T + b2 + y          [M, 512]
        gemm_tf32_kernel<EPI_BIAS_ADD><<<dim3(CDD/128, M/128), 256>>>(
            ffh, ffW2 + (size_t)i*CDD*CFF, ffb2 + i*CDD, y, x, M, CDD, CFF);
    }

    // final layernorm + logits
    logits_kernel<<<M, 256>>>(x, norm_g, norm_b, Wlog, out);
}

// round 3
// speedup vs baseline: 1.2620x; 1.2620x over previous
#include <cuda_runtime.h>
#include <cuda_bf16.h>
#include <cstdint>
#include <cstddef>

// Problem constants
#define CBB 8
#define CSS 4096
#define CDD 512
#define CLL 4
#define CDI 768
#define CFF 2048
#define CMM (CBB*CSS)          // 32768 rows
#define CNC 16                 // scan chunks
#define CCS (CSS/CNC)          // 256 per chunk

// weight scratch sizes (floats)
#define W_HG_SZ  ((size_t)CLL*2*CDI*CDD)
#define W_OUT_SZ ((size_t)CLL*CDD*CDI)
#define W_F1_SZ  ((size_t)CLL*CFF*CDD)
#define W_F2_SZ  ((size_t)CLL*CDD*CFF)

// ---------------- scratch (device globals; no allocation allowed) ----------
static __device__ float g_xn [(size_t)CMM*CDD];     // layernorm output (tf32-rounded)
static __device__ float g_hg [(size_t)CMM*2*CDI];   // minGRU pre-activations
static __device__ float g_h  [(size_t)CMM*CDI];     // scan output (tf32-rounded)
static __device__ float g_y  [(size_t)CMM*CDD];     // post-mingru residual stream
static __device__ float g_x  [(size_t)CMM*CDD];     // layer output
static __device__ float g_ffh[(size_t)CMM*CFF];     // ff hidden (tf32-rounded)
static __device__ float g_P  [CBB*CNC*CDI];
static __device__ float g_Hc [CBB*CNC*CDI];
static __device__ float g_wtf[W_HG_SZ + W_OUT_SZ + W_F1_SZ + W_F2_SZ];  // rounded weights

// ---------------- tf32 helpers ---------------------------------------------
__device__ __forceinline__ uint32_t f2tf32(float f){
    uint32_t u; asm("cvt.rna.tf32.f32 %0, %1;" : "=r"(u) : "f"(f)); return u;
}
__device__ __forceinline__ float rtf32(float f){ return __uint_as_float(f2tf32(f)); }

__device__ __forceinline__ void mma_tf32(float (&d)[4], const uint32_t (&a)[4],
                                         const uint32_t (&b)[2]){
    asm volatile(
        "mma.sync.aligned.m16n8k8.row.col.f32.tf32.tf32.f32 "
        "{%0,%1,%2,%3}, {%4,%5,%6,%7}, {%8,%9}, {%0,%1,%2,%3};\n"
        : "+f"(d[0]), "+f"(d[1]), "+f"(d[2]), "+f"(d[3])
        : "r"(a[0]), "r"(a[1]), "r"(a[2]), "r"(a[3]), "r"(b[0]), "r"(b[1]));
}

enum { EPI_NONE=0, EPI_ADD=1, EPI_BIAS_GELU=2, EPI_BIAS_ADD=3 };

// ---------------- weight prepass: round to tf32 (vectorized) ----------------
__global__ void wconv2(const float4* __restrict__ s1, int n1,   // counts in float4
                       const float4* __restrict__ s2, int n2,
                       float4* __restrict__ d1, float4* __restrict__ d2)
{
    const int gid = blockIdx.x*blockDim.x + threadIdx.x;
    const int stride = gridDim.x*blockDim.x;
    for (int i=gid; i<n1; i+=stride){
        float4 v = s1[i];
        v.x = rtf32(v.x); v.y = rtf32(v.y); v.z = rtf32(v.z); v.w = rtf32(v.w);
        d1[i] = v;
    }
    for (int i=gid; i<n2; i+=stride){
        float4 v = s2[i];
        v.x = rtf32(v.x); v.y = rtf32(v.y); v.z = rtf32(v.z); v.w = rtf32(v.w);
        d2[i] = v;
    }
}

// ---------------- GEMM v2: fragment-major smem, zero in-loop cvt ------------
// C[M,N] = A[M,K] @ W[N,K]^T. Operands are pre-rounded tf32 bit patterns.
// CTA 128x128x16, 256 thr (8 warps 2m x 4n), warp tile 64x32.
//
// A smem: 16 subtiles (mt 0..7, slab 0..1) x 32 16B-units. Unit for fragment
// lane p: u = p ^ (slab<<1) ^ ((p>>4)&1). Words within unit = af[0..3].
// B smem: 32 subtiles (nt 0..15, slab 0..1) x 32 8B-units, same swizzle,
// words = bf[0..1].
template<int EPI>
__global__ __launch_bounds__(256, 2)
void gemm_tf32_v2(const float* __restrict__ A, const float* __restrict__ W,
                  const float* __restrict__ bias, const float* __restrict__ add,
                  float* __restrict__ C, int M, int N, int K)
{
    __shared__ float As[2][2048];
    __shared__ float Bs[2][2048];

    const int bm   = blockIdx.y * 128;
    const int bn   = blockIdx.x * 128;
    const int tid  = threadIdx.x;
    const int lane = tid & 31;
    const int warp = tid >> 5;
    const int wm   = (warp >> 2) * 64;
    const int wn   = (warp & 3) * 32;
    const int g    = lane >> 2;
    const int t    = lane & 3;
    const int ph   = (lane >> 4) & 1;

    // global-load / smem-store mapping
    const int r0    = tid >> 2;          // 0..63, +64 second pass
    const int lc    = (tid & 3) * 4;     // k within tile: 0,4,8,12
    const int slabS = lc >> 3;
    const int khS   = (lc >> 2) & 1;

    float acc[4][4][4];
    #pragma unroll
    for (int i=0;i<4;i++)
        #pragma unroll
        for (int j=0;j<4;j++)
            #pragma unroll
            for (int k=0;k<4;k++) acc[i][j][k] = 0.0f;

    float4 ra[2], rb[2];

    auto gload = [&](int kt){
        const int k0 = kt*16 + lc;
        #pragma unroll
        for (int jj=0;jj<2;jj++){
            const int row = r0 + jj*64;
            ra[jj] = *reinterpret_cast<const float4*>(A + (size_t)(bm+row)*K + k0);
            rb[jj] = *reinterpret_cast<const float4*>(W + (size_t)(bn+row)*K + k0);
        }
    };
    auto sstore = [&](int buf){
        #pragma unroll
        for (int jj=0;jj<2;jj++){
            const int row = r0 + jj*64;
            const int pb  = (row & 7) << 2;
            const int px  = (slabS << 1) ^ ((pb >> 4) & 1);
            // A: subtile (row>>4, slabS), 4 words per 16B unit
            {
                const int regA = ((row >> 3) & 1) + 2*khS;
                float* base = &As[buf][(( (row>>4)*2 + slabS )*32) * 4];
                const float v[4] = {ra[jj].x, ra[jj].y, ra[jj].z, ra[jj].w};
                #pragma unroll
                for (int j=0;j<4;j++)
                    base[((pb|j) ^ px)*4 + regA] = v[j];
            }
            // B: subtile (row>>3, slabS), 2 words per 8B unit
            {
                float* base = &Bs[buf][(( (row>>3)*2 + slabS )*32) * 2];
                const float v[4] = {rb[jj].x, rb[jj].y, rb[jj].z, rb[jj].w};
                #pragma unroll
                for (int j=0;j<4;j++)
                    base[((pb|j) ^ px)*2 + khS] = v[j];
            }
        }
    };
    auto compute = [&](int buf){
        #pragma unroll
        for (int slab=0; slab<2; slab++){
            const int rx = (slab << 1) ^ ph;
            uint32_t bfr[4][2];
            #pragma unroll
            for (int ns=0; ns<4; ns++){
                const int nt = (wn >> 3) + ns;
                const float2 bv = *reinterpret_cast<const float2*>(
                    &Bs[buf][((nt*2 + slab)*32 + (lane ^ rx)) * 2]);
                bfr[ns][0] = __float_as_uint(bv.x);
                bfr[ns][1] = __float_as_uint(bv.y);
            }
            #pragma unroll
            for (int ms=0; ms<4; ms++){
                const int mt = (wm >> 4) + ms;
                const float4 av = *reinterpret_cast<const float4*>(
                    &As[buf][((mt*2 + slab)*32 + (lane ^ rx)) * 4]);
                const uint32_t afr[4] = {__float_as_uint(av.x), __float_as_uint(av.y),
                                         __float_as_uint(av.z), __float_as_uint(av.w)};
                #pragma unroll
                for (int ns=0; ns<4; ns++)
                    mma_tf32(acc[ms][ns], afr, bfr[ns]);
            }
        }
    };

    gload(0); sstore(0); __syncthreads();
    const int nk = K >> 4;
    for (int kt=0; kt<nk; kt++){
        const int buf = kt & 1;
        if (kt+1 < nk) gload(kt+1);
        compute(buf);
        if (kt+1 < nk){ sstore(buf^1); __syncthreads(); }
    }

    // epilogue
    #pragma unroll
    for (int ms=0; ms<4; ms++){
        const int rr = bm + wm + ms*16 + g;
        #pragma unroll
        for (int ns=0; ns<4; ns++){
            const int cc = bn + wn + ns*8 + 2*t;
            float v[4] = {acc[ms][ns][0], acc[ms][ns][1], acc[ms][ns][2], acc[ms][ns][3]};
            const int rows[2] = {rr, rr+8};
            #pragma unroll
            for (int h=0; h<2; h++){
                #pragma unroll
                for (int q=0; q<2; q++){
                    float val = v[h*2+q];
                    const int row = rows[h], col = cc + q;
                    if constexpr (EPI == EPI_ADD){
                        val += add[(size_t)row*N + col];
                    } else if constexpr (EPI == EPI_BIAS_GELU){
                        val += bias[col];
                        val = 0.5f * val * (1.0f + erff(val * 0.70710678118654752f));
                        val = rtf32(val);          // feeds next GEMM as A
                    } else if constexpr (EPI == EPI_BIAS_ADD){
                        val += bias[col] + add[(size_t)row*N + col];
                    }
                    v[h*2+q] = val;
                }
                float2 st = make_float2(v[h*2+0], v[h*2+1]);
                *reinterpret_cast<float2*>(C + (size_t)rows[h]*N + cc) = st;
            }
        }
    }
}

// ---------------- layernorm (D=512), one block/row, 128 threads ------------
// Output is tf32-rounded (always feeds a GEMM A operand).
__global__ void ln_kernel(const float* __restrict__ x, const float* __restrict__ gw,
                          const float* __restrict__ bw, float* __restrict__ y)
{
    const int row = blockIdx.x;
    const int tid = threadIdx.x;
    const float4 v = reinterpret_cast<const float4*>(x + (size_t)row*CDD)[tid];
    float s = (v.x+v.y)+(v.z+v.w);
    float q = v.x*v.x + v.y*v.y + v.z*v.z + v.w*v.w;
    __shared__ float sh[8];
    #pragma unroll
    for (int o=16;o>0;o>>=1){ s += __shfl_down_sync(0xffffffffu,s,o);
                              q += __shfl_down_sync(0xffffffffu,q,o); }
    const int warp = tid>>5, lane = tid&31;
    if (lane==0){ sh[warp]=s; sh[warp+4]=q; }
    __syncthreads();
    if (tid==0){
        float S = sh[0]+sh[1]+sh[2]+sh[3];
        float Q = sh[4]+sh[5]+sh[6]+sh[7];
        float mean = S * (1.0f/CDD);
        float var  = Q * (1.0f/CDD) - mean*mean;
        sh[0] = mean; sh[1] = rsqrtf(var + 1e-5f);
    }
    __syncthreads();
    const float mean = sh[0], rstd = sh[1];
    const float4 gg = reinterpret_cast<const float4*>(gw)[tid];
    const float4 bb = reinterpret_cast<const float4*>(bw)[tid];
    float4 o;
    o.x = rtf32((v.x-mean)*rstd*gg.x + bb.x);
    o.y = rtf32((v.y-mean)*rstd*gg.y + bb.y);
    o.z = rtf32((v.z-mean)*rstd*gg.z + bb.z);
    o.w = rtf32((v.w-mean)*rstd*gg.w + bb.w);
    reinterpret_cast<float4*>(y + (size_t)row*CDD)[tid] = o;
}

// ---------------- minGRU chunked scan --------------------------------------
__device__ __forceinline__ void gate_av(float hid, float gt, float& a, float& v){
    const float sg = 1.0f / (1.0f + expf(-gt));   // sigmoid(gate)
    a = 1.0f / (1.0f + expf(gt));                 // sigmoid(-gate) = 1 - z
    const float gv = (hid >= 0.0f) ? (hid + 0.5f) : (1.0f / (1.0f + expf(-hid)));
    v = sg * gv;
}

__global__ void scan_phase1(const float* __restrict__ hg, float* __restrict__ P,
                            float* __restrict__ H)
{
    const int e = blockIdx.x*128 + threadIdx.x;          // 0..CDI-1
    const int c = blockIdx.y, b = blockIdx.z;
    const float* base = hg + ((size_t)b*CSS + (size_t)c*CCS)*(2*CDI);
    float p = 1.0f, hacc = 0.0f;
    #pragma unroll 4
    for (int s=0; s<CCS; s++){
        const float hid = base[(size_t)s*(2*CDI) + e];
        const float gt  = base[(size_t)s*(2*CDI) + CDI + e];
        float a, v; gate_av(hid, gt, a, v);
        hacc = fmaf(a, hacc, v);
        p *= a;
    }
    const int idx = (b*CNC + c)*CDI + e;
    P[idx] = p; H[idx] = hacc;
}

// phase3 with fused carry computation (former phase2). Output tf32-rounded.
__global__ void scan_phase3(const float* __restrict__ hg, const float* __restrict__ P,
                            const float* __restrict__ H, float* __restrict__ hout)
{
    const int e = blockIdx.x*128 + threadIdx.x;
    const int c = blockIdx.y, b = blockIdx.z;
    float h = 0.5f;                                      // h_0
    for (int cc=0; cc<c; cc++){
        const int idx = (b*CNC + cc)*CDI + e;
        h = fmaf(P[idx], h, H[idx]);
    }
    const float* base = hg + ((size_t)b*CSS + (size_t)c*CCS)*(2*CDI);
    float* ob = hout + ((size_t)b*CSS + (size_t)c*CCS)*CDI;
    #pragma unroll 4
    for (int s=0; s<CCS; s++){
        const float hid = base[(size_t)s*(2*CDI) + e];
        const float gt  = base[(size_t)s*(2*CDI) + CDI + e];
        float a, v; gate_av(hid, gt, a, v);
        h = fmaf(a, h, v);
        ob[(size_t)s*CDI + e] = rtf32(h);
    }
}

// ---------------- final LN + 2-logit head, one block/row, 256 threads ------
__global__ void logits_kernel(const float* __restrict__ x, const float* __restrict__ gw,
                              const float* __restrict__ bw, const float* __restrict__ Wl,
                              float* __restrict__ out)
{
    const int row = blockIdx.x;
    const int tid = threadIdx.x;
    const float2 v = reinterpret_cast<const float2*>(x + (size_t)row*CDD)[tid];
    float s = v.x + v.y;
    float q = v.x*v.x + v.y*v.y;
    __shared__ float sh[16];
    #pragma unroll
    for (int o=16;o>0;o>>=1){ s += __shfl_down_sync(0xffffffffu,s,o);
                              q += __shfl_down_sync(0xffffffffu,q,o); }
    const int warp = tid>>5, lane = tid&31;
    if (lane==0){ sh[warp]=s; sh[warp+8]=q; }
    __syncthreads();
    if (tid==0){
        float S=0.f, Q=0.f;
        #pragma unroll
        for (int w=0;w<8;w++){ S += sh[w]; Q += sh[w+8]; }
        float mean = S*(1.0f/CDD);
        float var  = Q*(1.0f/CDD) - mean*mean;
        sh[0]=mean; sh[1]=rsqrtf(var + 1e-5f);
    }
    __syncthreads();
    const float mean = sh[0], rstd = sh[1];
    __syncthreads();

    const float2 gg = reinterpret_cast<const float2*>(gw)[tid];
    const float2 bb = reinterpret_cast<const float2*>(bw)[tid];
    const float n0 = (v.x-mean)*rstd*gg.x + bb.x;
    const float n1 = (v.y-mean)*rstd*gg.y + bb.y;
    const int c = tid*2;
    float a0 = n0*Wl[c]       + n1*Wl[c+1];
    float a1 = n0*Wl[CDD+c]   + n1*Wl[CDD+c+1];
    #pragma unroll
    for (int o=16;o>0;o>>=1){ a0 += __shfl_down_sync(0xffffffffu,a0,o);
                              a1 += __shfl_down_sync(0xffffffffu,a1,o); }
    if (lane==0){ sh[warp]=a0; sh[warp+8]=a1; }
    __syncthreads();
    if (tid==0){
        float r0=0.f, r1=0.f;
        #pragma unroll
        for (int w=0;w<8;w++){ r0 += sh[w]; r1 += sh[w+8]; }
        out[(size_t)row*2 + 0] = r0;
        out[(size_t)row*2 + 1] = r1;
    }
}

// ---------------- driver ----------------------------------------------------
extern "C" void kernel_launch(void* const* d_in, const int* in_sizes, int n_in,
                              void* d_out, int out_size)
{
    const float* input  = (const float*)d_in[0];
    const float* Whg    = (const float*)d_in[1];
    const float* Wout   = (const float*)d_in[2];
    const float* ln1_g  = (const float*)d_in[3];
    const float* ln1_b  = (const float*)d_in[4];
    const float* ln2_g  = (const float*)d_in[5];
    const float* ln2_b  = (const float*)d_in[6];
    const float* ffW1   = (const float*)d_in[7];
    const float* ffb1   = (const float*)d_in[8];
    const float* ffW2   = (const float*)d_in[9];
    const float* ffb2   = (const float*)d_in[10];
    const float* norm_g = (const float*)d_in[11];
    const float* norm_b = (const float*)d_in[12];
    const float* Wlog   = (const float*)d_in[13];
    float* out = (float*)d_out;

    float *xn, *hg, *h, *y, *x, *ffh, *P, *Hc, *wtf;
    cudaGetSymbolAddress((void**)&xn,  g_xn);
    cudaGetSymbolAddress((void**)&hg,  g_hg);
    cudaGetSymbolAddress((void**)&h,   g_h);
    cudaGetSymbolAddress((void**)&y,   g_y);
    cudaGetSymbolAddress((void**)&x,   g_x);
    cudaGetSymbolAddress((void**)&ffh, g_ffh);
    cudaGetSymbolAddress((void**)&P,   g_P);
    cudaGetSymbolAddress((void**)&Hc,  g_Hc);
    cudaGetSymbolAddress((void**)&wtf, g_wtf);

    float* w_hg  = wtf;
    float* w_out = w_hg  + W_HG_SZ;
    float* w_f1  = w_out + W_OUT_SZ;
    float* w_f2  = w_f1  + W_F1_SZ;

    // weight prepass: round all weights to tf32 (2 launches)
    wconv2<<<1024, 256>>>((const float4*)Whg,  (int)(W_HG_SZ/4),
                          (const float4*)Wout, (int)(W_OUT_SZ/4),
                          (float4*)w_hg, (float4*)w_out);
    wconv2<<<1024, 256>>>((const float4*)ffW1, (int)(W_F1_SZ/4),
                          (const float4*)ffW2, (int)(W_F2_SZ/4),
                          (float4*)w_f1, (float4*)w_f2);

    const int M = CMM;
    const dim3 scan_grid(CDI/128, CNC, CBB);

    for (int i=0; i<CLL; i++){
        const float* cur = (i==0) ? input : x;

        ln_kernel<<<M, 128>>>(cur, ln1_g + i*CDD, ln1_b + i*CDD, xn);
        gemm_tf32_v2<EPI_NONE><<<dim3(2*CDI/128, M/128), 256>>>(
            xn, w_hg + (size_t)i*2*CDI*CDD, nullptr, nullptr, hg, M, 2*CDI, CDD);
        scan_phase1<<<scan_grid, 128>>>(hg, P, Hc);
        scan_phase3<<<scan_grid, 128>>>(hg, P, Hc, h);
        gemm_tf32_v2<EPI_ADD><<<dim3(CDD/128, M/128), 256>>>(
            h, w_out + (size_t)i*CDD*CDI, nullptr, cur, y, M, CDD, CDI);
        ln_kernel<<<M, 128>>>(y, ln2_g + i*CDD, ln2_b + i*CDD, xn);
        gemm_tf32_v2<EPI_BIAS_GELU><<<dim3(CFF/128, M/128), 256>>>(
            xn, w_f1 + (size_t)i*CFF*CDD, ffb1 + i*CFF, nullptr, ffh, M, CFF, CDD);
        gemm_tf32_v2<EPI_BIAS_ADD><<<dim3(CDD/128, M/128), 256>>>(
            ffh, w_f2 + (size_t)i*CDD*CFF, ffb2 + i*CDD, y, x, M, CDD, CFF);
    }

    logits_kernel<<<M, 256>>>(x, norm_g, norm_b, Wlog, out);
}

// round 5
// speedup vs baseline: 1.5710x; 1.2448x over previous
#include <cuda_runtime.h>
#include <cstdint>
#include <cstddef>

// Problem constants
#define CBB 8
#define CSS 4096
#define CDD 512
#define CLL 4
#define CDI 768
#define CFF 2048
#define CMM (CBB*CSS)          // 32768 rows
#define CNC 16                 // scan chunks
#define CCS (CSS/CNC)          // 256 per chunk

// weight scratch sizes (floats)
#define W_HG_SZ  ((size_t)CLL*2*CDI*CDD)
#define W_OUT_SZ ((size_t)CLL*CDD*CDI)
#define W_F1_SZ  ((size_t)CLL*CFF*CDD)
#define W_F2_SZ  ((size_t)CLL*CDD*CFF)

// GEMM tiling: CTA 128(M) x 256(N), 8 warps (2m x 4n), warp tile 64x64.
// K staged 32 floats (128B rows, 8x16B chunks, swizzle c ^ (row&7)).
#define GMT 128
#define GNT 256
#define KC  32
#define NST 3
#define STG_A 16384                      // 128 rows * 128B
#define STG_B 32768                      // 256 rows * 128B
#define STG_BYTES (STG_A + STG_B)        // 49152
#define SMEM_DYN (NST*STG_BYTES)         // 147456

// ---------------- scratch (device globals; no allocation allowed) ----------
static __device__ __align__(256) float g_xn [(size_t)CMM*CDD];
static __device__ __align__(256) float g_hg [(size_t)CMM*2*CDI];
static __device__ __align__(256) float g_h  [(size_t)CMM*CDI];
static __device__ __align__(256) float g_y  [(size_t)CMM*CDD];
static __device__ __align__(256) float g_x  [(size_t)CMM*CDD];
static __device__ __align__(256) float g_ffh[(size_t)CMM*CFF];
static __device__ __align__(256) float g_P  [CBB*CNC*CDI];
static __device__ __align__(256) float g_Hc [CBB*CNC*CDI];
static __device__ __align__(256) float g_wtf[W_HG_SZ + W_OUT_SZ + W_F1_SZ + W_F2_SZ];

// ---------------- helpers ----------------------------------------------------
__device__ __forceinline__ uint32_t f2tf32(float f){
    uint32_t u; asm("cvt.rna.tf32.f32 %0, %1;" : "=r"(u) : "f"(f)); return u;
}
__device__ __forceinline__ float rtf32(float f){ return __uint_as_float(f2tf32(f)); }

__device__ __forceinline__ uint32_t smem_u32(const void* p){
    uint32_t a;
    asm("{ .reg .u64 t; cvta.to.shared.u64 t, %1; cvt.u32.u64 %0, t; }"
        : "=r"(a) : "l"(p));
    return a;
}
__device__ __forceinline__ void cp16(uint32_t saddr, const void* g){
    asm volatile("cp.async.cg.shared.global [%0], [%1], 16;"
                 :: "r"(saddr), "l"(g) : "memory");
}
__device__ __forceinline__ void cp_commit(){
    asm volatile("cp.async.commit_group;" ::: "memory");
}
__device__ __forceinline__ void cp_wait1(){
    asm volatile("cp.async.wait_group 1;" ::: "memory");
}
__device__ __forceinline__ void cp_wait0(){
    asm volatile("cp.async.wait_group 0;" ::: "memory");
}
__device__ __forceinline__ void ldsm_x4(uint32_t& r0, uint32_t& r1, uint32_t& r2,
                                        uint32_t& r3, uint32_t addr){
    asm volatile("ldmatrix.sync.aligned.m8n8.x4.shared.b16 {%0,%1,%2,%3}, [%4];"
                 : "=r"(r0), "=r"(r1), "=r"(r2), "=r"(r3) : "r"(addr));
}
__device__ __forceinline__ void mma_tf32(float (&d)[4], const uint32_t (&a)[4],
                                         const uint32_t (&b)[2]){
    asm volatile(
        "mma.sync.aligned.m16n8k8.row.col.f32.tf32.tf32.f32 "
        "{%0,%1,%2,%3}, {%4,%5,%6,%7}, {%8,%9}, {%0,%1,%2,%3};\n"
        : "+f"(d[0]), "+f"(d[1]), "+f"(d[2]), "+f"(d[3])
        : "r"(a[0]), "r"(a[1]), "r"(a[2]), "r"(a[3]), "r"(b[0]), "r"(b[1]));
}

enum { EPI_NONE=0, EPI_ADD=1, EPI_BIAS_GELU=2, EPI_BIAS_ADD=3 };

// ---------------- weight prepass: round to tf32 ------------------------------
__global__ void wconv2(const float4* __restrict__ s1, int n1,
                       const float4* __restrict__ s2, int n2,
                       float4* __restrict__ d1, float4* __restrict__ d2)
{
    const int gid = blockIdx.x*blockDim.x + threadIdx.x;
    const int stride = gridDim.x*blockDim.x;
    for (int i=gid; i<n1; i+=stride){
        float4 v = s1[i];
        v.x = rtf32(v.x); v.y = rtf32(v.y); v.z = rtf32(v.z); v.w = rtf32(v.w);
        d1[i] = v;
    }
    for (int i=gid; i<n2; i+=stride){
        float4 v = s2[i];
        v.x = rtf32(v.x); v.y = rtf32(v.y); v.z = rtf32(v.z); v.w = rtf32(v.w);
        d2[i] = v;
    }
}

// ---------------- GEMM v3: mma.sync + ldmatrix + cp.async ring ---------------
// C[M,N] = A[M,K] @ W[N,K]^T. Operands are pre-rounded tf32 bit patterns.
template<int EPI>
__global__ __launch_bounds__(256, 1)
void gemm_v3(const float* __restrict__ A, const float* __restrict__ W,
             const float* __restrict__ bias, const float* __restrict__ add,
             float* __restrict__ C, int M, int N, int K)
{
    extern __shared__ __align__(1024) char smem[];
    const uint32_t sb = smem_u32(smem);
    const int tid  = threadIdx.x;
    const int lane = tid & 31;
    const int warp = tid >> 5;
    const int wm   = (warp >> 2) * 64;     // warp M offset (2 warps)
    const int wn   = (warp & 3) * 64;      // warp N offset (4 warps)
    const int g    = lane >> 2;
    const int t    = lane & 3;
    const int bm = blockIdx.y * GMT;
    const int bn = blockIdx.x * GNT;

    // per-lane ldmatrix row/chunk selectors
    const int rowsel = lane & 7;
    const int rowA   = rowsel + ((lane >> 3) & 1) * 8;   // mats 0,1 -> +0; 2,3 -> k+4
    const int chA    = (lane >> 4) & 1;
    const int rowB   = rowsel + ((lane >> 4) & 1) * 8;   // mats 2,3 -> n+8
    const int chB    = (lane >> 3) & 1;                  // mats 1,3 -> k+4

    float acc[4][8][4];
    #pragma unroll
    for (int i=0;i<4;i++)
        #pragma unroll
        for (int j=0;j<8;j++)
            #pragma unroll
            for (int k=0;k<4;k++) acc[i][j][k] = 0.0f;

    auto load_stage = [&](int s){
        const int slot = s % NST;
        const uint32_t sA = sb + (uint32_t)slot*STG_BYTES;
        const uint32_t sB = sA + STG_A;
        const int k0 = s * KC;
        #pragma unroll
        for (int i=0;i<4;i++){                       // A: 1024 chunks
            const int q = tid + i*256;
            const int row = q >> 3, c = q & 7;
            cp16(sA + (uint32_t)(row*8 + (c ^ (row & 7)))*16u,
                 A + (size_t)(bm+row)*K + k0 + c*4);
        }
        #pragma unroll
        for (int i=0;i<8;i++){                       // B: 2048 chunks
            const int q = tid + i*256;
            const int row = q >> 3, c = q & 7;
            cp16(sB + (uint32_t)(row*8 + (c ^ (row & 7)))*16u,
                 W + (size_t)(bn+row)*K + k0 + c*4);
        }
    };

    auto compute = [&](int slot){
        const uint32_t sA = sb + (uint32_t)slot*STG_BYTES;
        const uint32_t sB = sA + STG_A;
        #pragma unroll
        for (int slab=0; slab<4; slab++){            // 4 x (K=8) per stage
            const uint32_t ab = sA +
                (uint32_t)((wm + rowA)*8 + (((slab<<1)|chA) ^ rowsel))*16u;
            const uint32_t bb = sB +
                (uint32_t)((wn + rowB)*8 + (((slab<<1)|chB) ^ rowsel))*16u;
            uint32_t Bf[8][2];
            #pragma unroll
            for (int n2=0; n2<4; n2++)
                ldsm_x4(Bf[2*n2][0], Bf[2*n2][1], Bf[2*n2+1][0], Bf[2*n2+1][1],
                        bb + n2*2048);
            #pragma unroll
            for (int ms=0; ms<4; ms++){
                uint32_t a[4];
                ldsm_x4(a[0], a[1], a[2], a[3], ab + ms*2048);
                #pragma unroll
                for (int ns=0; ns<8; ns++)
                    mma_tf32(acc[ms][ns], a, Bf[ns]);
            }
        }
    };

    const int nk = K / KC;                           // >= 16 for all shapes
    load_stage(0); cp_commit();
    load_stage(1); cp_commit();
    for (int kt=0; kt<nk; kt++){
        cp_wait1();                                  // stage kt landed
        __syncthreads();                             // visible to all warps
        if (kt+2 < nk) load_stage(kt+2);             // overwrites slot (kt-1)%3
        cp_commit();                                 // (possibly empty group)
        compute(kt % NST);
    }
    cp_wait0();

    // ---------------- epilogue ----------------
    #pragma unroll
    for (int ms=0; ms<4; ms++){
        const int rr = bm + wm + ms*16 + g;
        #pragma unroll
        for (int ns=0; ns<8; ns++){
            const int cc = bn + wn + ns*8 + 2*t;
            float v[4] = {acc[ms][ns][0], acc[ms][ns][1],
                          acc[ms][ns][2], acc[ms][ns][3]};
            const int rows[2] = {rr, rr+8};
            #pragma unroll
            for (int h=0; h<2; h++){
                #pragma unroll
                for (int q=0; q<2; q++){
                    float val = v[h*2+q];
                    const int row = rows[h], col = cc + q;
                    if constexpr (EPI == EPI_ADD){
                        val += add[(size_t)row*N + col];
                    } else if constexpr (EPI == EPI_BIAS_GELU){
                        val += bias[col];
                        val = 0.5f * val * (1.0f + erff(val * 0.70710678118654752f));
                        val = rtf32(val);            // feeds next GEMM as A
                    } else if constexpr (EPI == EPI_BIAS_ADD){
                        val += bias[col] + add[(size_t)row*N + col];
                    }
                    v[h*2+q] = val;
                }
                *reinterpret_cast<float2*>(C + (size_t)rows[h]*N + cc) =
                    make_float2(v[h*2+0], v[h*2+1]);
            }
        }
    }
}

// ---------------- layernorm (D=512), one block/row, 128 threads ------------
__global__ void ln_kernel(const float* __restrict__ x, const float* __restrict__ gw,
                          const float* __restrict__ bw, float* __restrict__ y)
{
    const int row = blockIdx.x;
    const int tid = threadIdx.x;
    const float4 v = reinterpret_cast<const float4*>(x + (size_t)row*CDD)[tid];
    float s = (v.x+v.y)+(v.z+v.w);
    float q = v.x*v.x + v.y*v.y + v.z*v.z + v.w*v.w;
    __shared__ float sh[8];
    #pragma unroll
    for (int o=16;o>0;o>>=1){ s += __shfl_down_sync(0xffffffffu,s,o);
                              q += __shfl_down_sync(0xffffffffu,q,o); }
    const int warp = tid>>5, lane = tid&31;
    if (lane==0){ sh[warp]=s; sh[warp+4]=q; }
    __syncthreads();
    if (tid==0){
        float S = sh[0]+sh[1]+sh[2]+sh[3];
        float Q = sh[4]+sh[5]+sh[6]+sh[7];
        float mean = S * (1.0f/CDD);
        float var  = Q * (1.0f/CDD) - mean*mean;
        sh[0] = mean; sh[1] = rsqrtf(var + 1e-5f);
    }
    __syncthreads();
    const float mean = sh[0], rstd = sh[1];
    const float4 gg = reinterpret_cast<const float4*>(gw)[tid];
    const float4 bb = reinterpret_cast<const float4*>(bw)[tid];
    float4 o;
    o.x = rtf32((v.x-mean)*rstd*gg.x + bb.x);
    o.y = rtf32((v.y-mean)*rstd*gg.y + bb.y);
    o.z = rtf32((v.z-mean)*rstd*gg.z + bb.z);
    o.w = rtf32((v.w-mean)*rstd*gg.w + bb.w);
    reinterpret_cast<float4*>(y + (size_t)row*CDD)[tid] = o;
}

// ---------------- minGRU chunked scan --------------------------------------
__device__ __forceinline__ void gate_av(float hid, float gt, float& a, float& v){
    const float sg = 1.0f / (1.0f + expf(-gt));   // sigmoid(gate)
    a = 1.0f / (1.0f + expf(gt));                 // sigmoid(-gate) = 1 - z
    const float gv = (hid >= 0.0f) ? (hid + 0.5f) : (1.0f / (1.0f + expf(-hid)));
    v = sg * gv;
}

__global__ void scan_phase1(const float* __restrict__ hg, float* __restrict__ P,
                            float* __restrict__ H)
{
    const int e = blockIdx.x*128 + threadIdx.x;          // 0..CDI-1
    const int c = blockIdx.y, b = blockIdx.z;
    const float* base = hg + ((size_t)b*CSS + (size_t)c*CCS)*(2*CDI);
    float p = 1.0f, hacc = 0.0f;
    #pragma unroll 4
    for (int s=0; s<CCS; s++){
        const float hid = base[(size_t)s*(2*CDI) + e];
        const float gt  = base[(size_t)s*(2*CDI) + CDI + e];
        float a, v; gate_av(hid, gt, a, v);
        hacc = fmaf(a, hacc, v);
        p *= a;
    }
    const int idx = (b*CNC + c)*CDI + e;
    P[idx] = p; H[idx] = hacc;
}

__global__ void scan_phase3(const float* __restrict__ hg, const float* __restrict__ P,
                            const float* __restrict__ H, float* __restrict__ hout)
{
    const int e = blockIdx.x*128 + threadIdx.x;
    const int c = blockIdx.y, b = blockIdx.z;
    float h = 0.5f;                                      // h_0
    for (int cc=0; cc<c; cc++){
        const int idx = (b*CNC + cc)*CDI + e;
        h = fmaf(P[idx], h, H[idx]);
    }
    const float* base = hg + ((size_t)b*CSS + (size_t)c*CCS)*(2*CDI);
    float* ob = hout + ((size_t)b*CSS + (size_t)c*CCS)*CDI;
    #pragma unroll 4
    for (int s=0; s<CCS; s++){
        const float hid = base[(size_t)s*(2*CDI) + e];
        const float gt  = base[(size_t)s*(2*CDI) + CDI + e];
        float a, v; gate_av(hid, gt, a, v);
        h = fmaf(a, h, v);
        ob[(size_t)s*CDI + e] = rtf32(h);
    }
}

// ---------------- final LN + 2-logit head ------------------------------------
__global__ void logits_kernel(const float* __restrict__ x, const float* __restrict__ gw,
                              const float* __restrict__ bw, const float* __restrict__ Wl,
                              float* __restrict__ out)
{
    const int row = blockIdx.x;
    const int tid = threadIdx.x;
    const float2 v = reinterpret_cast<const float2*>(x + (size_t)row*CDD)[tid];
    float s = v.x + v.y;
    float q = v.x*v.x + v.y*v.y;
    __shared__ float sh[16];
    #pragma unroll
    for (int o=16;o>0;o>>=1){ s += __shfl_down_sync(0xffffffffu,s,o);
                              q += __shfl_down_sync(0xffffffffu,q,o); }
    const int warp = tid>>5, lane = tid&31;
    if (lane==0){ sh[warp]=s; sh[warp+8]=q; }
    __syncthreads();
    if (tid==0){
        float S=0.f, Q=0.f;
        #pragma unroll
        for (int w=0;w<8;w++){ S += sh[w]; Q += sh[w+8]; }
        float mean = S*(1.0f/CDD);
        float var  = Q*(1.0f/CDD) - mean*mean;
        sh[0]=mean; sh[1]=rsqrtf(var + 1e-5f);
    }
    __syncthreads();
    const float mean = sh[0], rstd = sh[1];
    __syncthreads();

    const float2 gg = reinterpret_cast<const float2*>(gw)[tid];
    const float2 bb = reinterpret_cast<const float2*>(bw)[tid];
    const float n0 = (v.x-mean)*rstd*gg.x + bb.x;
    const float n1 = (v.y-mean)*rstd*gg.y + bb.y;
    const int c = tid*2;
    float a0 = n0*Wl[c]       + n1*Wl[c+1];
    float a1 = n0*Wl[CDD+c]   + n1*Wl[CDD+c+1];
    #pragma unroll
    for (int o=16;o>0;o>>=1){ a0 += __shfl_down_sync(0xffffffffu,a0,o);
                              a1 += __shfl_down_sync(0xffffffffu,a1,o); }
    if (lane==0){ sh[warp]=a0; sh[warp+8]=a1; }
    __syncthreads();
    if (tid==0){
        float r0=0.f, r1=0.f;
        #pragma unroll
        for (int w=0;w<8;w++){ r0 += sh[w]; r1 += sh[w+8]; }
        out[(size_t)row*2 + 0] = r0;
        out[(size_t)row*2 + 1] = r1;
    }
}

// ---------------- driver ----------------------------------------------------
extern "C" void kernel_launch(void* const* d_in, const int* in_sizes, int n_in,
                              void* d_out, int out_size)
{
    const float* input  = (const float*)d_in[0];
    const float* Whg    = (const float*)d_in[1];
    const float* Wout   = (const float*)d_in[2];
    const float* ln1_g  = (const float*)d_in[3];
    const float* ln1_b  = (const float*)d_in[4];
    const float* ln2_g  = (const float*)d_in[5];
    const float* ln2_b  = (const float*)d_in[6];
    const float* ffW1   = (const float*)d_in[7];
    const float* ffb1   = (const float*)d_in[8];
    const float* ffW2   = (const float*)d_in[9];
    const float* ffb2   = (const float*)d_in[10];
    const float* norm_g = (const float*)d_in[11];
    const float* norm_b = (const float*)d_in[12];
    const float* Wlog   = (const float*)d_in[13];
    float* out = (float*)d_out;

    float *xn, *hg, *h, *y, *x, *ffh, *P, *Hc, *wtf;
    cudaGetSymbolAddress((void**)&xn,  g_xn);
    cudaGetSymbolAddress((void**)&hg,  g_hg);
    cudaGetSymbolAddress((void**)&h,   g_h);
    cudaGetSymbolAddress((void**)&y,   g_y);
    cudaGetSymbolAddress((void**)&x,   g_x);
    cudaGetSymbolAddress((void**)&ffh, g_ffh);
    cudaGetSymbolAddress((void**)&P,   g_P);
    cudaGetSymbolAddress((void**)&Hc,  g_Hc);
    cudaGetSymbolAddress((void**)&wtf, g_wtf);

    float* w_hg  = wtf;
    float* w_out = w_hg  + W_HG_SZ;
    float* w_f1  = w_out + W_OUT_SZ;
    float* w_f2  = w_f1  + W_F1_SZ;

    // opt-in dynamic smem (idempotent host-side attribute sets)
    cudaFuncSetAttribute(gemm_v3<EPI_NONE>,
        cudaFuncAttributeMaxDynamicSharedMemorySize, SMEM_DYN);
    cudaFuncSetAttribute(gemm_v3<EPI_ADD>,
        cudaFuncAttributeMaxDynamicSharedMemorySize, SMEM_DYN);
    cudaFuncSetAttribute(gemm_v3<EPI_BIAS_GELU>,
        cudaFuncAttributeMaxDynamicSharedMemorySize, SMEM_DYN);
    cudaFuncSetAttribute(gemm_v3<EPI_BIAS_ADD>,
        cudaFuncAttributeMaxDynamicSharedMemorySize, SMEM_DYN);

    // weight prepass: round all weights to tf32
    wconv2<<<1024, 256>>>((const float4*)Whg,  (int)(W_HG_SZ/4),
                          (const float4*)Wout, (int)(W_OUT_SZ/4),
                          (float4*)w_hg, (float4*)w_out);
    wconv2<<<1024, 256>>>((const float4*)ffW1, (int)(W_F1_SZ/4),
                          (const float4*)ffW2, (int)(W_F2_SZ/4),
                          (float4*)w_f1, (float4*)w_f2);

    const int M = CMM;
    const dim3 scan_grid(CDI/128, CNC, CBB);

    for (int i=0; i<CLL; i++){
        const float* cur = (i==0) ? input : x;

        ln_kernel<<<M, 128>>>(cur, ln1_g + i*CDD, ln1_b + i*CDD, xn);
        gemm_v3<EPI_NONE><<<dim3(2*CDI/GNT, M/GMT), 256, SMEM_DYN>>>(
            xn, w_hg + (size_t)i*2*CDI*CDD, nullptr, nullptr, hg, M, 2*CDI, CDD);
        scan_phase1<<<scan_grid, 128>>>(hg, P, Hc);
        scan_phase3<<<scan_grid, 128>>>(hg, P, Hc, h);
        gemm_v3<EPI_ADD><<<dim3(CDD/GNT, M/GMT), 256, SMEM_DYN>>>(
            h, w_out + (size_t)i*CDD*CDI, nullptr, cur, y, M, CDD, CDI);
        ln_kernel<<<M, 128>>>(y, ln2_g + i*CDD, ln2_b + i*CDD, xn);
        gemm_v3<EPI_BIAS_GELU><<<dim3(CFF/GNT, M/GMT), 256, SMEM_DYN>>>(
            xn, w_f1 + (size_t)i*CFF*CDD, ffb1 + i*CFF, nullptr, ffh, M, CFF, CDD);
        gemm_v3<EPI_BIAS_ADD><<<dim3(CDD/GNT, M/GMT), 256, SMEM_DYN>>>(
            ffh, w_f2 + (size_t)i*CDD*CFF, ffb2 + i*CDD, y, x, M, CDD, CFF);
    }

    logits_kernel<<<M, 256>>>(x, norm_g, norm_b, Wlog, out);
}

// round 6
// speedup vs baseline: 1.7353x; 1.1046x over previous
#include <cuda_runtime.h>
#include <cstdint>
#include <cstddef>

// Problem constants
#define CBB 8
#define CSS 4096
#define CDD 512
#define CLL 4
#define CDI 768
#define CFF 2048
#define CMM (CBB*CSS)          // 32768 rows
#define CNC 16                 // scan chunks
#define CCS (CSS/CNC)          // 256 per chunk

// weight scratch sizes (floats)
#define W_HG_SZ  ((size_t)CLL*2*CDI*CDD)
#define W_OUT_SZ ((size_t)CLL*CDD*CDI)
#define W_F1_SZ  ((size_t)CLL*CFF*CDD)
#define W_F2_SZ  ((size_t)CLL*CDD*CFF)

// GEMM tiling: CTA 128(M) x 128(N), 8 warps (2m x 4n), warp tile 64x32.
// K staged 32 floats (128B rows, 8x16B chunks, swizzle c ^ (row&7)).
// 96KB smem + <=128 regs => 2 CTAs per SM.
#define GMT 128
#define GNT 128
#define KC  32
#define NST 3
#define STG_A 16384                      // 128 rows * 128B
#define STG_B 16384                      // 128 rows * 128B
#define STG_BYTES (STG_A + STG_B)        // 32768
#define SMEM_DYN (NST*STG_BYTES)         // 98304

// ---------------- scratch (device globals; no allocation allowed) ----------
static __device__ __align__(256) float g_xn [(size_t)CMM*CDD];
static __device__ __align__(256) float g_hg [(size_t)CMM*2*CDI];
static __device__ __align__(256) float g_h  [(size_t)CMM*CDI];
static __device__ __align__(256) float g_y  [(size_t)CMM*CDD];
static __device__ __align__(256) float g_x  [(size_t)CMM*CDD];
static __device__ __align__(256) float g_ffh[(size_t)CMM*CFF];
static __device__ __align__(256) float g_P  [CBB*CNC*CDI];
static __device__ __align__(256) float g_Hc [CBB*CNC*CDI];
static __device__ __align__(256) float g_wtf[W_HG_SZ + W_OUT_SZ + W_F1_SZ + W_F2_SZ];

// ---------------- helpers ----------------------------------------------------
__device__ __forceinline__ uint32_t f2tf32(float f){
    uint32_t u; asm("cvt.rna.tf32.f32 %0, %1;" : "=r"(u) : "f"(f)); return u;
}
__device__ __forceinline__ float rtf32(float f){ return __uint_as_float(f2tf32(f)); }

__device__ __forceinline__ uint32_t smem_u32(const void* p){
    uint32_t a;
    asm("{ .reg .u64 t; cvta.to.shared.u64 t, %1; cvt.u32.u64 %0, t; }"
        : "=r"(a) : "l"(p));
    return a;
}
__device__ __forceinline__ void cp16(uint32_t saddr, const void* g){
    asm volatile("cp.async.cg.shared.global [%0], [%1], 16;"
                 :: "r"(saddr), "l"(g) : "memory");
}
__device__ __forceinline__ void cp_commit(){
    asm volatile("cp.async.commit_group;" ::: "memory");
}
__device__ __forceinline__ void cp_wait1(){
    asm volatile("cp.async.wait_group 1;" ::: "memory");
}
__device__ __forceinline__ void cp_wait0(){
    asm volatile("cp.async.wait_group 0;" ::: "memory");
}
__device__ __forceinline__ void ldsm_x4(uint32_t& r0, uint32_t& r1, uint32_t& r2,
                                        uint32_t& r3, uint32_t addr){
    asm volatile("ldmatrix.sync.aligned.m8n8.x4.shared.b16 {%0,%1,%2,%3}, [%4];"
                 : "=r"(r0), "=r"(r1), "=r"(r2), "=r"(r3) : "r"(addr));
}
__device__ __forceinline__ void mma_tf32(float (&d)[4], const uint32_t (&a)[4],
                                         const uint32_t (&b)[2]){
    asm volatile(
        "mma.sync.aligned.m16n8k8.row.col.f32.tf32.tf32.f32 "
        "{%0,%1,%2,%3}, {%4,%5,%6,%7}, {%8,%9}, {%0,%1,%2,%3};\n"
        : "+f"(d[0]), "+f"(d[1]), "+f"(d[2]), "+f"(d[3])
        : "r"(a[0]), "r"(a[1]), "r"(a[2]), "r"(a[3]), "r"(b[0]), "r"(b[1]));
}

enum { EPI_NONE=0, EPI_ADD=1, EPI_BIAS_GELU=2, EPI_BIAS_ADD=3 };

// ---------------- weight prepass: round to tf32 ------------------------------
__global__ void wconv2(const float4* __restrict__ s1, int n1,
                       const float4* __restrict__ s2, int n2,
                       float4* __restrict__ d1, float4* __restrict__ d2)
{
    const int gid = blockIdx.x*blockDim.x + threadIdx.x;
    const int stride = gridDim.x*blockDim.x;
    for (int i=gid; i<n1; i+=stride){
        float4 v = s1[i];
        v.x = rtf32(v.x); v.y = rtf32(v.y); v.z = rtf32(v.z); v.w = rtf32(v.w);
        d1[i] = v;
    }
    for (int i=gid; i<n2; i+=stride){
        float4 v = s2[i];
        v.x = rtf32(v.x); v.y = rtf32(v.y); v.z = rtf32(v.z); v.w = rtf32(v.w);
        d2[i] = v;
    }
}

// ---------------- GEMM v4: 128x128 CTA, 2 CTAs/SM ----------------------------
// C[M,N] = A[M,K] @ W[N,K]^T. Operands are pre-rounded tf32 bit patterns.
template<int EPI>
__global__ __launch_bounds__(256, 2)
void gemm_v4(const float* __restrict__ A, const float* __restrict__ W,
             const float* __restrict__ bias, const float* __restrict__ add,
             float* __restrict__ C, int M, int N, int K)
{
    extern __shared__ __align__(1024) char smem[];
    const uint32_t sb = smem_u32(smem);
    const int tid  = threadIdx.x;
    const int lane = tid & 31;
    const int warp = tid >> 5;
    const int wm   = (warp >> 2) * 64;     // warp M offset (2 warps)
    const int wn   = (warp & 3) * 32;      // warp N offset (4 warps)
    const int g    = lane >> 2;
    const int t    = lane & 3;
    const int bm = blockIdx.y * GMT;
    const int bn = blockIdx.x * GNT;

    // per-lane ldmatrix row/chunk selectors
    const int rowsel = lane & 7;
    const int rowA   = rowsel + ((lane >> 3) & 1) * 8;   // mats 0,1: row; 2,3: k+4
    const int chA    = (lane >> 4) & 1;
    const int rowB   = rowsel + ((lane >> 4) & 1) * 8;   // mats 2,3 -> n+8
    const int chB    = (lane >> 3) & 1;                  // mats 1,3 -> k+4

    float acc[4][4][4];
    #pragma unroll
    for (int i=0;i<4;i++)
        #pragma unroll
        for (int j=0;j<4;j++)
            #pragma unroll
            for (int k=0;k<4;k++) acc[i][j][k] = 0.0f;

    auto load_stage = [&](int s){
        const int slot = s % NST;
        const uint32_t sA = sb + (uint32_t)slot*STG_BYTES;
        const uint32_t sB = sA + STG_A;
        const int k0 = s * KC;
        #pragma unroll
        for (int i=0;i<4;i++){                       // A: 1024 chunks
            const int q = tid + i*256;
            const int row = q >> 3, c = q & 7;
            cp16(sA + (uint32_t)(row*8 + (c ^ (row & 7)))*16u,
                 A + (size_t)(bm+row)*K + k0 + c*4);
        }
        #pragma unroll
        for (int i=0;i<4;i++){                       // B: 1024 chunks
            const int q = tid + i*256;
            const int row = q >> 3, c = q & 7;
            cp16(sB + (uint32_t)(row*8 + (c ^ (row & 7)))*16u,
                 W + (size_t)(bn+row)*K + k0 + c*4);
        }
    };

    auto compute = [&](int slot){
        const uint32_t sA = sb + (uint32_t)slot*STG_BYTES;
        const uint32_t sB = sA + STG_A;
        #pragma unroll
        for (int slab=0; slab<4; slab++){            // 4 x (K=8) per stage
            const uint32_t ab = sA +
                (uint32_t)((wm + rowA)*8 + (((slab<<1)|chA) ^ rowsel))*16u;
            const uint32_t bb = sB +
                (uint32_t)((wn + rowB)*8 + (((slab<<1)|chB) ^ rowsel))*16u;
            uint32_t Bf[4][2];
            #pragma unroll
            for (int n2=0; n2<2; n2++)
                ldsm_x4(Bf[2*n2][0], Bf[2*n2][1], Bf[2*n2+1][0], Bf[2*n2+1][1],
                        bb + n2*2048);
            #pragma unroll
            for (int ms=0; ms<4; ms++){
                uint32_t a[4];
                ldsm_x4(a[0], a[1], a[2], a[3], ab + ms*2048);
                #pragma unroll
                for (int ns=0; ns<4; ns++)
                    mma_tf32(acc[ms][ns], a, Bf[ns]);
            }
        }
    };

    const int nk = K / KC;                           // >= 16 for all shapes
    load_stage(0); cp_commit();
    load_stage(1); cp_commit();
    for (int kt=0; kt<nk; kt++){
        cp_wait1();                                  // stage kt landed
        __syncthreads();                             // visible to all warps
        if (kt+2 < nk) load_stage(kt+2);             // slot (kt+2)%3 != kt%3
        cp_commit();                                 // (possibly empty group)
        compute(kt % NST);
    }
    cp_wait0();

    // ---------------- epilogue ----------------
    #pragma unroll
    for (int ms=0; ms<4; ms++){
        const int rr = bm + wm + ms*16 + g;
        #pragma unroll
        for (int ns=0; ns<4; ns++){
            const int cc = bn + wn + ns*8 + 2*t;
            float v[4] = {acc[ms][ns][0], acc[ms][ns][1],
                          acc[ms][ns][2], acc[ms][ns][3]};
            const int rows[2] = {rr, rr+8};
            #pragma unroll
            for (int h=0; h<2; h++){
                #pragma unroll
                for (int q=0; q<2; q++){
                    float val = v[h*2+q];
                    const int row = rows[h], col = cc + q;
                    if constexpr (EPI == EPI_ADD){
                        val += add[(size_t)row*N + col];
                    } else if constexpr (EPI == EPI_BIAS_GELU){
                        val += bias[col];
                        val = 0.5f * val * (1.0f + erff(val * 0.70710678118654752f));
                        val = rtf32(val);            // feeds next GEMM as A
                    } else if constexpr (EPI == EPI_BIAS_ADD){
                        val += bias[col] + add[(size_t)row*N + col];
                    }
                    v[h*2+q] = val;
                }
                *reinterpret_cast<float2*>(C + (size_t)rows[h]*N + cc) =
                    make_float2(v[h*2+0], v[h*2+1]);
            }
        }
    }
}

// ---------------- layernorm (D=512), warp-per-row, 8 rows/block -------------
__global__ void ln_warp(const float* __restrict__ x, const float* __restrict__ gw,
                        const float* __restrict__ bw, float* __restrict__ y)
{
    const int warp = threadIdx.x >> 5, lane = threadIdx.x & 31;
    const int row  = blockIdx.x*8 + warp;
    const float4* xr = reinterpret_cast<const float4*>(x + (size_t)row*CDD);
    float4 v[4];
    float s = 0.0f, q = 0.0f;
    #pragma unroll
    for (int j=0;j<4;j++){
        v[j] = xr[lane + j*32];
        s += (v[j].x+v[j].y)+(v[j].z+v[j].w);
        q += v[j].x*v[j].x + v[j].y*v[j].y + v[j].z*v[j].z + v[j].w*v[j].w;
    }
    #pragma unroll
    for (int o=16;o>0;o>>=1){ s += __shfl_xor_sync(0xffffffffu,s,o);
                              q += __shfl_xor_sync(0xffffffffu,q,o); }
    const float mean = s * (1.0f/CDD);
    const float rstd = rsqrtf(q*(1.0f/CDD) - mean*mean + 1e-5f);
    const float4* gr = reinterpret_cast<const float4*>(gw);
    const float4* br = reinterpret_cast<const float4*>(bw);
    float4* yr = reinterpret_cast<float4*>(y + (size_t)row*CDD);
    #pragma unroll
    for (int j=0;j<4;j++){
        const float4 gg = gr[lane + j*32];
        const float4 bb = br[lane + j*32];
        float4 o;
        o.x = rtf32((v[j].x-mean)*rstd*gg.x + bb.x);
        o.y = rtf32((v[j].y-mean)*rstd*gg.y + bb.y);
        o.z = rtf32((v[j].z-mean)*rstd*gg.z + bb.z);
        o.w = rtf32((v[j].w-mean)*rstd*gg.w + bb.w);
        yr[lane + j*32] = o;
    }
}

// ---------------- minGRU chunked scan --------------------------------------
// a = sigmoid(-g), sg = sigmoid(g) from ONE exp; g(h) branch uses one exp.
__device__ __forceinline__ void gate_av(float hid, float gt, float& a, float& v){
    const float tg = __expf(-gt);
    const float sg = 1.0f / (1.0f + tg);        // sigmoid(gate)
    a = 1.0f - sg;                              // sigmoid(-gate), NaN-safe
    float gv;
    if (hid >= 0.0f) gv = hid + 0.5f;
    else { const float u = __expf(hid); gv = u / (1.0f + u); }
    v = sg * gv;
}

__global__ void scan_phase1(const float* __restrict__ hg, float* __restrict__ P,
                            float* __restrict__ H)
{
    const int e = blockIdx.x*128 + threadIdx.x;          // 0..CDI-1
    const int c = blockIdx.y, b = blockIdx.z;
    const float* base = hg + ((size_t)b*CSS + (size_t)c*CCS)*(2*CDI);
    float p = 1.0f, hacc = 0.0f;
    #pragma unroll 4
    for (int s=0; s<CCS; s++){
        const float hid = base[(size_t)s*(2*CDI) + e];
        const float gt  = base[(size_t)s*(2*CDI) + CDI + e];
        float a, v; gate_av(hid, gt, a, v);
        hacc = fmaf(a, hacc, v);
        p *= a;
    }
    const int idx = (b*CNC + c)*CDI + e;
    P[idx] = p; H[idx] = hacc;
}

__global__ void scan_phase3(const float* __restrict__ hg, const float* __restrict__ P,
                            const float* __restrict__ H, float* __restrict__ hout)
{
    const int e = blockIdx.x*128 + threadIdx.x;
    const int c = blockIdx.y, b = blockIdx.z;
    float h = 0.5f;                                      // h_0
    for (int cc=0; cc<c; cc++){
        const int idx = (b*CNC + cc)*CDI + e;
        h = fmaf(P[idx], h, H[idx]);
    }
    const float* base = hg + ((size_t)b*CSS + (size_t)c*CCS)*(2*CDI);
    float* ob = hout + ((size_t)b*CSS + (size_t)c*CCS)*CDI;
    #pragma unroll 4
    for (int s=0; s<CCS; s++){
        const float hid = base[(size_t)s*(2*CDI) + e];
        const float gt  = base[(size_t)s*(2*CDI) + CDI + e];
        float a, v; gate_av(hid, gt, a, v);
        h = fmaf(a, h, v);
        ob[(size_t)s*CDI + e] = rtf32(h);
    }
}

// ---------------- final LN + 2-logit head, warp-per-row ----------------------
__global__ void logits_warp(const float* __restrict__ x, const float* __restrict__ gw,
                            const float* __restrict__ bw, const float* __restrict__ Wl,
                            float* __restrict__ out)
{
    const int warp = threadIdx.x >> 5, lane = threadIdx.x & 31;
    const int row  = blockIdx.x*8 + warp;
    const float4* xr = reinterpret_cast<const float4*>(x + (size_t)row*CDD);
    float4 v[4];
    float s = 0.0f, q = 0.0f;
    #pragma unroll
    for (int j=0;j<4;j++){
        v[j] = xr[lane + j*32];
        s += (v[j].x+v[j].y)+(v[j].z+v[j].w);
        q += v[j].x*v[j].x + v[j].y*v[j].y + v[j].z*v[j].z + v[j].w*v[j].w;
    }
    #pragma unroll
    for (int o=16;o>0;o>>=1){ s += __shfl_xor_sync(0xffffffffu,s,o);
                              q += __shfl_xor_sync(0xffffffffu,q,o); }
    const float mean = s * (1.0f/CDD);
    const float rstd = rsqrtf(q*(1.0f/CDD) - mean*mean + 1e-5f);

    const float4* gr = reinterpret_cast<const float4*>(gw);
    const float4* br = reinterpret_cast<const float4*>(bw);
    const float4* w0 = reinterpret_cast<const float4*>(Wl);
    const float4* w1 = reinterpret_cast<const float4*>(Wl + CDD);
    float a0 = 0.0f, a1 = 0.0f;
    #pragma unroll
    for (int j=0;j<4;j++){
        const int idx = lane + j*32;
        const float4 gg = gr[idx], bb = br[idx];
        const float4 wa = w0[idx], wb = w1[idx];
        const float n0 = (v[j].x-mean)*rstd*gg.x + bb.x;
        const float n1 = (v[j].y-mean)*rstd*gg.y + bb.y;
        const float n2 = (v[j].z-mean)*rstd*gg.z + bb.z;
        const float n3 = (v[j].w-mean)*rstd*gg.w + bb.w;
        a0 += n0*wa.x + n1*wa.y + n2*wa.z + n3*wa.w;
        a1 += n0*wb.x + n1*wb.y + n2*wb.z + n3*wb.w;
    }
    #pragma unroll
    for (int o=16;o>0;o>>=1){ a0 += __shfl_xor_sync(0xffffffffu,a0,o);
                              a1 += __shfl_xor_sync(0xffffffffu,a1,o); }
    if (lane == 0){
        out[(size_t)row*2 + 0] = a0;
        out[(size_t)row*2 + 1] = a1;
    }
}

// ---------------- driver ----------------------------------------------------
extern "C" void kernel_launch(void* const* d_in, const int* in_sizes, int n_in,
                              void* d_out, int out_size)
{
    const float* input  = (const float*)d_in[0];
    const float* Whg    = (const float*)d_in[1];
    const float* Wout   = (const float*)d_in[2];
    const float* ln1_g  = (const float*)d_in[3];
    const float* ln1_b  = (const float*)d_in[4];
    const float* ln2_g  = (const float*)d_in[5];
    const float* ln2_b  = (const float*)d_in[6];
    const float* ffW1   = (const float*)d_in[7];
    const float* ffb1   = (const float*)d_in[8];
    const float* ffW2   = (const float*)d_in[9];
    const float* ffb2   = (const float*)d_in[10];
    const float* norm_g = (const float*)d_in[11];
    const float* norm_b = (const float*)d_in[12];
    const float* Wlog   = (const float*)d_in[13];
    float* out = (float*)d_out;

    float *xn, *hg, *h, *y, *x, *ffh, *P, *Hc, *wtf;
    cudaGetSymbolAddress((void**)&xn,  g_xn);
    cudaGetSymbolAddress((void**)&hg,  g_hg);
    cudaGetSymbolAddress((void**)&h,   g_h);
    cudaGetSymbolAddress((void**)&y,   g_y);
    cudaGetSymbolAddress((void**)&x,   g_x);
    cudaGetSymbolAddress((void**)&ffh, g_ffh);
    cudaGetSymbolAddress((void**)&P,   g_P);
    cudaGetSymbolAddress((void**)&Hc,  g_Hc);
    cudaGetSymbolAddress((void**)&wtf, g_wtf);

    float* w_hg  = wtf;
    float* w_out = w_hg  + W_HG_SZ;
    float* w_f1  = w_out + W_OUT_SZ;
    float* w_f2  = w_f1  + W_F1_SZ;

    // opt-in dynamic smem (idempotent host-side attribute sets)
    cudaFuncSetAttribute(gemm_v4<EPI_NONE>,
        cudaFuncAttributeMaxDynamicSharedMemorySize, SMEM_DYN);
    cudaFuncSetAttribute(gemm_v4<EPI_ADD>,
        cudaFuncAttributeMaxDynamicSharedMemorySize, SMEM_DYN);
    cudaFuncSetAttribute(gemm_v4<EPI_BIAS_GELU>,
        cudaFuncAttributeMaxDynamicSharedMemorySize, SMEM_DYN);
    cudaFuncSetAttribute(gemm_v4<EPI_BIAS_ADD>,
        cudaFuncAttributeMaxDynamicSharedMemorySize, SMEM_DYN);

    // weight prepass: round all weights to tf32
    wconv2<<<1024, 256>>>((const float4*)Whg,  (int)(W_HG_SZ/4),
                          (const float4*)Wout, (int)(W_OUT_SZ/4),
                          (float4*)w_hg, (float4*)w_out);
    wconv2<<<1024, 256>>>((const float4*)ffW1, (int)(W_F1_SZ/4),
                          (const float4*)ffW2, (int)(W_F2_SZ/4),
                          (float4*)w_f1, (float4*)w_f2);

    const int M = CMM;
    const dim3 scan_grid(CDI/128, CNC, CBB);

    for (int i=0; i<CLL; i++){
        const float* cur = (i==0) ? input : x;

        ln_warp<<<M/8, 256>>>(cur, ln1_g + i*CDD, ln1_b + i*CDD, xn);
        gemm_v4<EPI_NONE><<<dim3(2*CDI/GNT, M/GMT), 256, SMEM_DYN>>>(
            xn, w_hg + (size_t)i*2*CDI*CDD, nullptr, nullptr, hg, M, 2*CDI, CDD);
        scan_phase1<<<scan_grid, 128>>>(hg, P, Hc);
        scan_phase3<<<scan_grid, 128>>>(hg, P, Hc, h);
        gemm_v4<EPI_ADD><<<dim3(CDD/GNT, M/GMT), 256, SMEM_DYN>>>(
            h, w_out + (size_t)i*CDD*CDI, nullptr, cur, y, M, CDD, CDI);
        ln_warp<<<M/8, 256>>>(y, ln2_g + i*CDD, ln2_b + i*CDD, xn);
        gemm_v4<EPI_BIAS_GELU><<<dim3(CFF/GNT, M/GMT), 256, SMEM_DYN>>>(
            xn, w_f1 + (size_t)i*CFF*CDD, ffb1 + i*CFF, nullptr, ffh, M, CFF, CDD);
        gemm_v4<EPI_BIAS_ADD><<<dim3(CDD/GNT, M/GMT), 256, SMEM_DYN>>>(
            ffh, w_f2 + (size_t)i*CDD*CFF, ffb2 + i*CDD, y, x, M, CDD, CFF);
    }

    logits_warp<<<M/8, 256>>>(x, norm_g, norm_b, Wlog, out);
}

// round 7
// speedup vs baseline: 3.3287x; 1.9183x over previous
#include <cuda_runtime.h>
#include <cuda_fp16.h>
#include <cstdint>
#include <cstddef>

// Problem constants
#define CBB 8
#define CSS 4096
#define CDD 512
#define CLL 4
#define CDI 768
#define CFF 2048
#define CMM (CBB*CSS)          // 32768 rows
#define CNC 16                 // scan chunks
#define CCS (CSS/CNC)          // 256 per chunk

// weight scratch sizes (elements)
#define W_HG_SZ  ((size_t)CLL*2*CDI*CDD)
#define W_OUT_SZ ((size_t)CLL*CDD*CDI)
#define W_F1_SZ  ((size_t)CLL*CFF*CDD)
#define W_F2_SZ  ((size_t)CLL*CDD*CFF)

// GEMM tiling: CTA 128(M) x 128(N), 8 warps (2m x 4n), warp tile 64x32.
// fp16 m16n8k16. K staged 64 halves (128B rows, 8x16B chunks, swizzle c^(row&7)).
// 96KB smem + 128 regs => 2 CTAs per SM.
#define GMT 128
#define GNT 128
#define KC  64                           // halves per stage
#define NST 3
#define STG_A 16384                      // 128 rows * 128B
#define STG_B 16384
#define STG_BYTES (STG_A + STG_B)        // 32768
#define SMEM_DYN (NST*STG_BYTES)         // 98304

// ---------------- scratch (device globals; no allocation allowed) ----------
static __device__ __align__(256) __half   g_xn [(size_t)CMM*CDD];   // LN out (fp16)
static __device__ __align__(256) __half2  g_av [(size_t)CMM*CDI];   // (a, v) pairs
static __device__ __align__(256) __half   g_h  [(size_t)CMM*CDI];   // scan out (fp16)
static __device__ __align__(256) float    g_y  [(size_t)CMM*CDD];   // residual (fp32)
static __device__ __align__(256) float    g_x  [(size_t)CMM*CDD];   // layer out (fp32)
static __device__ __align__(256) __half   g_ffh[(size_t)CMM*CFF];   // ff hidden (fp16)
static __device__ __align__(256) __half   g_wh [W_HG_SZ + W_OUT_SZ + W_F1_SZ + W_F2_SZ];

// ---------------- helpers ----------------------------------------------------
__device__ __forceinline__ uint32_t smem_u32(const void* p){
    uint32_t a;
    asm("{ .reg .u64 t; cvta.to.shared.u64 t, %1; cvt.u32.u64 %0, t; }"
        : "=r"(a) : "l"(p));
    return a;
}
__device__ __forceinline__ void cp16(uint32_t saddr, const void* g){
    asm volatile("cp.async.cg.shared.global [%0], [%1], 16;"
                 :: "r"(saddr), "l"(g) : "memory");
}
__device__ __forceinline__ void cp_commit(){
    asm volatile("cp.async.commit_group;" ::: "memory");
}
__device__ __forceinline__ void cp_wait1(){
    asm volatile("cp.async.wait_group 1;" ::: "memory");
}
__device__ __forceinline__ void cp_wait0(){
    asm volatile("cp.async.wait_group 0;" ::: "memory");
}
__device__ __forceinline__ void ldsm_x4(uint32_t& r0, uint32_t& r1, uint32_t& r2,
                                        uint32_t& r3, uint32_t addr){
    asm volatile("ldmatrix.sync.aligned.m8n8.x4.shared.b16 {%0,%1,%2,%3}, [%4];"
                 : "=r"(r0), "=r"(r1), "=r"(r2), "=r"(r3) : "r"(addr));
}
__device__ __forceinline__ void mma_f16(float (&d)[4], const uint32_t (&a)[4],
                                        const uint32_t (&b)[2]){
    asm volatile(
        "mma.sync.aligned.m16n8k16.row.col.f32.f16.f16.f32 "
        "{%0,%1,%2,%3}, {%4,%5,%6,%7}, {%8,%9}, {%0,%1,%2,%3};\n"
        : "+f"(d[0]), "+f"(d[1]), "+f"(d[2]), "+f"(d[3])
        : "r"(a[0]), "r"(a[1]), "r"(a[2]), "r"(a[3]), "r"(b[0]), "r"(b[1]));
}

enum { EPI_AV=0, EPI_ADD=1, EPI_BIAS_GELU=2, EPI_BIAS_ADD=3 };

// ---------------- weight prepass ---------------------------------------------
// Permute+convert Whg: dst row 2e = hidden_e (src e), 2e+1 = gate_e (src 768+e).
__global__ void wperm_hg(const float* __restrict__ src, __half* __restrict__ dst)
{
    const int id = blockIdx.x*blockDim.x + threadIdx.x;   // 8 halves each
    const int perlayer = 2*CDI*CDD/8;                     // 98304
    if (id >= CLL*perlayer) return;
    const int l = id / perlayer, rem = id % perlayer;
    const int r = rem / (CDD/8), c8 = rem % (CDD/8);
    const int sr = (r & 1) ? (CDI + (r >> 1)) : (r >> 1);
    const float* s = src + ((size_t)l*2*CDI + sr)*CDD + c8*8;
    __half h[8];
    #pragma unroll
    for (int j=0;j<8;j++) h[j] = __float2half_rn(s[j]);
    *reinterpret_cast<uint4*>(dst + ((size_t)l*2*CDI + r)*CDD + c8*8) =
        *reinterpret_cast<uint4*>(h);
}

__global__ void wcvt(const float4* __restrict__ s, __half* __restrict__ d, int n4)
{
    const int gid = blockIdx.x*blockDim.x + threadIdx.x;
    const int stride = gridDim.x*blockDim.x;
    for (int i=gid; i<n4; i+=stride){
        const float4 v = s[i];
        __half h[4] = {__float2half_rn(v.x), __float2half_rn(v.y),
                       __float2half_rn(v.z), __float2half_rn(v.w)};
        *reinterpret_cast<uint2*>(d + (size_t)i*4) = *reinterpret_cast<uint2*>(h);
    }
}

// ---------------- GEMM fp16: 128x128 CTA, 2 CTAs/SM --------------------------
// C[M,N] = A[M,K] @ W[N,K]^T, fp16 operands, fp32 accumulate.
template<int EPI>
__global__ __launch_bounds__(256, 2)
void gemm_h(const __half* __restrict__ A, const __half* __restrict__ W,
            const float* __restrict__ bias, const float* __restrict__ add,
            void* __restrict__ Cv, int M, int N, int K)
{
    extern __shared__ __align__(1024) char smem[];
    const uint32_t sb = smem_u32(smem);
    const int tid  = threadIdx.x;
    const int lane = tid & 31;
    const int warp = tid >> 5;
    const int wm   = (warp >> 2) * 64;     // warp M offset (2 warps)
    const int wn   = (warp & 3) * 32;      // warp N offset (4 warps)
    const int g    = lane >> 2;
    const int t    = lane & 3;
    const int bm = blockIdx.y * GMT;
    const int bn = blockIdx.x * GNT;

    // ldmatrix lane->row/chunk selectors (identical shape to tf32 version;
    // chunk = 16B = 8 halves, slab = K16)
    const int rowsel = lane & 7;
    const int rowA   = rowsel + ((lane >> 3) & 1) * 8;   // mats 0,1: m; 2,3: k+8
    const int chA    = (lane >> 4) & 1;
    const int rowB   = rowsel + ((lane >> 4) & 1) * 8;   // mats 2,3 -> n+8
    const int chB    = (lane >> 3) & 1;                  // mats 1,3 -> k+8

    float acc[4][4][4];
    #pragma unroll
    for (int i=0;i<4;i++)
        #pragma unroll
        for (int j=0;j<4;j++)
            #pragma unroll
            for (int k=0;k<4;k++) acc[i][j][k] = 0.0f;

    auto load_stage = [&](int s){
        const int slot = s % NST;
        const uint32_t sA = sb + (uint32_t)slot*STG_BYTES;
        const uint32_t sB = sA + STG_A;
        const int k0 = s * KC;
        #pragma unroll
        for (int i=0;i<4;i++){                       // A: 1024 chunks
            const int q = tid + i*256;
            const int row = q >> 3, c = q & 7;
            cp16(sA + (uint32_t)(row*8 + (c ^ (row & 7)))*16u,
                 A + (size_t)(bm+row)*K + k0 + c*8);
        }
        #pragma unroll
        for (int i=0;i<4;i++){                       // B: 1024 chunks
            const int q = tid + i*256;
            const int row = q >> 3, c = q & 7;
            cp16(sB + (uint32_t)(row*8 + (c ^ (row & 7)))*16u,
                 W + (size_t)(bn+row)*K + k0 + c*8);
        }
    };

    auto compute = [&](int slot){
        const uint32_t sA = sb + (uint32_t)slot*STG_BYTES;
        const uint32_t sB = sA + STG_A;
        #pragma unroll
        for (int slab=0; slab<4; slab++){            // 4 x (K=16) per stage
            const uint32_t ab = sA +
                (uint32_t)((wm + rowA)*8 + (((slab<<1)|chA) ^ rowsel))*16u;
            const uint32_t bb = sB +
                (uint32_t)((wn + rowB)*8 + (((slab<<1)|chB) ^ rowsel))*16u;
            uint32_t Bf[4][2];
            #pragma unroll
            for (int n2=0; n2<2; n2++)
                ldsm_x4(Bf[2*n2][0], Bf[2*n2][1], Bf[2*n2+1][0], Bf[2*n2+1][1],
                        bb + n2*2048);
            #pragma unroll
            for (int ms=0; ms<4; ms++){
                uint32_t a[4];
                ldsm_x4(a[0], a[1], a[2], a[3], ab + ms*2048);
                #pragma unroll
                for (int ns=0; ns<4; ns++)
                    mma_f16(acc[ms][ns], a, Bf[ns]);
            }
        }
    };

    const int nk = K / KC;                           // 8/12/32
    load_stage(0); cp_commit();
    load_stage(1); cp_commit();
    for (int kt=0; kt<nk; kt++){
        cp_wait1();                                  // stage kt landed
        __syncthreads();                             // visible to all warps
        if (kt+2 < nk) load_stage(kt+2);             // slot (kt+2)%3 != kt%3
        cp_commit();                                 // (possibly empty group)
        compute(kt % NST);
    }
    cp_wait0();

    // ---------------- epilogue ----------------
    #pragma unroll
    for (int ms=0; ms<4; ms++){
        const int rr = bm + wm + ms*16 + g;
        #pragma unroll
        for (int ns=0; ns<4; ns++){
            const int cc = bn + wn + ns*8 + 2*t;     // even
            float v[4] = {acc[ms][ns][0], acc[ms][ns][1],
                          acc[ms][ns][2], acc[ms][ns][3]};
            const int rows[2] = {rr, rr+8};
            #pragma unroll
            for (int h=0; h<2; h++){
                const int row = rows[h];
                if constexpr (EPI == EPI_AV){
                    // v[h*2+0] = hidden, v[h*2+1] = gate (permuted weights)
                    const float hid = v[h*2+0], gt = v[h*2+1];
                    const float sg = 1.0f / (1.0f + __expf(-gt));
                    const float a  = 1.0f - sg;
                    float gv;
                    if (hid >= 0.0f) gv = hid + 0.5f;
                    else { const float u = __expf(hid); gv = u / (1.0f + u); }
                    reinterpret_cast<__half2*>(Cv)[(size_t)row*(N>>1) + (cc>>1)] =
                        __floats2half2_rn(a, sg * gv);
                } else if constexpr (EPI == EPI_ADD){
                    float* C = reinterpret_cast<float*>(Cv);
                    const float2 a2 = *reinterpret_cast<const float2*>(
                        add + (size_t)row*N + cc);
                    *reinterpret_cast<float2*>(C + (size_t)row*N + cc) =
                        make_float2(v[h*2+0] + a2.x, v[h*2+1] + a2.y);
                } else if constexpr (EPI == EPI_BIAS_GELU){
                    float v0 = v[h*2+0] + bias[cc];
                    float v1 = v[h*2+1] + bias[cc+1];
                    v0 = 0.5f * v0 * (1.0f + erff(v0 * 0.70710678118654752f));
                    v1 = 0.5f * v1 * (1.0f + erff(v1 * 0.70710678118654752f));
                    __half* C = reinterpret_cast<__half*>(Cv);
                    *reinterpret_cast<__half2*>(C + (size_t)row*N + cc) =
                        __floats2half2_rn(v0, v1);
                } else {   // EPI_BIAS_ADD
                    float* C = reinterpret_cast<float*>(Cv);
                    const float2 a2 = *reinterpret_cast<const float2*>(
                        add + (size_t)row*N + cc);
                    *reinterpret_cast<float2*>(C + (size_t)row*N + cc) =
                        make_float2(v[h*2+0] + bias[cc]   + a2.x,
                                    v[h*2+1] + bias[cc+1] + a2.y);
                }
            }
        }
    }
}

// ---------------- layernorm (D=512), warp-per-row, fp16 out ------------------
__global__ void ln_warp(const float* __restrict__ x, const float* __restrict__ gw,
                        const float* __restrict__ bw, __half* __restrict__ y)
{
    const int warp = threadIdx.x >> 5, lane = threadIdx.x & 31;
    const int row  = blockIdx.x*8 + warp;
    const float4* xr = reinterpret_cast<const float4*>(x + (size_t)row*CDD);
    float4 v[4];
    float s = 0.0f, q = 0.0f;
    #pragma unroll
    for (int j=0;j<4;j++){
        v[j] = xr[lane + j*32];
        s += (v[j].x+v[j].y)+(v[j].z+v[j].w);
        q += v[j].x*v[j].x + v[j].y*v[j].y + v[j].z*v[j].z + v[j].w*v[j].w;
    }
    #pragma unroll
    for (int o=16;o>0;o>>=1){ s += __shfl_xor_sync(0xffffffffu,s,o);
                              q += __shfl_xor_sync(0xffffffffu,q,o); }
    const float mean = s * (1.0f/CDD);
    const float rstd = rsqrtf(q*(1.0f/CDD) - mean*mean + 1e-5f);
    const float4* gr = reinterpret_cast<const float4*>(gw);
    const float4* br = reinterpret_cast<const float4*>(bw);
    uint2* yr = reinterpret_cast<uint2*>(y + (size_t)row*CDD);
    #pragma unroll
    for (int j=0;j<4;j++){
        const float4 gg = gr[lane + j*32];
        const float4 bb = br[lane + j*32];
        const __half2 h0 = __floats2half2_rn((v[j].x-mean)*rstd*gg.x + bb.x,
                                             (v[j].y-mean)*rstd*gg.y + bb.y);
        const __half2 h1 = __floats2half2_rn((v[j].z-mean)*rstd*gg.z + bb.z,
                                             (v[j].w-mean)*rstd*gg.w + bb.w);
        uint2 u;
        u.x = *reinterpret_cast<const uint32_t*>(&h0);
        u.y = *reinterpret_cast<const uint32_t*>(&h1);
        yr[lane + j*32] = u;
    }
}

// ---------------- minGRU chunked scan (pure streaming over av pairs) --------
__global__ void scan_phase1(const __half2* __restrict__ av, float* __restrict__ P,
                            float* __restrict__ H)
{
    const int e = blockIdx.x*128 + threadIdx.x;          // 0..CDI-1
    const int c = blockIdx.y, b = blockIdx.z;
    const __half2* base = av + ((size_t)b*CSS + (size_t)c*CCS)*CDI + e;
    float p = 1.0f, hacc = 0.0f;
    #pragma unroll 4
    for (int s=0; s<CCS; s++){
        const float2 f = __half22float2(base[(size_t)s*CDI]);
        hacc = fmaf(f.x, hacc, f.y);
        p *= f.x;
    }
    const int idx = (b*CNC + c)*CDI + e;
    P[idx] = p; H[idx] = hacc;
}

__global__ void scan_phase3(const __half2* __restrict__ av, const float* __restrict__ P,
                            const float* __restrict__ H, __half* __restrict__ hout)
{
    const int e = blockIdx.x*128 + threadIdx.x;
    const int c = blockIdx.y, b = blockIdx.z;
    float h = 0.5f;                                      // h_0
    for (int cc=0; cc<c; cc++){
        const int idx = (b*CNC + cc)*CDI + e;
        h = fmaf(P[idx], h, H[idx]);
    }
    const __half2* base = av + ((size_t)b*CSS + (size_t)c*CCS)*CDI + e;
    __half* ob = hout + ((size_t)b*CSS + (size_t)c*CCS)*CDI + e;
    #pragma unroll 4
    for (int s=0; s<CCS; s++){
        const float2 f = __half22float2(base[(size_t)s*CDI]);
        h = fmaf(f.x, h, f.y);
        ob[(size_t)s*CDI] = __float2half_rn(h);
    }
}

// ---------------- final LN + 2-logit head, warp-per-row ----------------------
__global__ void logits_warp(const float* __restrict__ x, const float* __restrict__ gw,
                            const float* __restrict__ bw, const float* __restrict__ Wl,
                            float* __restrict__ out)
{
    const int warp = threadIdx.x >> 5, lane = threadIdx.x & 31;
    const int row  = blockIdx.x*8 + warp;
    const float4* xr = reinterpret_cast<const float4*>(x + (size_t)row*CDD);
    float4 v[4];
    float s = 0.0f, q = 0.0f;
    #pragma unroll
    for (int j=0;j<4;j++){
        v[j] = xr[lane + j*32];
        s += (v[j].x+v[j].y)+(v[j].z+v[j].w);
        q += v[j].x*v[j].x + v[j].y*v[j].y + v[j].z*v[j].z + v[j].w*v[j].w;
    }
    #pragma unroll
    for (int o=16;o>0;o>>=1){ s += __shfl_xor_sync(0xffffffffu,s,o);
                              q += __shfl_xor_sync(0xffffffffu,q,o); }
    const float mean = s * (1.0f/CDD);
    const float rstd = rsqrtf(q*(1.0f/CDD) - mean*mean + 1e-5f);

    const float4* gr = reinterpret_cast<const float4*>(gw);
    const float4* br = reinterpret_cast<const float4*>(bw);
    const float4* w0 = reinterpret_cast<const float4*>(Wl);
    const float4* w1 = reinterpret_cast<const float4*>(Wl + CDD);
    float a0 = 0.0f, a1 = 0.0f;
    #pragma unroll
    for (int j=0;j<4;j++){
        const int idx = lane + j*32;
        const float4 gg = gr[idx], bb = br[idx];
        const float4 wa = w0[idx], wb = w1[idx];
        const float n0 = (v[j].x-mean)*rstd*gg.x + bb.x;
        const float n1 = (v[j].y-mean)*rstd*gg.y + bb.y;
        const float n2 = (v[j].z-mean)*rstd*gg.z + bb.z;
        const float n3 = (v[j].w-mean)*rstd*gg.w + bb.w;
        a0 += n0*wa.x + n1*wa.y + n2*wa.z + n3*wa.w;
        a1 += n0*wb.x + n1*wb.y + n2*wb.z + n3*wb.w;
    }
    #pragma unroll
    for (int o=16;o>0;o>>=1){ a0 += __shfl_xor_sync(0xffffffffu,a0,o);
                              a1 += __shfl_xor_sync(0xffffffffu,a1,o); }
    if (lane == 0){
        out[(size_t)row*2 + 0] = a0;
        out[(size_t)row*2 + 1] = a1;
    }
}

// ---------------- carry scratch ----------------------------------------------
static __device__ __align__(256) float g_P  [CBB*CNC*CDI];
static __device__ __align__(256) float g_Hc [CBB*CNC*CDI];

// ---------------- driver ----------------------------------------------------
extern "C" void kernel_launch(void* const* d_in, const int* in_sizes, int n_in,
                              void* d_out, int out_size)
{
    const float* input  = (const float*)d_in[0];
    const float* Whg    = (const float*)d_in[1];
    const float* Wout   = (const float*)d_in[2];
    const float* ln1_g  = (const float*)d_in[3];
    const float* ln1_b  = (const float*)d_in[4];
    const float* ln2_g  = (const float*)d_in[5];
    const float* ln2_b  = (const float*)d_in[6];
    const float* ffW1   = (const float*)d_in[7];
    const float* ffb1   = (const float*)d_in[8];
    const float* ffW2   = (const float*)d_in[9];
    const float* ffb2   = (const float*)d_in[10];
    const float* norm_g = (const float*)d_in[11];
    const float* norm_b = (const float*)d_in[12];
    const float* Wlog   = (const float*)d_in[13];
    float* out = (float*)d_out;

    __half *xn, *h, *ffh, *wh; __half2 *av; float *y, *x, *P, *Hc;
    cudaGetSymbolAddress((void**)&xn,  g_xn);
    cudaGetSymbolAddress((void**)&av,  g_av);
    cudaGetSymbolAddress((void**)&h,   g_h);
    cudaGetSymbolAddress((void**)&y,   g_y);
    cudaGetSymbolAddress((void**)&x,   g_x);
    cudaGetSymbolAddress((void**)&ffh, g_ffh);
    cudaGetSymbolAddress((void**)&P,   g_P);
    cudaGetSymbolAddress((void**)&Hc,  g_Hc);
    cudaGetSymbolAddress((void**)&wh,  g_wh);

    __half* w_hg  = wh;
    __half* w_out = w_hg  + W_HG_SZ;
    __half* w_f1  = w_out + W_OUT_SZ;
    __half* w_f2  = w_f1  + W_F1_SZ;

    cudaFuncSetAttribute(gemm_h<EPI_AV>,
        cudaFuncAttributeMaxDynamicSharedMemorySize, SMEM_DYN);
    cudaFuncSetAttribute(gemm_h<EPI_ADD>,
        cudaFuncAttributeMaxDynamicSharedMemorySize, SMEM_DYN);
    cudaFuncSetAttribute(gemm_h<EPI_BIAS_GELU>,
        cudaFuncAttributeMaxDynamicSharedMemorySize, SMEM_DYN);
    cudaFuncSetAttribute(gemm_h<EPI_BIAS_ADD>,
        cudaFuncAttributeMaxDynamicSharedMemorySize, SMEM_DYN);

    // weight prepass: permute+convert Whg; convert the rest to fp16
    wperm_hg<<<(int)(W_HG_SZ/8 + 255)/256, 256>>>(Whg, w_hg);
    wcvt<<<1024, 256>>>((const float4*)Wout, w_out, (int)(W_OUT_SZ/4));
    wcvt<<<1024, 256>>>((const float4*)ffW1, w_f1,  (int)(W_F1_SZ/4));
    wcvt<<<1024, 256>>>((const float4*)ffW2, w_f2,  (int)(W_F2_SZ/4));

    const int M = CMM;
    const dim3 scan_grid(CDI/128, CNC, CBB);

    for (int i=0; i<CLL; i++){
        const float* cur = (i==0) ? input : x;

        ln_warp<<<M/8, 256>>>(cur, ln1_g + i*CDD, ln1_b + i*CDD, xn);
        // hg GEMM with fused gate transform -> (a,v) fp16 pairs
        gemm_h<EPI_AV><<<dim3(2*CDI/GNT, M/GMT), 256, SMEM_DYN>>>(
            xn, w_hg + (size_t)i*2*CDI*CDD, nullptr, nullptr, av, M, 2*CDI, CDD);
        scan_phase1<<<scan_grid, 128>>>(av, P, Hc);
        scan_phase3<<<scan_grid, 128>>>(av, P, Hc, h);
        gemm_h<EPI_ADD><<<dim3(CDD/GNT, M/GMT), 256, SMEM_DYN>>>(
            h, w_out + (size_t)i*CDD*CDI, nullptr, cur, y, M, CDD, CDI);
        ln_warp<<<M/8, 256>>>(y, ln2_g + i*CDD, ln2_b + i*CDD, xn);
        gemm_h<EPI_BIAS_GELU><<<dim3(CFF/GNT, M/GMT), 256, SMEM_DYN>>>(
            xn, w_f1 + (size_t)i*CFF*CDD, ffb1 + i*CFF, nullptr, ffh, M, CFF, CDD);
        gemm_h<EPI_BIAS_ADD><<<dim3(CDD/GNT, M/GMT), 256, SMEM_DYN>>>(
            ffh, w_f2 + (size_t)i*CDD*CFF, ffb2 + i*CDD, y, x, M, CDD, CFF);
    }

    logits_warp<<<M/8, 256>>>(x, norm_g, norm_b, Wlog, out);
}

// round 8
// speedup vs baseline: 3.6500x; 1.0965x over previous
#include <cuda_runtime.h>
#include <cuda_fp16.h>
#include <cstdint>
#include <cstddef>

// Problem constants
#define CBB 8
#define CSS 4096
#define CDD 512
#define CLL 4
#define CDI 768
#define CFF 2048
#define CMM (CBB*CSS)          // 32768 rows
#define CNC 64                 // scan chunks
#define CCS (CSS/CNC)          // 64 per chunk

// weight scratch sizes (elements)
#define W_HG_SZ  ((size_t)CLL*2*CDI*CDD)
#define W_OUT_SZ ((size_t)CLL*CDD*CDI)
#define W_F1_SZ  ((size_t)CLL*CFF*CDD)
#define W_F2_SZ  ((size_t)CLL*CDD*CFF)

// GEMM tiling: CTA 128(M) x 128(N), 8 warps (2m x 4n), warp tile 64x32.
// fp16 m16n8k16. K staged 64 halves (128B rows, 8x16B chunks, swizzle c^(row&7)).
// 96KB smem + 128 regs => 2 CTAs per SM.
#define GMT 128
#define GNT 128
#define KC  64                           // halves per stage
#define NST 3
#define STG_A 16384
#define STG_B 16384
#define STG_BYTES (STG_A + STG_B)        // 32768
#define SMEM_DYN (NST*STG_BYTES)         // 98304

// ---------------- scratch (device globals; no allocation allowed) ----------
static __device__ __align__(256) __half   g_xn [(size_t)CMM*CDD];   // LN out (fp16)
static __device__ __align__(256) __half2  g_av [(size_t)CMM*CDI];   // (a, v) pairs
static __device__ __align__(256) __half   g_h  [(size_t)CMM*CDI];   // scan out (fp16)
static __device__ __align__(256) float    g_y  [(size_t)CMM*CDD];   // residual (fp32)
static __device__ __align__(256) float    g_x  [(size_t)CMM*CDD];   // layer out (fp32)
static __device__ __align__(256) __half   g_ffh[(size_t)CMM*CFF];   // ff hidden (fp16)
static __device__ __align__(256) __half   g_wh [W_HG_SZ + W_OUT_SZ + W_F1_SZ + W_F2_SZ];
static __device__ __align__(256) float    g_P  [CBB*CNC*CDI];
static __device__ __align__(256) float    g_Hc [CBB*CNC*CDI];

// ---------------- helpers ----------------------------------------------------
__device__ __forceinline__ uint32_t smem_u32(const void* p){
    uint32_t a;
    asm("{ .reg .u64 t; cvta.to.shared.u64 t, %1; cvt.u32.u64 %0, t; }"
        : "=r"(a) : "l"(p));
    return a;
}
__device__ __forceinline__ void cp16(uint32_t saddr, const void* g){
    asm volatile("cp.async.cg.shared.global [%0], [%1], 16;"
                 :: "r"(saddr), "l"(g) : "memory");
}
__device__ __forceinline__ void cp_commit(){
    asm volatile("cp.async.commit_group;" ::: "memory");
}
__device__ __forceinline__ void cp_wait1(){
    asm volatile("cp.async.wait_group 1;" ::: "memory");
}
__device__ __forceinline__ void cp_wait0(){
    asm volatile("cp.async.wait_group 0;" ::: "memory");
}
__device__ __forceinline__ void ldsm_x4(uint32_t& r0, uint32_t& r1, uint32_t& r2,
                                        uint32_t& r3, uint32_t addr){
    asm volatile("ldmatrix.sync.aligned.m8n8.x4.shared.b16 {%0,%1,%2,%3}, [%4];"
                 : "=r"(r0), "=r"(r1), "=r"(r2), "=r"(r3) : "r"(addr));
}
__device__ __forceinline__ void mma_f16(float (&d)[4], const uint32_t (&a)[4],
                                        const uint32_t (&b)[2]){
    asm volatile(
        "mma.sync.aligned.m16n8k16.row.col.f32.f16.f16.f32 "
        "{%0,%1,%2,%3}, {%4,%5,%6,%7}, {%8,%9}, {%0,%1,%2,%3};\n"
        : "+f"(d[0]), "+f"(d[1]), "+f"(d[2]), "+f"(d[3])
        : "r"(a[0]), "r"(a[1]), "r"(a[2]), "r"(a[3]), "r"(b[0]), "r"(b[1]));
}

enum { EPI_AV=0, EPI_ADD=1, EPI_BIAS_GELU=2, EPI_BIAS_ADD=3 };

// ---------------- weight prepass ---------------------------------------------
// Permute+convert Whg: dst row 2e = hidden_e (src e), 2e+1 = gate_e (src 768+e).
__global__ void wperm_hg(const float* __restrict__ src, __half* __restrict__ dst)
{
    const int id = blockIdx.x*blockDim.x + threadIdx.x;   // 8 halves each
    const int perlayer = 2*CDI*CDD/8;                     // 98304
    if (id >= CLL*perlayer) return;
    const int l = id / perlayer, rem = id % perlayer;
    const int r = rem / (CDD/8), c8 = rem % (CDD/8);
    const int sr = (r & 1) ? (CDI + (r >> 1)) : (r >> 1);
    const float* s = src + ((size_t)l*2*CDI + sr)*CDD + c8*8;
    __half h[8];
    #pragma unroll
    for (int j=0;j<8;j++) h[j] = __float2half_rn(s[j]);
    *reinterpret_cast<uint4*>(dst + ((size_t)l*2*CDI + r)*CDD + c8*8) =
        *reinterpret_cast<uint4*>(h);
}

// One kernel converts all three remaining weight blocks (contiguous in g_wh).
__global__ void wcvt3(const float4* __restrict__ s1, int n1,
                      const float4* __restrict__ s2, int n2,
                      const float4* __restrict__ s3, int n3,
                      __half* __restrict__ d1, __half* __restrict__ d2,
                      __half* __restrict__ d3)
{
    const int gid = blockIdx.x*blockDim.x + threadIdx.x;
    const int stride = gridDim.x*blockDim.x;
    auto conv = [&](const float4* s, __half* d, int n4){
        for (int i=gid; i<n4; i+=stride){
            const float4 v = s[i];
            __half h[4] = {__float2half_rn(v.x), __float2half_rn(v.y),
                           __float2half_rn(v.z), __float2half_rn(v.w)};
            *reinterpret_cast<uint2*>(d + (size_t)i*4) =
                *reinterpret_cast<uint2*>(h);
        }
    };
    conv(s1, d1, n1); conv(s2, d2, n2); conv(s3, d3, n3);
}

// ---------------- GEMM fp16, compile-time shapes -----------------------------
// C[M,N] = A[M,K] @ W[N,K]^T, fp16 operands, fp32 accumulate.
template<int EPI, int NN, int KK>
__global__ __launch_bounds__(256, 2)
void gemm_h(const __half* __restrict__ A, const __half* __restrict__ W,
            const float* __restrict__ bias, const float* __restrict__ add,
            void* __restrict__ Cv)
{
    extern __shared__ __align__(1024) char smem[];
    const uint32_t sb = smem_u32(smem);
    const int tid  = threadIdx.x;
    const int lane = tid & 31;
    const int warp = tid >> 5;
    const int wm   = (warp >> 2) * 64;     // warp M offset (2 warps)
    const int wn   = (warp & 3) * 32;      // warp N offset (4 warps)
    const int g    = lane >> 2;
    const int t    = lane & 3;
    const int bm = blockIdx.y * GMT;
    const int bn = blockIdx.x * GNT;

    const int rowsel = lane & 7;
    const int rowA   = rowsel + ((lane >> 3) & 1) * 8;   // mats 0,1: m; 2,3: k+8
    const int chA    = (lane >> 4) & 1;
    const int rowB   = rowsel + ((lane >> 4) & 1) * 8;   // mats 2,3 -> n+8
    const int chB    = (lane >> 3) & 1;                  // mats 1,3 -> k+8

    float acc[4][4][4];
    #pragma unroll
    for (int i=0;i<4;i++)
        #pragma unroll
        for (int j=0;j<4;j++)
            #pragma unroll
            for (int k=0;k<4;k++) acc[i][j][k] = 0.0f;

    auto load_stage = [&](int s){
        const int slot = s % NST;
        const uint32_t sA = sb + (uint32_t)slot*STG_BYTES;
        const uint32_t sB = sA + STG_A;
        const int k0 = s * KC;
        #pragma unroll
        for (int i=0;i<4;i++){                       // A: 1024 chunks
            const int q = tid + i*256;
            const int row = q >> 3, c = q & 7;
            cp16(sA + (uint32_t)(row*8 + (c ^ (row & 7)))*16u,
                 A + (size_t)(bm+row)*KK + k0 + c*8);
        }
        #pragma unroll
        for (int i=0;i<4;i++){                       // B: 1024 chunks
            const int q = tid + i*256;
            const int row = q >> 3, c = q & 7;
            cp16(sB + (uint32_t)(row*8 + (c ^ (row & 7)))*16u,
                 W + (size_t)(bn+row)*KK + k0 + c*8);
        }
    };

    auto compute = [&](int slot){
        const uint32_t sA = sb + (uint32_t)slot*STG_BYTES;
        const uint32_t sB = sA + STG_A;
        #pragma unroll
        for (int slab=0; slab<4; slab++){            // 4 x (K=16) per stage
            const uint32_t ab = sA +
                (uint32_t)((wm + rowA)*8 + (((slab<<1)|chA) ^ rowsel))*16u;
            const uint32_t bb = sB +
                (uint32_t)((wn + rowB)*8 + (((slab<<1)|chB) ^ rowsel))*16u;
            uint32_t Bf[4][2];
            #pragma unroll
            for (int n2=0; n2<2; n2++)
                ldsm_x4(Bf[2*n2][0], Bf[2*n2][1], Bf[2*n2+1][0], Bf[2*n2+1][1],
                        bb + n2*2048);
            #pragma unroll
            for (int ms=0; ms<4; ms++){
                uint32_t a[4];
                ldsm_x4(a[0], a[1], a[2], a[3], ab + ms*2048);
                #pragma unroll
                for (int ns=0; ns<4; ns++)
                    mma_f16(acc[ms][ns], a, Bf[ns]);
            }
        }
    };

    constexpr int nk = KK / KC;                      // 8 / 12 / 32
    load_stage(0); cp_commit();
    load_stage(1); cp_commit();
    #pragma unroll 1
    for (int kt=0; kt<nk; kt++){
        cp_wait1();                                  // stage kt landed
        __syncthreads();                             // visible to all warps
        if (kt+2 < nk) load_stage(kt+2);             // slot (kt+2)%3 != kt%3
        cp_commit();                                 // (possibly empty group)
        compute(kt % NST);
    }
    cp_wait0();

    // ---------------- epilogue ----------------
    #pragma unroll
    for (int ms=0; ms<4; ms++){
        const int rr = bm + wm + ms*16 + g;
        #pragma unroll
        for (int ns=0; ns<4; ns++){
            const int cc = bn + wn + ns*8 + 2*t;     // even
            float v[4] = {acc[ms][ns][0], acc[ms][ns][1],
                          acc[ms][ns][2], acc[ms][ns][3]};
            const int rows[2] = {rr, rr+8};
            #pragma unroll
            for (int h=0; h<2; h++){
                const int row = rows[h];
                if constexpr (EPI == EPI_AV){
                    const float hid = v[h*2+0], gt = v[h*2+1];
                    const float sg = 1.0f / (1.0f + __expf(-gt));
                    const float a  = 1.0f - sg;
                    float gv;
                    if (hid >= 0.0f) gv = hid + 0.5f;
                    else { const float u = __expf(hid); gv = u / (1.0f + u); }
                    reinterpret_cast<__half2*>(Cv)[(size_t)row*(NN>>1) + (cc>>1)] =
                        __floats2half2_rn(a, sg * gv);
                } else if constexpr (EPI == EPI_ADD){
                    float* C = reinterpret_cast<float*>(Cv);
                    const float2 a2 = *reinterpret_cast<const float2*>(
                        add + (size_t)row*NN + cc);
                    *reinterpret_cast<float2*>(C + (size_t)row*NN + cc) =
                        make_float2(v[h*2+0] + a2.x, v[h*2+1] + a2.y);
                } else if constexpr (EPI == EPI_BIAS_GELU){
                    float v0 = v[h*2+0] + bias[cc];
                    float v1 = v[h*2+1] + bias[cc+1];
                    v0 = 0.5f * v0 * (1.0f + erff(v0 * 0.70710678118654752f));
                    v1 = 0.5f * v1 * (1.0f + erff(v1 * 0.70710678118654752f));
                    __half* C = reinterpret_cast<__half*>(Cv);
                    *reinterpret_cast<__half2*>(C + (size_t)row*NN + cc) =
                        __floats2half2_rn(v0, v1);
                } else {   // EPI_BIAS_ADD
                    float* C = reinterpret_cast<float*>(Cv);
                    const float2 a2 = *reinterpret_cast<const float2*>(
                        add + (size_t)row*NN + cc);
                    *reinterpret_cast<float2*>(C + (size_t)row*NN + cc) =
                        make_float2(v[h*2+0] + bias[cc]   + a2.x,
                                    v[h*2+1] + bias[cc+1] + a2.y);
                }
            }
        }
    }
}

// ---------------- layernorm (D=512), warp-per-row, fp16 out ------------------
__global__ void ln_warp(const float* __restrict__ x, const float* __restrict__ gw,
                        const float* __restrict__ bw, __half* __restrict__ y)
{
    const int warp = threadIdx.x >> 5, lane = threadIdx.x & 31;
    const int row  = blockIdx.x*8 + warp;
    const float4* xr = reinterpret_cast<const float4*>(x + (size_t)row*CDD);
    float4 v[4];
    float s = 0.0f, q = 0.0f;
    #pragma unroll
    for (int j=0;j<4;j++){
        v[j] = xr[lane + j*32];
        s += (v[j].x+v[j].y)+(v[j].z+v[j].w);
        q += v[j].x*v[j].x + v[j].y*v[j].y + v[j].z*v[j].z + v[j].w*v[j].w;
    }
    #pragma unroll
    for (int o=16;o>0;o>>=1){ s += __shfl_xor_sync(0xffffffffu,s,o);
                              q += __shfl_xor_sync(0xffffffffu,q,o); }
    const float mean = s * (1.0f/CDD);
    const float rstd = rsqrtf(q*(1.0f/CDD) - mean*mean + 1e-5f);
    const float4* gr = reinterpret_cast<const float4*>(gw);
    const float4* br = reinterpret_cast<const float4*>(bw);
    uint2* yr = reinterpret_cast<uint2*>(y + (size_t)row*CDD);
    #pragma unroll
    for (int j=0;j<4;j++){
        const float4 gg = gr[lane + j*32];
        const float4 bb = br[lane + j*32];
        const __half2 h0 = __floats2half2_rn((v[j].x-mean)*rstd*gg.x + bb.x,
                                             (v[j].y-mean)*rstd*gg.y + bb.y);
        const __half2 h1 = __floats2half2_rn((v[j].z-mean)*rstd*gg.z + bb.z,
                                             (v[j].w-mean)*rstd*gg.w + bb.w);
        uint2 u;
        u.x = *reinterpret_cast<const uint32_t*>(&h0);
        u.y = *reinterpret_cast<const uint32_t*>(&h1);
        yr[lane + j*32] = u;
    }
}

// ---------------- minGRU chunked scan (2 pairs per thread, uint2 loads) -----
__global__ void scan_phase1(const uint2* __restrict__ av, float* __restrict__ P,
                            float* __restrict__ H)
{
    const int e2 = blockIdx.x*128 + threadIdx.x;         // 0..383
    const int c = blockIdx.y, b = blockIdx.z;
    const uint2* base = av + (size_t)(b*CSS + c*CCS)*(CDI/2) + e2;
    float p0 = 1.0f, h0 = 0.0f, p1 = 1.0f, h1 = 0.0f;
    #pragma unroll 4
    for (int s=0; s<CCS; s++){
        const uint2 u = base[(size_t)s*(CDI/2)];
        const float2 f0 = __half22float2(*reinterpret_cast<const __half2*>(&u.x));
        const float2 f1 = __half22float2(*reinterpret_cast<const __half2*>(&u.y));
        h0 = fmaf(f0.x, h0, f0.y); p0 *= f0.x;
        h1 = fmaf(f1.x, h1, f1.y); p1 *= f1.x;
    }
    const int idx = (b*CNC + c)*CDI + 2*e2;
    *reinterpret_cast<float2*>(P + idx) = make_float2(p0, p1);
    *reinterpret_cast<float2*>(H + idx) = make_float2(h0, h1);
}

__global__ void scan_phase3(const uint2* __restrict__ av, const float* __restrict__ P,
                            const float* __restrict__ H, __half* __restrict__ hout)
{
    const int e2 = blockIdx.x*128 + threadIdx.x;
    const int c = blockIdx.y, b = blockIdx.z;
    float h0 = 0.5f, h1 = 0.5f;                          // h_0
    for (int cc=0; cc<c; cc++){
        const int idx = (b*CNC + cc)*CDI + 2*e2;
        const float2 pp = *reinterpret_cast<const float2*>(P + idx);
        const float2 hh = *reinterpret_cast<const float2*>(H + idx);
        h0 = fmaf(pp.x, h0, hh.x);
        h1 = fmaf(pp.y, h1, hh.y);
    }
    const uint2* base = av + (size_t)(b*CSS + c*CCS)*(CDI/2) + e2;
    __half2* ob = reinterpret_cast<__half2*>(
        hout + (size_t)(b*CSS + c*CCS)*CDI + 2*e2);
    #pragma unroll 4
    for (int s=0; s<CCS; s++){
        const uint2 u = base[(size_t)s*(CDI/2)];
        const float2 f0 = __half22float2(*reinterpret_cast<const __half2*>(&u.x));
        const float2 f1 = __half22float2(*reinterpret_cast<const __half2*>(&u.y));
        h0 = fmaf(f0.x, h0, f0.y);
        h1 = fmaf(f1.x, h1, f1.y);
        ob[(size_t)s*(CDI/2)] = __floats2half2_rn(h0, h1);
    }
}

// ---------------- final LN + 2-logit head, warp-per-row ----------------------
__global__ void logits_warp(const float* __restrict__ x, const float* __restrict__ gw,
                            const float* __restrict__ bw, const float* __restrict__ Wl,
                            float* __restrict__ out)
{
    const int warp = threadIdx.x >> 5, lane = threadIdx.x & 31;
    const int row  = blockIdx.x*8 + warp;
    const float4* xr = reinterpret_cast<const float4*>(x + (size_t)row*CDD);
    float4 v[4];
    float s = 0.0f, q = 0.0f;
    #pragma unroll
    for (int j=0;j<4;j++){
        v[j] = xr[lane + j*32];
        s += (v[j].x+v[j].y)+(v[j].z+v[j].w);
        q += v[j].x*v[j].x + v[j].y*v[j].y + v[j].z*v[j].z + v[j].w*v[j].w;
    }
    #pragma unroll
    for (int o=16;o>0;o>>=1){ s += __shfl_xor_sync(0xffffffffu,s,o);
                              q += __shfl_xor_sync(0xffffffffu,q,o); }
    const float mean = s * (1.0f/CDD);
    const float rstd = rsqrtf(q*(1.0f/CDD) - mean*mean + 1e-5f);

    const float4* gr = reinterpret_cast<const float4*>(gw);
    const float4* br = reinterpret_cast<const float4*>(bw);
    const float4* w0 = reinterpret_cast<const float4*>(Wl);
    const float4* w1 = reinterpret_cast<const float4*>(Wl + CDD);
    float a0 = 0.0f, a1 = 0.0f;
    #pragma unroll
    for (int j=0;j<4;j++){
        const int idx = lane + j*32;
        const float4 gg = gr[idx], bb = br[idx];
        const float4 wa = w0[idx], wb = w1[idx];
        const float n0 = (v[j].x-mean)*rstd*gg.x + bb.x;
        const float n1 = (v[j].y-mean)*rstd*gg.y + bb.y;
        const float n2 = (v[j].z-mean)*rstd*gg.z + bb.z;
        const float n3 = (v[j].w-mean)*rstd*gg.w + bb.w;
        a0 += n0*wa.x + n1*wa.y + n2*wa.z + n3*wa.w;
        a1 += n0*wb.x + n1*wb.y + n2*wb.z + n3*wb.w;
    }
    #pragma unroll
    for (int o=16;o>0;o>>=1){ a0 += __shfl_xor_sync(0xffffffffu,a0,o);
                              a1 += __shfl_xor_sync(0xffffffffu,a1,o); }
    if (lane == 0){
        out[(size_t)row*2 + 0] = a0;
        out[(size_t)row*2 + 1] = a1;
    }
}

// ---------------- driver ----------------------------------------------------
extern "C" void kernel_launch(void* const* d_in, const int* in_sizes, int n_in,
                              void* d_out, int out_size)
{
    const float* input  = (const float*)d_in[0];
    const float* Whg    = (const float*)d_in[1];
    const float* Wout   = (const float*)d_in[2];
    const float* ln1_g  = (const float*)d_in[3];
    const float* ln1_b  = (const float*)d_in[4];
    const float* ln2_g  = (const float*)d_in[5];
    const float* ln2_b  = (const float*)d_in[6];
    const float* ffW1   = (const float*)d_in[7];
    const float* ffb1   = (const float*)d_in[8];
    const float* ffW2   = (const float*)d_in[9];
    const float* ffb2   = (const float*)d_in[10];
    const float* norm_g = (const float*)d_in[11];
    const float* norm_b = (const float*)d_in[12];
    const float* Wlog   = (const float*)d_in[13];
    float* out = (float*)d_out;

    __half *xn, *h, *ffh, *wh; __half2 *av; float *y, *x, *P, *Hc;
    cudaGetSymbolAddress((void**)&xn,  g_xn);
    cudaGetSymbolAddress((void**)&av,  g_av);
    cudaGetSymbolAddress((void**)&h,   g_h);
    cudaGetSymbolAddress((void**)&y,   g_y);
    cudaGetSymbolAddress((void**)&x,   g_x);
    cudaGetSymbolAddress((void**)&ffh, g_ffh);
    cudaGetSymbolAddress((void**)&P,   g_P);
    cudaGetSymbolAddress((void**)&Hc,  g_Hc);
    cudaGetSymbolAddress((void**)&wh,  g_wh);

    __half* w_hg  = wh;
    __half* w_out = w_hg  + W_HG_SZ;
    __half* w_f1  = w_out + W_OUT_SZ;
    __half* w_f2  = w_f1  + W_F1_SZ;

    cudaFuncSetAttribute(gemm_h<EPI_AV, 2*CDI, CDD>,
        cudaFuncAttributeMaxDynamicSharedMemorySize, SMEM_DYN);
    cudaFuncSetAttribute(gemm_h<EPI_ADD, CDD, CDI>,
        cudaFuncAttributeMaxDynamicSharedMemorySize, SMEM_DYN);
    cudaFuncSetAttribute(gemm_h<EPI_BIAS_GELU, CFF, CDD>,
        cudaFuncAttributeMaxDynamicSharedMemorySize, SMEM_DYN);
    cudaFuncSetAttribute(gemm_h<EPI_BIAS_ADD, CDD, CFF>,
        cudaFuncAttributeMaxDynamicSharedMemorySize, SMEM_DYN);

    // weight prepass (2 launches)
    wperm_hg<<<(int)(W_HG_SZ/8 + 255)/256, 256>>>(Whg, w_hg);
    wcvt3<<<4096, 256>>>((const float4*)Wout, (int)(W_OUT_SZ/4),
                         (const float4*)ffW1, (int)(W_F1_SZ/4),
                         (const float4*)ffW2, (int)(W_F2_SZ/4),
                         w_out, w_f1, w_f2);

    const int M = CMM;
    const dim3 scan_grid(3, CNC, CBB);   // 384 uint2 lanes / 128 thr = 3

    for (int i=0; i<CLL; i++){
        const float* cur = (i==0) ? input : x;

        ln_warp<<<M/8, 256>>>(cur, ln1_g + i*CDD, ln1_b + i*CDD, xn);
        gemm_h<EPI_AV, 2*CDI, CDD><<<dim3(2*CDI/GNT, M/GMT), 256, SMEM_DYN>>>(
            xn, w_hg + (size_t)i*2*CDI*CDD, nullptr, nullptr, av);
        scan_phase1<<<scan_grid, 128>>>((const uint2*)av, P, Hc);
        scan_phase3<<<scan_grid, 128>>>((const uint2*)av, P, Hc, h);
        gemm_h<EPI_ADD, CDD, CDI><<<dim3(CDD/GNT, M/GMT), 256, SMEM_DYN>>>(
            h, w_out + (size_t)i*CDD*CDI, nullptr, cur, y);
        ln_warp<<<M/8, 256>>>(y, ln2_g + i*CDD, ln2_b + i*CDD, xn);
        gemm_h<EPI_BIAS_GELU, CFF, CDD><<<dim3(CFF/GNT, M/GMT), 256, SMEM_DYN>>>(
            xn, w_f1 + (size_t)i*CFF*CDD, ffb1 + i*CFF, nullptr, ffh);
        gemm_h<EPI_BIAS_ADD, CDD, CFF><<<dim3(CDD/GNT, M/GMT), 256, SMEM_DYN>>>(
            ffh, w_f2 + (size_t)i*CDD*CFF, ffb2 + i*CDD, y, x);
    }

    logits_warp<<<M/8, 256>>>(x, norm_g, norm_b, Wlog, out);
}

// round 10
// speedup vs baseline: 3.7627x; 1.0309x over previous
#include <cuda_runtime.h>
#include <cuda_fp16.h>
#include <cstdint>
#include <cstddef>

// Problem constants
#define CBB 8
#define CSS 4096
#define CDD 512
#define CLL 4
#define CDI 768
#define CFF 2048
#define CMM (CBB*CSS)          // 32768 rows
#define CNC 64                 // scan chunks
#define CCS (CSS/CNC)          // 64 per chunk

// weight scratch sizes (elements)
#define W_HG_SZ  ((size_t)CLL*2*CDI*CDD)
#define W_OUT_SZ ((size_t)CLL*CDD*CDI)
#define W_F1_SZ  ((size_t)CLL*CFF*CDD)
#define W_F2_SZ  ((size_t)CLL*CDD*CFF)

// GEMM tiling: CTA 128(M) x 128(N), 8 warps (2m x 4n), warp tile 64x32.
// fp16 m16n8k16. K staged 64 halves (128B rows, 8x16B chunks, swizzle c^(row&7)).
// 96KB smem + 128 regs => 2 CTAs per SM.
#define GMT 128
#define GNT 128
#define KC  64                           // halves per stage
#define NST 3
#define STG_A 16384
#define STG_B 16384
#define STG_BYTES (STG_A + STG_B)        // 32768
#define SMEM_DYN (NST*STG_BYTES)         // 98304
#define SPITCH 133                       // fused-scan smem pitch (bank spread)

// ---------------- scratch (device globals; no allocation allowed) ----------
static __device__ __align__(256) __half   g_xn [(size_t)CMM*CDD];   // LN out (fp16)
static __device__ __align__(256) __half2  g_av [(size_t)CMM*CDI];   // (a, v) pairs
static __device__ __align__(256) __half   g_h  [(size_t)CMM*CDI];   // scan out (fp16)
static __device__ __align__(256) float    g_y  [(size_t)CMM*CDD];   // residual (fp32)
static __device__ __align__(256) float    g_x  [(size_t)CMM*CDD];   // layer out (fp32)
static __device__ __align__(256) __half   g_ffh[(size_t)CMM*CFF];   // ff hidden (fp16)
static __device__ __align__(256) __half   g_wh [W_HG_SZ + W_OUT_SZ + W_F1_SZ + W_F2_SZ];
static __device__ __align__(256) float    g_P  [CBB*CNC*CDI];
static __device__ __align__(256) float    g_Hc [CBB*CNC*CDI];

// ---------------- helpers ----------------------------------------------------
__device__ __forceinline__ uint32_t smem_u32(const void* p){
    uint32_t a;
    asm("{ .reg .u64 t; cvta.to.shared.u64 t, %1; cvt.u32.u64 %0, t; }"
        : "=r"(a) : "l"(p));
    return a;
}
__device__ __forceinline__ void cp16(uint32_t saddr, const void* g){
    asm volatile("cp.async.cg.shared.global [%0], [%1], 16;"
                 :: "r"(saddr), "l"(g) : "memory");
}
__device__ __forceinline__ void cp_commit(){
    asm volatile("cp.async.commit_group;" ::: "memory");
}
__device__ __forceinline__ void cp_wait1(){
    asm volatile("cp.async.wait_group 1;" ::: "memory");
}
__device__ __forceinline__ void cp_wait0(){
    asm volatile("cp.async.wait_group 0;" ::: "memory");
}
__device__ __forceinline__ void ldsm_x4(uint32_t& r0, uint32_t& r1, uint32_t& r2,
                                        uint32_t& r3, uint32_t addr){
    asm volatile("ldmatrix.sync.aligned.m8n8.x4.shared.b16 {%0,%1,%2,%3}, [%4];"
                 : "=r"(r0), "=r"(r1), "=r"(r2), "=r"(r3) : "r"(addr));
}
__device__ __forceinline__ void mma_f16(float (&d)[4], const uint32_t (&a)[4],
                                        const uint32_t (&b)[2]){
    asm volatile(
        "mma.sync.aligned.m16n8k16.row.col.f32.f16.f16.f32 "
        "{%0,%1,%2,%3}, {%4,%5,%6,%7}, {%8,%9}, {%0,%1,%2,%3};\n"
        : "+f"(d[0]), "+f"(d[1]), "+f"(d[2]), "+f"(d[3])
        : "r"(a[0]), "r"(a[1]), "r"(a[2]), "r"(a[3]), "r"(b[0]), "r"(b[1]));
}

enum { EPI_AV=0, EPI_ADD=1, EPI_BIAS_GELU=2, EPI_BIAS_ADD=3 };

// ---------------- weight prepass ---------------------------------------------
// Permute+convert Whg: dst row 2e = hidden_e (src e), 2e+1 = gate_e (src 768+e).
__global__ void wperm_hg(const float* __restrict__ src, __half* __restrict__ dst)
{
    const int id = blockIdx.x*blockDim.x + threadIdx.x;   // 8 halves each
    const int perlayer = 2*CDI*CDD/8;                     // 98304
    if (id >= CLL*perlayer) return;
    const int l = id / perlayer, rem = id % perlayer;
    const int r = rem / (CDD/8), c8 = rem % (CDD/8);
    const int sr = (r & 1) ? (CDI + (r >> 1)) : (r >> 1);
    const float* s = src + ((size_t)l*2*CDI + sr)*CDD + c8*8;
    __half h[8];
    #pragma unroll
    for (int j=0;j<8;j++) h[j] = __float2half_rn(s[j]);
    *reinterpret_cast<uint4*>(dst + ((size_t)l*2*CDI + r)*CDD + c8*8) =
        *reinterpret_cast<uint4*>(h);
}

// One kernel converts all three remaining weight blocks.
__global__ void wcvt3(const float4* __restrict__ s1, int n1,
                      const float4* __restrict__ s2, int n2,
                      const float4* __restrict__ s3, int n3,
                      __half* __restrict__ d1, __half* __restrict__ d2,
                      __half* __restrict__ d3)
{
    const int gid = blockIdx.x*blockDim.x + threadIdx.x;
    const int stride = gridDim.x*blockDim.x;
    auto conv = [&](const float4* s, __half* d, int n4){
        for (int i=gid; i<n4; i+=stride){
            const float4 v = s[i];
            __half h[4] = {__float2half_rn(v.x), __float2half_rn(v.y),
                           __float2half_rn(v.z), __float2half_rn(v.w)};
            *reinterpret_cast<uint2*>(d + (size_t)i*4) =
                *reinterpret_cast<uint2*>(h);
        }
    };
    conv(s1, d1, n1); conv(s2, d2, n2); conv(s3, d3, n3);
}

// ---------------- GEMM fp16, compile-time shapes + slots ---------------------
// C[M,N] = A[M,K] @ W[N,K]^T, fp16 operands, fp32 accumulate.
// EPI_AV additionally performs the chunk-level scan reduction (phase 1) in
// smem and writes P/H: CTA M-tile (128 rows) == 2 scan chunks, CTA N-tile
// owns a disjoint e-range, so (b, chunk, e) products are CTA-local.
template<int EPI, int NN, int KK>
__global__ __launch_bounds__(256, 2)
void gemm_h(const __half* __restrict__ A, const __half* __restrict__ W,
            const float* __restrict__ bias, const float* __restrict__ add,
            void* __restrict__ Cv, float* __restrict__ Pg, float* __restrict__ Hg)
{
    extern __shared__ __align__(1024) char smem[];
    const uint32_t sb = smem_u32(smem);
    const int tid  = threadIdx.x;
    const int lane = tid & 31;
    const int warp = tid >> 5;
    const int wm   = (warp >> 2) * 64;     // warp M offset (2 warps)
    const int wn   = (warp & 3) * 32;      // warp N offset (4 warps)
    const int g    = lane >> 2;
    const int t    = lane & 3;
    const int bm = blockIdx.y * GMT;
    const int bn = blockIdx.x * GNT;

    const int rowsel = lane & 7;
    const int rowA   = rowsel + ((lane >> 3) & 1) * 8;   // mats 0,1: m; 2,3: k+8
    const int chA    = (lane >> 4) & 1;
    const int rowB   = rowsel + ((lane >> 4) & 1) * 8;   // mats 2,3 -> n+8
    const int chB    = (lane >> 3) & 1;                  // mats 1,3 -> k+8

    float acc[4][4][4];
    #pragma unroll
    for (int i=0;i<4;i++)
        #pragma unroll
        for (int j=0;j<4;j++)
            #pragma unroll
            for (int k=0;k<4;k++) acc[i][j][k] = 0.0f;

    auto load_stage = [&](int s, int slot){
        const uint32_t sA = sb + (uint32_t)(slot*STG_BYTES);
        const uint32_t sB = sA + STG_A;
        const int k0 = s * KC;
        #pragma unroll
        for (int i=0;i<4;i++){                       // A: 1024 chunks
            const int q = tid + i*256;
            const int row = q >> 3, c = q & 7;
            cp16(sA + (uint32_t)(row*8 + (c ^ (row & 7)))*16u,
                 A + (size_t)(bm+row)*KK + k0 + c*8);
        }
        #pragma unroll
        for (int i=0;i<4;i++){                       // B: 1024 chunks
            const int q = tid + i*256;
            const int row = q >> 3, c = q & 7;
            cp16(sB + (uint32_t)(row*8 + (c ^ (row & 7)))*16u,
                 W + (size_t)(bn+row)*KK + k0 + c*8);
        }
    };

    auto compute = [&](int slot){
        const uint32_t sA = sb + (uint32_t)(slot*STG_BYTES);
        const uint32_t sB = sA + STG_A;
        #pragma unroll
        for (int slab=0; slab<4; slab++){            // 4 x (K=16) per stage
            const uint32_t ab = sA +
                (uint32_t)((wm + rowA)*8 + (((slab<<1)|chA) ^ rowsel))*16u;
            const uint32_t bb = sB +
                (uint32_t)((wn + rowB)*8 + (((slab<<1)|chB) ^ rowsel))*16u;
            uint32_t Bf[4][2];
            #pragma unroll
            for (int n2=0; n2<2; n2++)
                ldsm_x4(Bf[2*n2][0], Bf[2*n2][1], Bf[2*n2+1][0], Bf[2*n2+1][1],
                        bb + n2*2048);
            #pragma unroll
            for (int ms=0; ms<4; ms++){
                uint32_t a[4];
                ldsm_x4(a[0], a[1], a[2], a[3], ab + ms*2048);
                #pragma unroll
                for (int ns=0; ns<4; ns++)
                    mma_f16(acc[ms][ns], a, Bf[ns]);
            }
        }
    };

    constexpr int nk = KK / KC;                      // 8 / 12 / 32
    load_stage(0, 0); cp_commit();
    load_stage(1, 1); cp_commit();
    #pragma unroll 1
    for (int base = 0; base < nk; base += 3){
        // step kt = base (slot 0)
        cp_wait1(); __syncthreads();
        if (base+2 < nk) load_stage(base+2, 2);
        cp_commit();
        compute(0);
        if (base+1 < nk){                            // kt = base+1 (slot 1)
            cp_wait1(); __syncthreads();
            if (base+3 < nk) load_stage(base+3, 0);
            cp_commit();
            compute(1);
        }
        if (base+2 < nk){                            // kt = base+2 (slot 2)
            cp_wait1(); __syncthreads();
            if (base+4 < nk) load_stage(base+4, 1);
            cp_commit();
            compute(2);
        }
    }
    cp_wait0();

    // ---------------- epilogue ----------------
    if constexpr (EPI == EPI_AV){
        // Stage smem is dead; reuse for the chunk scan. Sync: some warps may
        // still be ldsm-reading the last stage.
        __syncthreads();
        float* sa = reinterpret_cast<float*>(smem);
        float* sv = sa + 64*SPITCH;
        #pragma unroll
        for (int ms=0; ms<4; ms++){
            #pragma unroll
            for (int ns=0; ns<4; ns++){
                const int cp = (wn >> 1) + ns*4 + t;        // 0..63
                #pragma unroll
                for (int hh=0; hh<2; hh++){
                    const int rl = wm + ms*16 + g + 8*hh;   // 0..127
                    const float hid = acc[ms][ns][hh*2+0];
                    const float gt  = acc[ms][ns][hh*2+1];
                    const float sg = 1.0f / (1.0f + __expf(-gt));
                    const float a  = 1.0f - sg;
                    float gv;
                    if (hid >= 0.0f) gv = hid + 0.5f;
                    else { const float u = __expf(hid); gv = u / (1.0f + u); }
                    const __half2 pair = __floats2half2_rn(a, sg * gv);
                    reinterpret_cast<__half2*>(Cv)[
                        (size_t)(bm+rl)*(NN>>1) + (bn>>1) + cp] = pair;
                    // rounded values -> scan (bit-identical to old phase1)
                    const float2 fr = __half22float2(pair);
                    sa[cp*SPITCH + rl] = fr.x;
                    sv[cp*SPITCH + rl] = fr.y;
                }
            }
        }
        __syncthreads();
        if (tid < 128){
            const int chunk = tid >> 6, cp = tid & 63;
            const float* pa = sa + cp*SPITCH + chunk*64;
            const float* pv = sv + cp*SPITCH + chunk*64;
            float p = 1.0f, h = 0.0f;
            #pragma unroll 8
            for (int s=0; s<CCS; s++){
                const float a = pa[s], v = pv[s];
                h = fmaf(a, h, v);
                p *= a;
            }
            const int b = bm >> 12;
            const int c = ((bm & 4095) >> 6) + chunk;
            const int e = (bn >> 1) + cp;
            const int idx = (b*CNC + c)*CDI + e;
            Pg[idx] = p; Hg[idx] = h;
        }
    } else {
        #pragma unroll
        for (int ms=0; ms<4; ms++){
            const int rr = bm + wm + ms*16 + g;
            #pragma unroll
            for (int ns=0; ns<4; ns++){
                const int cc = bn + wn + ns*8 + 2*t;     // even
                float v[4] = {acc[ms][ns][0], acc[ms][ns][1],
                              acc[ms][ns][2], acc[ms][ns][3]};
                const int rows[2] = {rr, rr+8};
                #pragma unroll
                for (int h=0; h<2; h++){
                    const int row = rows[h];
                    if constexpr (EPI == EPI_ADD){
                        float* C = reinterpret_cast<float*>(Cv);
                        const float2 a2 = *reinterpret_cast<const float2*>(
                            add + (size_t)row*NN + cc);
                        *reinterpret_cast<float2*>(C + (size_t)row*NN + cc) =
                            make_float2(v[h*2+0] + a2.x, v[h*2+1] + a2.y);
                    } else if constexpr (EPI == EPI_BIAS_GELU){
                        float v0 = v[h*2+0] + bias[cc];
                        float v1 = v[h*2+1] + bias[cc+1];
                        v0 = 0.5f*v0*(1.0f + erff(v0 * 0.70710678118654752f));
                        v1 = 0.5f*v1*(1.0f + erff(v1 * 0.70710678118654752f));
                        __half* C = reinterpret_cast<__half*>(Cv);
                        *reinterpret_cast<__half2*>(C + (size_t)row*NN + cc) =
                            __floats2half2_rn(v0, v1);
                    } else {   // EPI_BIAS_ADD
                        float* C = reinterpret_cast<float*>(Cv);
                        const float2 a2 = *reinterpret_cast<const float2*>(
                            add + (size_t)row*NN + cc);
                        *reinterpret_cast<float2*>(C + (size_t)row*NN + cc) =
                            make_float2(v[h*2+0] + bias[cc]   + a2.x,
                                        v[h*2+1] + bias[cc+1] + a2.y);
                    }
                }
            }
        }
    }
}

// ---------------- layernorm (D=512), warp-per-row, fp16 out ------------------
__global__ void ln_warp(const float* __restrict__ x, const float* __restrict__ gw,
                        const float* __restrict__ bw, __half* __restrict__ y)
{
    const int warp = threadIdx.x >> 5, lane = threadIdx.x & 31;
    const int row  = blockIdx.x*8 + warp;
    const float4* xr = reinterpret_cast<const float4*>(x + (size_t)row*CDD);
    float4 v[4];
    float s = 0.0f, q = 0.0f;
    #pragma unroll
    for (int j=0;j<4;j++){
        v[j] = xr[lane + j*32];
        s += (v[j].x+v[j].y)+(v[j].z+v[j].w);
        q += v[j].x*v[j].x + v[j].y*v[j].y + v[j].z*v[j].z + v[j].w*v[j].w;
    }
    #pragma unroll
    for (int o=16;o>0;o>>=1){ s += __shfl_xor_sync(0xffffffffu,s,o);
                              q += __shfl_xor_sync(0xffffffffu,q,o); }
    const float mean = s * (1.0f/CDD);
    const float rstd = rsqrtf(q*(1.0f/CDD) - mean*mean + 1e-5f);
    const float4* gr = reinterpret_cast<const float4*>(gw);
    const float4* br = reinterpret_cast<const float4*>(bw);
    uint2* yr = reinterpret_cast<uint2*>(y + (size_t)row*CDD);
    #pragma unroll
    for (int j=0;j<4;j++){
        const float4 gg = gr[lane + j*32];
        const float4 bb = br[lane + j*32];
        const __half2 h0 = __floats2half2_rn((v[j].x-mean)*rstd*gg.x + bb.x,
                                             (v[j].y-mean)*rstd*gg.y + bb.y);
        const __half2 h1 = __floats2half2_rn((v[j].z-mean)*rstd*gg.z + bb.z,
                                             (v[j].w-mean)*rstd*gg.w + bb.w);
        uint2 u;
        u.x = *reinterpret_cast<const uint32_t*>(&h0);
        u.y = *reinterpret_cast<const uint32_t*>(&h1);
        yr[lane + j*32] = u;
    }
}

// ---------------- scan phase 3 (phase 1 now fused into hg GEMM) -------------
__global__ void scan_phase3(const uint2* __restrict__ av, const float* __restrict__ P,
                            const float* __restrict__ H, __half* __restrict__ hout)
{
    const int e2 = blockIdx.x*128 + threadIdx.x;
    const int c = blockIdx.y, b = blockIdx.z;
    float h0 = 0.5f, h1 = 0.5f;                          // h_0
    for (int cc=0; cc<c; cc++){
        const int idx = (b*CNC + cc)*CDI + 2*e2;
        const float2 pp = *reinterpret_cast<const float2*>(P + idx);
        const float2 hh = *reinterpret_cast<const float2*>(H + idx);
        h0 = fmaf(pp.x, h0, hh.x);
        h1 = fmaf(pp.y, h1, hh.y);
    }
    const uint2* base = av + (size_t)(b*CSS + c*CCS)*(CDI/2) + e2;
    __half2* ob = reinterpret_cast<__half2*>(
        hout + (size_t)(b*CSS + c*CCS)*CDI + 2*e2);
    #pragma unroll 4
    for (int s=0; s<CCS; s++){
        const uint2 u = base[(size_t)s*(CDI/2)];
        const float2 f0 = __half22float2(*reinterpret_cast<const __half2*>(&u.x));
        const float2 f1 = __half22float2(*reinterpret_cast<const __half2*>(&u.y));
        h0 = fmaf(f0.x, h0, f0.y);
        h1 = fmaf(f1.x, h1, f1.y);
        ob[(size_t)s*(CDI/2)] = __floats2half2_rn(h0, h1);
    }
}

// ---------------- final LN + 2-logit head, warp-per-row ----------------------
__global__ void logits_warp(const float* __restrict__ x, const float* __restrict__ gw,
                            const float* __restrict__ bw, const float* __restrict__ Wl,
                            float* __restrict__ out)
{
    const int warp = threadIdx.x >> 5, lane = threadIdx.x & 31;
    const int row  = blockIdx.x*8 + warp;
    const float4* xr = reinterpret_cast<const float4*>(x + (size_t)row*CDD);
    float4 v[4];
    float s = 0.0f, q = 0.0f;
    #pragma unroll
    for (int j=0;j<4;j++){
        v[j] = xr[lane + j*32];
        s += (v[j].x+v[j].y)+(v[j].z+v[j].w);
        q += v[j].x*v[j].x + v[j].y*v[j].y + v[j].z*v[j].z + v[j].w*v[j].w;
    }
    #pragma unroll
    for (int o=16;o>0;o>>=1){ s += __shfl_xor_sync(0xffffffffu,s,o);
                              q += __shfl_xor_sync(0xffffffffu,q,o); }
    const float mean = s * (1.0f/CDD);
    const float rstd = rsqrtf(q*(1.0f/CDD) - mean*mean + 1e-5f);

    const float4* gr = reinterpret_cast<const float4*>(gw);
    const float4* br = reinterpret_cast<const float4*>(bw);
    const float4* w0 = reinterpret_cast<const float4*>(Wl);
    const float4* w1 = reinterpret_cast<const float4*>(Wl + CDD);
    float a0 = 0.0f, a1 = 0.0f;
    #pragma unroll
    for (int j=0;j<4;j++){
        const int idx = lane + j*32;
        const float4 gg = gr[idx], bb = br[idx];
        const float4 wa = w0[idx], wb = w1[idx];
        const float n0 = (v[j].x-mean)*rstd*gg.x + bb.x;
        const float n1 = (v[j].y-mean)*rstd*gg.y + bb.y;
        const float n2 = (v[j].z-mean)*rstd*gg.z + bb.z;
        const float n3 = (v[j].w-mean)*rstd*gg.w + bb.w;
        a0 += n0*wa.x + n1*wa.y + n2*wa.z + n3*wa.w;
        a1 += n0*wb.x + n1*wb.y + n2*wb.z + n3*wb.w;
    }
    #pragma unroll
    for (int o=16;o>0;o>>=1){ a0 += __shfl_xor_sync(0xffffffffu,a0,o);
                              a1 += __shfl_xor_sync(0xffffffffu,a1,o); }
    if (lane == 0){
        out[(size_t)row*2 + 0] = a0;
        out[(size_t)row*2 + 1] = a1;
    }
}

// ---------------- driver ----------------------------------------------------
extern "C" void kernel_launch(void* const* d_in, const int* in_sizes, int n_in,
                              void* d_out, int out_size)
{
    const float* input  = (const float*)d_in[0];
    const float* Whg    = (const float*)d_in[1];
    const float* Wout   = (const float*)d_in[2];
    const float* ln1_g  = (const float*)d_in[3];
    const float* ln1_b  = (const float*)d_in[4];
    const float* ln2_g  = (const float*)d_in[5];
    const float* ln2_b  = (const float*)d_in[6];
    const float* ffW1   = (const float*)d_in[7];
    const float* ffb1   = (const float*)d_in[8];
    const float* ffW2   = (const float*)d_in[9];
    const float* ffb2   = (const float*)d_in[10];
    const float* norm_g = (const float*)d_in[11];
    const float* norm_b = (const float*)d_in[12];
    const float* Wlog   = (const float*)d_in[13];
    float* out = (float*)d_out;

    __half *xn, *h, *ffh, *wh; __half2 *av; float *y, *x, *P, *Hc;
    cudaGetSymbolAddress((void**)&xn,  g_xn);
    cudaGetSymbolAddress((void**)&av,  g_av);
    cudaGetSymbolAddress((void**)&h,   g_h);
    cudaGetSymbolAddress((void**)&y,   g_y);
    cudaGetSymbolAddress((void**)&x,   g_x);
    cudaGetSymbolAddress((void**)&ffh, g_ffh);
    cudaGetSymbolAddress((void**)&P,   g_P);
    cudaGetSymbolAddress((void**)&Hc,  g_Hc);
    cudaGetSymbolAddress((void**)&wh,  g_wh);

    __half* w_hg  = wh;
    __half* w_out = w_hg  + W_HG_SZ;
    __half* w_f1  = w_out + W_OUT_SZ;
    __half* w_f2  = w_f1  + W_F1_SZ;

    cudaFuncSetAttribute(gemm_h<EPI_AV, 2*CDI, CDD>,
        cudaFuncAttributeMaxDynamicSharedMemorySize, SMEM_DYN);
    cudaFuncSetAttribute(gemm_h<EPI_ADD, CDD, CDI>,
        cudaFuncAttributeMaxDynamicSharedMemorySize, SMEM_DYN);
    cudaFuncSetAttribute(gemm_h<EPI_BIAS_GELU, CFF, CDD>,
        cudaFuncAttributeMaxDynamicSharedMemorySize, SMEM_DYN);
    cudaFuncSetAttribute(gemm_h<EPI_BIAS_ADD, CDD, CFF>,
        cudaFuncAttributeMaxDynamicSharedMemorySize, SMEM_DYN);

    // weight prepass (2 launches)
    wperm_hg<<<(int)(W_HG_SZ/8 + 255)/256, 256>>>(Whg, w_hg);
    wcvt3<<<4096, 256>>>((const float4*)Wout, (int)(W_OUT_SZ/4),
                         (const float4*)ffW1, (int)(W_F1_SZ/4),
                         (const float4*)ffW2, (int)(W_F2_SZ/4),
                         w_out, w_f1, w_f2);

    const int M = CMM;
    const dim3 scan_grid(3, CNC, CBB);   // 384 uint2 lanes / 128 thr = 3

    for (int i=0; i<CLL; i++){
        const float* cur = (i==0) ? input : x;

        ln_warp<<<M/8, 256>>>(cur, ln1_g + i*CDD, ln1_b + i*CDD, xn);
        // hg GEMM: fused gates + chunk-scan (phase 1) -> av, P, Hc
        gemm_h<EPI_AV, 2*CDI, CDD><<<dim3(2*CDI/GNT, M/GMT), 256, SMEM_DYN>>>(
            xn, w_hg + (size_t)i*2*CDI*CDD, nullptr, nullptr, av, P, Hc);
        scan_phase3<<<scan_grid, 128>>>((const uint2*)av, P, Hc, h);
        gemm_h<EPI_ADD, CDD, CDI><<<dim3(CDD/GNT, M/GMT), 256, SMEM_DYN>>>(
            h, w_out + (size_t)i*CDD*CDI, nullptr, cur, y, nullptr, nullptr);
        ln_warp<<<M/8, 256>>>(y, ln2_g + i*CDD, ln2_b + i*CDD, xn);
        gemm_h<EPI_BIAS_GELU, CFF, CDD><<<dim3(CFF/GNT, M/GMT), 256, SMEM_DYN>>>(
            xn, w_f1 + (size_t)i*CFF*CDD, ffb1 + i*CFF, nullptr, ffh, nullptr, nullptr);
        gemm_h<EPI_BIAS_ADD, CDD, CFF><<<dim3(CDD/GNT, M/GMT), 256, SMEM_DYN>>>(
            ffh, w_f2 + (size_t)i*CDD*CFF, ffb2 + i*CDD, y, x, nullptr, nullptr);
    }

    logits_warp<<<M/8, 256>>>(x, norm_g, norm_b, Wlog, out);
}

// round 13
// speedup vs baseline: 3.7728x; 1.0027x over previous
#include <cuda_runtime.h>
#include <cuda_fp16.h>
#include <cstdint>
#include <cstddef>

// Problem constants
#define CBB 8
#define CSS 4096
#define CDD 512
#define CLL 4
#define CDI 768
#define CFF 2048
#define CMM (CBB*CSS)          // 32768 rows
#define CNC 64                 // scan chunks
#define CCS (CSS/CNC)          // 64 per chunk

// weight scratch sizes (elements)
#define W_HG_SZ  ((size_t)CLL*2*CDI*CDD)
#define W_OUT_SZ ((size_t)CLL*CDD*CDI)
#define W_F1_SZ  ((size_t)CLL*CFF*CDD)
#define W_F2_SZ  ((size_t)CLL*CDD*CFF)

// GEMM tiling: CTA 128(M) x 128(N), 8 warps (2m x 4n), warp tile 64x32.
// fp16 m16n8k16. K staged 64 halves (128B rows, 8x16B chunks, swizzle c^(row&7)).
// 96KB smem + 128 regs => 2 CTAs per SM.
#define GMT 128
#define GNT 128
#define KC  64                           // halves per stage
#define NST 3
#define STG_A 16384
#define STG_B 16384
#define STG_BYTES (STG_A + STG_B)        // 32768
#define SMEM_DYN (NST*STG_BYTES)         // 98304
#define SPITCH 133                       // fused-scan smem pitch (bank spread)

// ---------------- scratch (device globals; no allocation allowed) ----------
static __device__ __align__(256) __half   g_xn [(size_t)CMM*CDD];   // LN out (fp16)
static __device__ __align__(256) __half2  g_av [(size_t)CMM*CDI];   // (a, v) pairs
static __device__ __align__(256) __half   g_h  [(size_t)CMM*CDI];   // scan out (fp16)
static __device__ __align__(256) float    g_y  [(size_t)CMM*CDD];   // residual (fp32)
static __device__ __align__(256) float    g_x  [(size_t)CMM*CDD];   // layer out (fp32)
static __device__ __align__(256) __half   g_ffh[(size_t)CMM*CFF];   // ff hidden (fp16)
static __device__ __align__(256) __half   g_wh [W_HG_SZ + W_OUT_SZ + W_F1_SZ + W_F2_SZ];
static __device__ __align__(256) float    g_P  [CBB*CNC*CDI];
static __device__ __align__(256) float    g_Hc [CBB*CNC*CDI];
static __device__ __align__(256) float    g_Cy [CBB*CNC*CDI];       // chunk carries

// ---------------- helpers ----------------------------------------------------
__device__ __forceinline__ uint32_t smem_u32(const void* p){
    uint32_t a;
    asm("{ .reg .u64 t; cvta.to.shared.u64 t, %1; cvt.u32.u64 %0, t; }"
        : "=r"(a) : "l"(p));
    return a;
}
__device__ __forceinline__ void cp16(uint32_t saddr, const void* g){
    asm volatile("cp.async.cg.shared.global [%0], [%1], 16;"
                 :: "r"(saddr), "l"(g) : "memory");
}
__device__ __forceinline__ void cp_commit(){
    asm volatile("cp.async.commit_group;" ::: "memory");
}
__device__ __forceinline__ void cp_wait1(){
    asm volatile("cp.async.wait_group 1;" ::: "memory");
}
__device__ __forceinline__ void cp_wait0(){
    asm volatile("cp.async.wait_group 0;" ::: "memory");
}
__device__ __forceinline__ void ldsm_x4(uint32_t& r0, uint32_t& r1, uint32_t& r2,
                                        uint32_t& r3, uint32_t addr){
    asm volatile("ldmatrix.sync.aligned.m8n8.x4.shared.b16 {%0,%1,%2,%3}, [%4];"
                 : "=r"(r0), "=r"(r1), "=r"(r2), "=r"(r3) : "r"(addr));
}
__device__ __forceinline__ void mma_f16(float (&d)[4], const uint32_t (&a)[4],
                                        const uint32_t (&b)[2]){
    asm volatile(
        "mma.sync.aligned.m16n8k16.row.col.f32.f16.f16.f32 "
        "{%0,%1,%2,%3}, {%4,%5,%6,%7}, {%8,%9}, {%0,%1,%2,%3};\n"
        : "+f"(d[0]), "+f"(d[1]), "+f"(d[2]), "+f"(d[3])
        : "r"(a[0]), "r"(a[1]), "r"(a[2]), "r"(a[3]), "r"(b[0]), "r"(b[1]));
}

enum { EPI_AV=0, EPI_ADD=1, EPI_BIAS_GELU=2, EPI_BIAS_ADD=3 };

// ---------------- weight prepass ---------------------------------------------
// Permute+convert Whg: dst row 2e = hidden_e (src e), 2e+1 = gate_e (src 768+e).
__global__ void wperm_hg(const float* __restrict__ src, __half* __restrict__ dst)
{
    const int id = blockIdx.x*blockDim.x + threadIdx.x;   // 8 halves each
    const int perlayer = 2*CDI*CDD/8;                     // 98304
    if (id >= CLL*perlayer) return;
    const int l = id / perlayer, rem = id % perlayer;
    const int r = rem / (CDD/8), c8 = rem % (CDD/8);
    const int sr = (r & 1) ? (CDI + (r >> 1)) : (r >> 1);
    const float* s = src + ((size_t)l*2*CDI + sr)*CDD + c8*8;
    __half h[8];
    #pragma unroll
    for (int j=0;j<8;j++) h[j] = __float2half_rn(s[j]);
    *reinterpret_cast<uint4*>(dst + ((size_t)l*2*CDI + r)*CDD + c8*8) =
        *reinterpret_cast<uint4*>(h);
}

// One kernel converts all three remaining weight blocks.
__global__ void wcvt3(const float4* __restrict__ s1, int n1,
                      const float4* __restrict__ s2, int n2,
                      const float4* __restrict__ s3, int n3,
                      __half* __restrict__ d1, __half* __restrict__ d2,
                      __half* __restrict__ d3)
{
    const int gid = blockIdx.x*blockDim.x + threadIdx.x;
    const int stride = gridDim.x*blockDim.x;
    auto conv = [&](const float4* s, __half* d, int n4){
        for (int i=gid; i<n4; i+=stride){
            const float4 v = s[i];
            __half h[4] = {__float2half_rn(v.x), __float2half_rn(v.y),
                           __float2half_rn(v.z), __float2half_rn(v.w)};
            *reinterpret_cast<uint2*>(d + (size_t)i*4) =
                *reinterpret_cast<uint2*>(h);
        }
    };
    conv(s1, d1, n1); conv(s2, d2, n2); conv(s3, d3, n3);
}

// ---------------- GEMM fp16, compile-time shapes + slots ---------------------
// C[M,N] = A[M,K] @ W[N,K]^T, fp16 operands, fp32 accumulate.
// EPI_AV additionally performs the chunk-level scan reduction (phase 1) in
// smem and writes P/H.  (Compute loop identical to the R10 passing kernel.)
template<int EPI, int NN, int KK>
__global__ __launch_bounds__(256, 2)
void gemm_h(const __half* __restrict__ A, const __half* __restrict__ W,
            const float* __restrict__ bias, const float* __restrict__ add,
            void* __restrict__ Cv, float* __restrict__ Pg, float* __restrict__ Hg)
{
    extern __shared__ __align__(1024) char smem[];
    const uint32_t sb = smem_u32(smem);
    const int tid  = threadIdx.x;
    const int lane = tid & 31;
    const int warp = tid >> 5;
    const int wm   = (warp >> 2) * 64;     // warp M offset (2 warps)
    const int wn   = (warp & 3) * 32;      // warp N offset (4 warps)
    const int g    = lane >> 2;
    const int t    = lane & 3;
    const int bm = blockIdx.y * GMT;
    const int bn = blockIdx.x * GNT;

    const int rowsel = lane & 7;
    const int rowA   = rowsel + ((lane >> 3) & 1) * 8;   // mats 0,1: m; 2,3: k+8
    const int chA    = (lane >> 4) & 1;
    const int rowB   = rowsel + ((lane >> 4) & 1) * 8;   // mats 2,3 -> n+8
    const int chB    = (lane >> 3) & 1;                  // mats 1,3 -> k+8

    float acc[4][4][4];
    #pragma unroll
    for (int i=0;i<4;i++)
        #pragma unroll
        for (int j=0;j<4;j++)
            #pragma unroll
            for (int k=0;k<4;k++) acc[i][j][k] = 0.0f;

    auto load_stage = [&](int s, int slot){
        const uint32_t sA = sb + (uint32_t)(slot*STG_BYTES);
        const uint32_t sB = sA + STG_A;
        const int k0 = s * KC;
        #pragma unroll
        for (int i=0;i<4;i++){                       // A: 1024 chunks
            const int q = tid + i*256;
            const int row = q >> 3, c = q & 7;
            cp16(sA + (uint32_t)(row*8 + (c ^ (row & 7)))*16u,
                 A + (size_t)(bm+row)*KK + k0 + c*8);
        }
        #pragma unroll
        for (int i=0;i<4;i++){                       // B: 1024 chunks
            const int q = tid + i*256;
            const int row = q >> 3, c = q & 7;
            cp16(sB + (uint32_t)(row*8 + (c ^ (row & 7)))*16u,
                 W + (size_t)(bn+row)*KK + k0 + c*8);
        }
    };

    auto compute = [&](int slot){
        const uint32_t sA = sb + (uint32_t)(slot*STG_BYTES);
        const uint32_t sB = sA + STG_A;
        #pragma unroll
        for (int slab=0; slab<4; slab++){            // 4 x (K=16) per stage
            const uint32_t ab = sA +
                (uint32_t)((wm + rowA)*8 + (((slab<<1)|chA) ^ rowsel))*16u;
            const uint32_t bb = sB +
                (uint32_t)((wn + rowB)*8 + (((slab<<1)|chB) ^ rowsel))*16u;
            uint32_t Bf[4][2];
            #pragma unroll
            for (int n2=0; n2<2; n2++)
                ldsm_x4(Bf[2*n2][0], Bf[2*n2][1], Bf[2*n2+1][0], Bf[2*n2+1][1],
                        bb + n2*2048);
            #pragma unroll
            for (int ms=0; ms<4; ms++){
                uint32_t a[4];
                ldsm_x4(a[0], a[1], a[2], a[3], ab + ms*2048);
                #pragma unroll
                for (int ns=0; ns<4; ns++)
                    mma_f16(acc[ms][ns], a, Bf[ns]);
            }
        }
    };

    constexpr int nk = KK / KC;                      // 8 / 12 / 32
    load_stage(0, 0); cp_commit();
    load_stage(1, 1); cp_commit();
    #pragma unroll 1
    for (int base = 0; base < nk; base += 3){
        // step kt = base (slot 0)
        cp_wait1(); __syncthreads();
        if (base+2 < nk) load_stage(base+2, 2);
        cp_commit();
        compute(0);
        if (base+1 < nk){                            // kt = base+1 (slot 1)
            cp_wait1(); __syncthreads();
            if (base+3 < nk) load_stage(base+3, 0);
            cp_commit();
            compute(1);
        }
        if (base+2 < nk){                            // kt = base+2 (slot 2)
            cp_wait1(); __syncthreads();
            if (base+4 < nk) load_stage(base+4, 1);
            cp_commit();
            compute(2);
        }
    }
    cp_wait0();

    // ---------------- epilogue ----------------
    if constexpr (EPI == EPI_AV){
        __syncthreads();
        float* sa = reinterpret_cast<float*>(smem);
        float* sv = sa + 64*SPITCH;
        #pragma unroll
        for (int ms=0; ms<4; ms++){
            #pragma unroll
            for (int ns=0; ns<4; ns++){
                const int cp = (wn >> 1) + ns*4 + t;        // 0..63
                #pragma unroll
                for (int hh=0; hh<2; hh++){
                    const int rl = wm + ms*16 + g + 8*hh;   // 0..127
                    const float hid = acc[ms][ns][hh*2+0];
                    const float gt  = acc[ms][ns][hh*2+1];
                    const float sg = 1.0f / (1.0f + __expf(-gt));
                    const float a  = 1.0f - sg;
                    float gv;
                    if (hid >= 0.0f) gv = hid + 0.5f;
                    else { const float u = __expf(hid); gv = u / (1.0f + u); }
                    const __half2 pair = __floats2half2_rn(a, sg * gv);
                    reinterpret_cast<__half2*>(Cv)[
                        (size_t)(bm+rl)*(NN>>1) + (bn>>1) + cp] = pair;
                    const float2 fr = __half22float2(pair);
                    sa[cp*SPITCH + rl] = fr.x;
                    sv[cp*SPITCH + rl] = fr.y;
                }
            }
        }
        __syncthreads();
        if (tid < 128){
            const int chunk = tid >> 6, cp = tid & 63;
            const float* pa = sa + cp*SPITCH + chunk*64;
            const float* pv = sv + cp*SPITCH + chunk*64;
            float p = 1.0f, h = 0.0f;
            #pragma unroll 8
            for (int s=0; s<CCS; s++){
                const float a = pa[s], v = pv[s];
                h = fmaf(a, h, v);
                p *= a;
            }
            const int b = bm >> 12;
            const int c = ((bm & 4095) >> 6) + chunk;
            const int e = (bn >> 1) + cp;
            const int idx = (b*CNC + c)*CDI + e;
            Pg[idx] = p; Hg[idx] = h;
        }
    } else {
        #pragma unroll
        for (int ms=0; ms<4; ms++){
            const int rr = bm + wm + ms*16 + g;
            #pragma unroll
            for (int ns=0; ns<4; ns++){
                const int cc = bn + wn + ns*8 + 2*t;     // even
                float v[4] = {acc[ms][ns][0], acc[ms][ns][1],
                              acc[ms][ns][2], acc[ms][ns][3]};
                const int rows[2] = {rr, rr+8};
                #pragma unroll
                for (int h=0; h<2; h++){
                    const int row = rows[h];
                    if constexpr (EPI == EPI_ADD){
                        float* C = reinterpret_cast<float*>(Cv);
                        const float2 a2 = *reinterpret_cast<const float2*>(
                            add + (size_t)row*NN + cc);
                        *reinterpret_cast<float2*>(C + (size_t)row*NN + cc) =
                            make_float2(v[h*2+0] + a2.x, v[h*2+1] + a2.y);
                    } else if constexpr (EPI == EPI_BIAS_GELU){
                        float v0 = v[h*2+0] + bias[cc];
                        float v1 = v[h*2+1] + bias[cc+1];
                        v0 = 0.5f*v0*(1.0f + erff(v0 * 0.70710678118654752f));
                        v1 = 0.5f*v1*(1.0f + erff(v1 * 0.70710678118654752f));
                        __half* C = reinterpret_cast<__half*>(Cv);
                        *reinterpret_cast<__half2*>(C + (size_t)row*NN + cc) =
                            __floats2half2_rn(v0, v1);
                    } else {   // EPI_BIAS_ADD
                        float* C = reinterpret_cast<float*>(Cv);
                        const float2 a2 = *reinterpret_cast<const float2*>(
                            add + (size_t)row*NN + cc);
                        *reinterpret_cast<float2*>(C + (size_t)row*NN + cc) =
                            make_float2(v[h*2+0] + bias[cc]   + a2.x,
                                        v[h*2+1] + bias[cc+1] + a2.y);
                    }
                }
            }
        }
    }
}

// ---------------- layernorm (D=512), 2 rows/warp (MLP 8), fp16 out -----------
__global__ void ln_warp(const float* __restrict__ x, const float* __restrict__ gw,
                        const float* __restrict__ bw, __half* __restrict__ y)
{
    const int warp = threadIdx.x >> 5, lane = threadIdx.x & 31;
    const int row0 = blockIdx.x*16 + warp*2;
    float4 v[2][4];
    float s0=0.f, q0=0.f, s1=0.f, q1=0.f;
    {
        const float4* xr0 = reinterpret_cast<const float4*>(x + (size_t)row0*CDD);
        const float4* xr1 = reinterpret_cast<const float4*>(x + (size_t)(row0+1)*CDD);
        #pragma unroll
        for (int j=0;j<4;j++){
            v[0][j] = xr0[lane + j*32];
            v[1][j] = xr1[lane + j*32];
        }
        #pragma unroll
        for (int j=0;j<4;j++){
            s0 += (v[0][j].x+v[0][j].y)+(v[0][j].z+v[0][j].w);
            q0 += v[0][j].x*v[0][j].x + v[0][j].y*v[0][j].y
                + v[0][j].z*v[0][j].z + v[0][j].w*v[0][j].w;
            s1 += (v[1][j].x+v[1][j].y)+(v[1][j].z+v[1][j].w);
            q1 += v[1][j].x*v[1][j].x + v[1][j].y*v[1][j].y
                + v[1][j].z*v[1][j].z + v[1][j].w*v[1][j].w;
        }
    }
    #pragma unroll
    for (int o=16;o>0;o>>=1){
        s0 += __shfl_xor_sync(0xffffffffu,s0,o);
        q0 += __shfl_xor_sync(0xffffffffu,q0,o);
        s1 += __shfl_xor_sync(0xffffffffu,s1,o);
        q1 += __shfl_xor_sync(0xffffffffu,q1,o);
    }
    const float m0 = s0*(1.0f/CDD), r0 = rsqrtf(q0*(1.0f/CDD) - m0*m0 + 1e-5f);
    const float m1 = s1*(1.0f/CDD), r1 = rsqrtf(q1*(1.0f/CDD) - m1*m1 + 1e-5f);
    const float4* gr = reinterpret_cast<const float4*>(gw);
    const float4* br = reinterpret_cast<const float4*>(bw);
    uint2* y0 = reinterpret_cast<uint2*>(y + (size_t)row0*CDD);
    uint2* y1 = reinterpret_cast<uint2*>(y + (size_t)(row0+1)*CDD);
    #pragma unroll
    for (int j=0;j<4;j++){
        const float4 gg = gr[lane + j*32];
        const float4 bb = br[lane + j*32];
        {
            const __half2 h0 = __floats2half2_rn((v[0][j].x-m0)*r0*gg.x + bb.x,
                                                 (v[0][j].y-m0)*r0*gg.y + bb.y);
            const __half2 h1 = __floats2half2_rn((v[0][j].z-m0)*r0*gg.z + bb.z,
                                                 (v[0][j].w-m0)*r0*gg.w + bb.w);
            uint2 u;
            u.x = *reinterpret_cast<const uint32_t*>(&h0);
            u.y = *reinterpret_cast<const uint32_t*>(&h1);
            y0[lane + j*32] = u;
        }
        {
            const __half2 h0 = __floats2half2_rn((v[1][j].x-m1)*r1*gg.x + bb.x,
                                                 (v[1][j].y-m1)*r1*gg.y + bb.y);
            const __half2 h1 = __floats2half2_rn((v[1][j].z-m1)*r1*gg.z + bb.z,
                                                 (v[1][j].w-m1)*r1*gg.w + bb.w);
            uint2 u;
            u.x = *reinterpret_cast<const uint32_t*>(&h0);
            u.y = *reinterpret_cast<const uint32_t*>(&h1);
            y1[lane + j*32] = u;
        }
    }
}

// ---------------- carry kernel: chunk prefix (was phase3's inner loop) -------
__global__ void carry_k(const float* __restrict__ P, const float* __restrict__ H,
                        float* __restrict__ Cy)
{
    const int i = blockIdx.x*256 + threadIdx.x;          // 0..CBB*CDI-1
    if (i >= CBB*CDI) return;
    const int b = i / CDI, e = i % CDI;
    float T = 0.5f;                                      // h_0
    #pragma unroll 8
    for (int c=0; c<CNC; c++){
        const int idx = (b*CNC + c)*CDI + e;
        Cy[idx] = T;
        T = fmaf(P[idx], T, H[idx]);
    }
}

// ---------------- scan phase 3 (pure streaming; carry precomputed) -----------
__global__ void scan_phase3(const uint2* __restrict__ av, const float* __restrict__ Cy,
                            __half* __restrict__ hout)
{
    const int e2 = blockIdx.x*128 + threadIdx.x;
    const int c = blockIdx.y, b = blockIdx.z;
    const float2 cv = *reinterpret_cast<const float2*>(
        Cy + (b*CNC + c)*CDI + 2*e2);
    float h0 = cv.x, h1 = cv.y;
    const uint2* base = av + (size_t)(b*CSS + c*CCS)*(CDI/2) + e2;
    __half2* ob = reinterpret_cast<__half2*>(
        hout + (size_t)(b*CSS + c*CCS)*CDI + 2*e2);
    #pragma unroll 8
    for (int s=0; s<CCS; s++){
        const uint2 u = base[(size_t)s*(CDI/2)];
        const float2 f0 = __half22float2(*reinterpret_cast<const __half2*>(&u.x));
        const float2 f1 = __half22float2(*reinterpret_cast<const __half2*>(&u.y));
        h0 = fmaf(f0.x, h0, f0.y);
        h1 = fmaf(f1.x, h1, f1.y);
        ob[(size_t)s*(CDI/2)] = __floats2half2_rn(h0, h1);
    }
}

// ---------------- final LN + 2-logit head, warp-per-row ----------------------
__global__ void logits_warp(const float* __restrict__ x, const float* __restrict__ gw,
                            const float* __restrict__ bw, const float* __restrict__ Wl,
                            float* __restrict__ out)
{
    const int warp = threadIdx.x >> 5, lane = threadIdx.x & 31;
    const int row  = blockIdx.x*8 + warp;
    const float4* xr = reinterpret_cast<const float4*>(x + (size_t)row*CDD);
    float4 v[4];
    float s = 0.0f, q = 0.0f;
    #pragma unroll
    for (int j=0;j<4;j++){
        v[j] = xr[lane + j*32];
        s += (v[j].x+v[j].y)+(v[j].z+v[j].w);
        q += v[j].x*v[j].x + v[j].y*v[j].y + v[j].z*v[j].z + v[j].w*v[j].w;
    }
    #pragma unroll
    for (int o=16;o>0;o>>=1){ s += __shfl_xor_sync(0xffffffffu,s,o);
                              q += __shfl_xor_sync(0xffffffffu,q,o); }
    const float mean = s * (1.0f/CDD);
    const float rstd = rsqrtf(q*(1.0f/CDD) - mean*mean + 1e-5f);

    const float4* gr = reinterpret_cast<const float4*>(gw);
    const float4* br = reinterpret_cast<const float4*>(bw);
    const float4* w0 = reinterpret_cast<const float4*>(Wl);
    const float4* w1 = reinterpret_cast<const float4*>(Wl + CDD);
    float a0 = 0.0f, a1 = 0.0f;
    #pragma unroll
    for (int j=0;j<4;j++){
        const int idx = lane + j*32;
        const float4 gg = gr[idx], bb = br[idx];
        const float4 wa = w0[idx], wb = w1[idx];
        const float n0 = (v[j].x-mean)*rstd*gg.x + bb.x;
        const float n1 = (v[j].y-mean)*rstd*gg.y + bb.y;
        const float n2 = (v[j].z-mean)*rstd*gg.z + bb.z;
        const float n3 = (v[j].w-mean)*rstd*gg.w + bb.w;
        a0 += n0*wa.x + n1*wa.y + n2*wa.z + n3*wa.w;
        a1 += n0*wb.x + n1*wb.y + n2*wb.z + n3*wb.w;
    }
    #pragma unroll
    for (int o=16;o>0;o>>=1){ a0 += __shfl_xor_sync(0xffffffffu,a0,o);
                              a1 += __shfl_xor_sync(0xffffffffu,a1,o); }
    if (lane == 0){
        out[(size_t)row*2 + 0] = a0;
        out[(size_t)row*2 + 1] = a1;
    }
}

// ---------------- driver ----------------------------------------------------
extern "C" void kernel_launch(void* const* d_in, const int* in_sizes, int n_in,
                              void* d_out, int out_size)
{
    const float* input  = (const float*)d_in[0];
    const float* Whg    = (const float*)d_in[1];
    const float* Wout   = (const float*)d_in[2];
    const float* ln1_g  = (const float*)d_in[3];
    const float* ln1_b  = (const float*)d_in[4];
    const float* ln2_g  = (const float*)d_in[5];
    const float* ln2_b  = (const float*)d_in[6];
    const float* ffW1   = (const float*)d_in[7];
    const float* ffb1   = (const float*)d_in[8];
    const float* ffW2   = (const float*)d_in[9];
    const float* ffb2   = (const float*)d_in[10];
    const float* norm_g = (const float*)d_in[11];
    const float* norm_b = (const float*)d_in[12];
    const float* Wlog   = (const float*)d_in[13];
    float* out = (float*)d_out;

    __half *xn, *h, *ffh, *wh; __half2 *av; float *y, *x, *P, *Hc, *Cy;
    cudaGetSymbolAddress((void**)&xn,  g_xn);
    cudaGetSymbolAddress((void**)&av,  g_av);
    cudaGetSymbolAddress((void**)&h,   g_h);
    cudaGetSymbolAddress((void**)&y,   g_y);
    cudaGetSymbolAddress((void**)&x,   g_x);
    cudaGetSymbolAddress((void**)&ffh, g_ffh);
    cudaGetSymbolAddress((void**)&P,   g_P);
    cudaGetSymbolAddress((void**)&Hc,  g_Hc);
    cudaGetSymbolAddress((void**)&Cy,  g_Cy);
    cudaGetSymbolAddress((void**)&wh,  g_wh);

    __half* w_hg  = wh;
    __half* w_out = w_hg  + W_HG_SZ;
    __half* w_f1  = w_out + W_OUT_SZ;
    __half* w_f2  = w_f1  + W_F1_SZ;

    cudaFuncSetAttribute(gemm_h<EPI_AV, 2*CDI, CDD>,
        cudaFuncAttributeMaxDynamicSharedMemorySize, SMEM_DYN);
    cudaFuncSetAttribute(gemm_h<EPI_ADD, CDD, CDI>,
        cudaFuncAttributeMaxDynamicSharedMemorySize, SMEM_DYN);
    cudaFuncSetAttribute(gemm_h<EPI_BIAS_GELU, CFF, CDD>,
        cudaFuncAttributeMaxDynamicSharedMemorySize, SMEM_DYN);
    cudaFuncSetAttribute(gemm_h<EPI_BIAS_ADD, CDD, CFF>,
        cudaFuncAttributeMaxDynamicSharedMemorySize, SMEM_DYN);

    // weight prepass (2 launches)
    wperm_hg<<<(int)(W_HG_SZ/8 + 255)/256, 256>>>(Whg, w_hg);
    wcvt3<<<4096, 256>>>((const float4*)Wout, (int)(W_OUT_SZ/4),
                         (const float4*)ffW1, (int)(W_F1_SZ/4),
                         (const float4*)ffW2, (int)(W_F2_SZ/4),
                         w_out, w_f1, w_f2);

    const int M = CMM;
    const dim3 scan_grid(3, CNC, CBB);   // 384 uint2 lanes / 128 thr = 3

    for (int i=0; i<CLL; i++){
        const float* cur = (i==0) ? input : x;

        ln_warp<<<M/16, 256>>>(cur, ln1_g + i*CDD, ln1_b + i*CDD, xn);
        // hg GEMM: fused gates + chunk-scan (phase 1) -> av, P, Hc
        gemm_h<EPI_AV, 2*CDI, CDD><<<dim3(2*CDI/GNT, M/GMT), 256, SMEM_DYN>>>(
            xn, w_hg + (size_t)i*2*CDI*CDD, nullptr, nullptr, av, P, Hc);
        carry_k<<<(CBB*CDI + 255)/256, 256>>>(P, Hc, Cy);
        scan_phase3<<<scan_grid, 128>>>((const uint2*)av, Cy, h);
        gemm_h<EPI_ADD, CDD, CDI><<<dim3(CDD/GNT, M/GMT), 256, SMEM_DYN>>>(
            h, w_out + (size_t)i*CDD*CDI, nullptr, cur, y, nullptr, nullptr);
        ln_warp<<<M/16, 256>>>(y, ln2_g + i*CDD, ln2_b + i*CDD, xn);
        gemm_h<EPI_BIAS_GELU, CFF, CDD><<<dim3(CFF/GNT, M/GMT), 256, SMEM_DYN>>>(
            xn, w_f1 + (size_t)i*CFF*CDD, ffb1 + i*CFF, nullptr, ffh, nullptr, nullptr);
        gemm_h<EPI_BIAS_ADD, CDD, CFF><<<dim3(CDD/GNT, M/GMT), 256, SMEM_DYN>>>(
            ffh, w_f2 + (size_t)i*CDD*CFF, ffb2 + i*CDD, y, x, nullptr, nullptr);
    }

    logits_warp<<<M/8, 256>>>(x, norm_g, norm_b, Wlog, out);
}

// round 16
// speedup vs baseline: 3.7731x; 1.0001x over previous
#include <cuda_runtime.h>
#include <cuda_fp16.h>
#include <cstdint>
#include <cstddef>

// Problem constants
#define CBB 8
#define CSS 4096
#define CDD 512
#define CLL 4
#define CDI 768
#define CFF 2048
#define CMM (CBB*CSS)          // 32768 rows
#define CNC 64                 // scan chunks
#define CCS (CSS/CNC)          // 64 per chunk

// weight scratch sizes (elements)
#define W_HG_SZ  ((size_t)CLL*2*CDI*CDD)
#define W_OUT_SZ ((size_t)CLL*CDD*CDI)
#define W_F1_SZ  ((size_t)CLL*CFF*CDD)
#define W_F2_SZ  ((size_t)CLL*CDD*CFF)

// GEMM tiling: CTA 128(M) x 128(N), 8 warps (2m x 4n), warp tile 64x32.
// fp16 m16n8k16. K staged 64 halves (128B rows, 8x16B chunks, swizzle c^(row&7)).
// 96KB smem + 128 regs => 2 CTAs per SM.
#define GMT 128
#define GNT 128
#define KC  64                           // halves per stage
#define NST 3
#define STG_A 16384
#define STG_B 16384
#define STG_BYTES (STG_A + STG_B)        // 32768
#define SMEM_DYN (NST*STG_BYTES)         // 98304
#define SPITCH 133                       // fused-scan smem pitch (bank spread)

// ---------------- scratch (device globals; no allocation allowed) ----------
static __device__ __align__(256) __half   g_xn [(size_t)CMM*CDD];   // LN out (fp16)
static __device__ __align__(256) __half2  g_av [(size_t)CMM*CDI];   // (a, v) pairs
static __device__ __align__(256) __half   g_h  [(size_t)CMM*CDI];   // scan out (fp16)
static __device__ __align__(256) float    g_y  [(size_t)CMM*CDD];   // residual (fp32)
static __device__ __align__(256) float    g_x  [(size_t)CMM*CDD];   // layer out (fp32)
static __device__ __align__(256) __half   g_ffh[(size_t)CMM*CFF];   // ff hidden (fp16)
static __device__ __align__(256) __half   g_wh [W_HG_SZ + W_OUT_SZ + W_F1_SZ + W_F2_SZ];
static __device__ __align__(256) float    g_P  [CBB*CNC*CDI];
static __device__ __align__(256) float    g_Hc [CBB*CNC*CDI];
static __device__ __align__(256) float    g_Cy [CBB*CNC*CDI];       // chunk carries

// ---------------- helpers ----------------------------------------------------
__device__ __forceinline__ uint32_t smem_u32(const void* p){
    uint32_t a;
    asm("{ .reg .u64 t; cvta.to.shared.u64 t, %1; cvt.u32.u64 %0, t; }"
        : "=r"(a) : "l"(p));
    return a;
}
__device__ __forceinline__ void cp16(uint32_t saddr, const void* g){
    asm volatile("cp.async.cg.shared.global [%0], [%1], 16;"
                 :: "r"(saddr), "l"(g) : "memory");
}
__device__ __forceinline__ void cp_commit(){
    asm volatile("cp.async.commit_group;" ::: "memory");
}
__device__ __forceinline__ void cp_wait1(){
    asm volatile("cp.async.wait_group 1;" ::: "memory");
}
__device__ __forceinline__ void cp_wait0(){
    asm volatile("cp.async.wait_group 0;" ::: "memory");
}
__device__ __forceinline__ void ldsm_x4(uint32_t& r0, uint32_t& r1, uint32_t& r2,
                                        uint32_t& r3, uint32_t addr){
    asm volatile("ldmatrix.sync.aligned.m8n8.x4.shared.b16 {%0,%1,%2,%3}, [%4];"
                 : "=r"(r0), "=r"(r1), "=r"(r2), "=r"(r3) : "r"(addr));
}
__device__ __forceinline__ void mma_f16(float (&d)[4], const uint32_t (&a)[4],
                                        const uint32_t (&b)[2]){
    asm volatile(
        "mma.sync.aligned.m16n8k16.row.col.f32.f16.f16.f32 "
        "{%0,%1,%2,%3}, {%4,%5,%6,%7}, {%8,%9}, {%0,%1,%2,%3};\n"
        : "+f"(d[0]), "+f"(d[1]), "+f"(d[2]), "+f"(d[3])
        : "r"(a[0]), "r"(a[1]), "r"(a[2]), "r"(a[3]), "r"(b[0]), "r"(b[1]));
}

enum { EPI_AV=0, EPI_ADD=1, EPI_BIAS_GELU=2, EPI_BIAS_ADD=3 };

// ---------------- weight prepass ---------------------------------------------
// Permute+convert Whg: dst row 2e = hidden_e (src e), 2e+1 = gate_e (src 768+e).
__global__ void wperm_hg(const float* __restrict__ src, __half* __restrict__ dst)
{
    const int id = blockIdx.x*blockDim.x + threadIdx.x;   // 8 halves each
    const int perlayer = 2*CDI*CDD/8;                     // 98304
    if (id >= CLL*perlayer) return;
    const int l = id / perlayer, rem = id % perlayer;
    const int r = rem / (CDD/8), c8 = rem % (CDD/8);
    const int sr = (r & 1) ? (CDI + (r >> 1)) : (r >> 1);
    const float* s = src + ((size_t)l*2*CDI + sr)*CDD + c8*8;
    __half h[8];
    #pragma unroll
    for (int j=0;j<8;j++) h[j] = __float2half_rn(s[j]);
    *reinterpret_cast<uint4*>(dst + ((size_t)l*2*CDI + r)*CDD + c8*8) =
        *reinterpret_cast<uint4*>(h);
}

// One kernel converts all three remaining weight blocks.
__global__ void wcvt3(const float4* __restrict__ s1, int n1,
                      const float4* __restrict__ s2, int n2,
                      const float4* __restrict__ s3, int n3,
                      __half* __restrict__ d1, __half* __restrict__ d2,
                      __half* __restrict__ d3)
{
    const int gid = blockIdx.x*blockDim.x + threadIdx.x;
    const int stride = gridDim.x*blockDim.x;
    auto conv = [&](const float4* s, __half* d, int n4){
        for (int i=gid; i<n4; i+=stride){
            const float4 v = s[i];
            __half h[4] = {__float2half_rn(v.x), __float2half_rn(v.y),
                           __float2half_rn(v.z), __float2half_rn(v.w)};
            *reinterpret_cast<uint2*>(d + (size_t)i*4) =
                *reinterpret_cast<uint2*>(h);
        }
    };
    conv(s1, d1, n1); conv(s2, d2, n2); conv(s3, d3, n3);
}

// ---------------- GEMM fp16, compile-time shapes + slots ---------------------
// C[M,N] = A[M,K] @ W[N,K]^T, fp16 operands, fp32 accumulate.
// EPI_AV additionally performs the chunk-level scan reduction (phase 1) in
// smem and writes P/H.  (Identical to the R13 passing kernel.)
template<int EPI, int NN, int KK>
__global__ __launch_bounds__(256, 2)
void gemm_h(const __half* __restrict__ A, const __half* __restrict__ W,
            const float* __restrict__ bias, const float* __restrict__ add,
            void* __restrict__ Cv, float* __restrict__ Pg, float* __restrict__ Hg)
{
    extern __shared__ __align__(1024) char smem[];
    const uint32_t sb = smem_u32(smem);
    const int tid  = threadIdx.x;
    const int lane = tid & 31;
    const int warp = tid >> 5;
    const int wm   = (warp >> 2) * 64;     // warp M offset (2 warps)
    const int wn   = (warp & 3) * 32;      // warp N offset (4 warps)
    const int g    = lane >> 2;
    const int t    = lane & 3;
    const int bm = blockIdx.y * GMT;
    const int bn = blockIdx.x * GNT;

    const int rowsel = lane & 7;
    const int rowA   = rowsel + ((lane >> 3) & 1) * 8;   // mats 0,1: m; 2,3: k+8
    const int chA    = (lane >> 4) & 1;
    const int rowB   = rowsel + ((lane >> 4) & 1) * 8;   // mats 2,3 -> n+8
    const int chB    = (lane >> 3) & 1;                  // mats 1,3 -> k+8

    float acc[4][4][4];
    #pragma unroll
    for (int i=0;i<4;i++)
        #pragma unroll
        for (int j=0;j<4;j++)
            #pragma unroll
            for (int k=0;k<4;k++) acc[i][j][k] = 0.0f;

    auto load_stage = [&](int s, int slot){
        const uint32_t sA = sb + (uint32_t)(slot*STG_BYTES);
        const uint32_t sB = sA + STG_A;
        const int k0 = s * KC;
        #pragma unroll
        for (int i=0;i<4;i++){                       // A: 1024 chunks
            const int q = tid + i*256;
            const int row = q >> 3, c = q & 7;
            cp16(sA + (uint32_t)(row*8 + (c ^ (row & 7)))*16u,
                 A + (size_t)(bm+row)*KK + k0 + c*8);
        }
        #pragma unroll
        for (int i=0;i<4;i++){                       // B: 1024 chunks
            const int q = tid + i*256;
            const int row = q >> 3, c = q & 7;
            cp16(sB + (uint32_t)(row*8 + (c ^ (row & 7)))*16u,
                 W + (size_t)(bn+row)*KK + k0 + c*8);
        }
    };

    auto compute = [&](int slot){
        const uint32_t sA = sb + (uint32_t)(slot*STG_BYTES);
        const uint32_t sB = sA + STG_A;
        #pragma unroll
        for (int slab=0; slab<4; slab++){            // 4 x (K=16) per stage
            const uint32_t ab = sA +
                (uint32_t)((wm + rowA)*8 + (((slab<<1)|chA) ^ rowsel))*16u;
            const uint32_t bb = sB +
                (uint32_t)((wn + rowB)*8 + (((slab<<1)|chB) ^ rowsel))*16u;
            uint32_t Bf[4][2];
            #pragma unroll
            for (int n2=0; n2<2; n2++)
                ldsm_x4(Bf[2*n2][0], Bf[2*n2][1], Bf[2*n2+1][0], Bf[2*n2+1][1],
                        bb + n2*2048);
            #pragma unroll
            for (int ms=0; ms<4; ms++){
                uint32_t a[4];
                ldsm_x4(a[0], a[1], a[2], a[3], ab + ms*2048);
                #pragma unroll
                for (int ns=0; ns<4; ns++)
                    mma_f16(acc[ms][ns], a, Bf[ns]);
            }
        }
    };

    constexpr int nk = KK / KC;                      // 8 / 12 / 32
    load_stage(0, 0); cp_commit();
    load_stage(1, 1); cp_commit();
    #pragma unroll 1
    for (int base = 0; base < nk; base += 3){
        // step kt = base (slot 0)
        cp_wait1(); __syncthreads();
        if (base+2 < nk) load_stage(base+2, 2);
        cp_commit();
        compute(0);
        if (base+1 < nk){                            // kt = base+1 (slot 1)
            cp_wait1(); __syncthreads();
            if (base+3 < nk) load_stage(base+3, 0);
            cp_commit();
            compute(1);
        }
        if (base+2 < nk){                            // kt = base+2 (slot 2)
            cp_wait1(); __syncthreads();
            if (base+4 < nk) load_stage(base+4, 1);
            cp_commit();
            compute(2);
        }
    }
    cp_wait0();

    // ---------------- epilogue ----------------
    if constexpr (EPI == EPI_AV){
        __syncthreads();
        float* sa = reinterpret_cast<float*>(smem);
        float* sv = sa + 64*SPITCH;
        #pragma unroll
        for (int ms=0; ms<4; ms++){
            #pragma unroll
            for (int ns=0; ns<4; ns++){
                const int cp = (wn >> 1) + ns*4 + t;        // 0..63
                #pragma unroll
                for (int hh=0; hh<2; hh++){
                    const int rl = wm + ms*16 + g + 8*hh;   // 0..127
                    const float hid = acc[ms][ns][hh*2+0];
                    const float gt  = acc[ms][ns][hh*2+1];
                    const float sg = 1.0f / (1.0f + __expf(-gt));
                    const float a  = 1.0f - sg;
                    float gv;
                    if (hid >= 0.0f) gv = hid + 0.5f;
                    else { const float u = __expf(hid); gv = u / (1.0f + u); }
                    const __half2 pair = __floats2half2_rn(a, sg * gv);
                    reinterpret_cast<__half2*>(Cv)[
                        (size_t)(bm+rl)*(NN>>1) + (bn>>1) + cp] = pair;
                    const float2 fr = __half22float2(pair);
                    sa[cp*SPITCH + rl] = fr.x;
                    sv[cp*SPITCH + rl] = fr.y;
                }
            }
        }
        __syncthreads();
        if (tid < 128){
            const int chunk = tid >> 6, cp = tid & 63;
            const float* pa = sa + cp*SPITCH + chunk*64;
            const float* pv = sv + cp*SPITCH + chunk*64;
            float p = 1.0f, h = 0.0f;
            #pragma unroll 8
            for (int s=0; s<CCS; s++){
                const float a = pa[s], v = pv[s];
                h = fmaf(a, h, v);
                p *= a;
            }
            const int b = bm >> 12;
            const int c = ((bm & 4095) >> 6) + chunk;
            const int e = (bn >> 1) + cp;
            const int idx = (b*CNC + c)*CDI + e;
            Pg[idx] = p; Hg[idx] = h;
        }
    } else {
        #pragma unroll
        for (int ms=0; ms<4; ms++){
            const int rr = bm + wm + ms*16 + g;
            #pragma unroll
            for (int ns=0; ns<4; ns++){
                const int cc = bn + wn + ns*8 + 2*t;     // even
                float v[4] = {acc[ms][ns][0], acc[ms][ns][1],
                              acc[ms][ns][2], acc[ms][ns][3]};
                const int rows[2] = {rr, rr+8};
                #pragma unroll
                for (int h=0; h<2; h++){
                    const int row = rows[h];
                    if constexpr (EPI == EPI_ADD){
                        float* C = reinterpret_cast<float*>(Cv);
                        const float2 a2 = *reinterpret_cast<const float2*>(
                            add + (size_t)row*NN + cc);
                        *reinterpret_cast<float2*>(C + (size_t)row*NN + cc) =
                            make_float2(v[h*2+0] + a2.x, v[h*2+1] + a2.y);
                    } else if constexpr (EPI == EPI_BIAS_GELU){
                        float v0 = v[h*2+0] + bias[cc];
                        float v1 = v[h*2+1] + bias[cc+1];
                        v0 = 0.5f*v0*(1.0f + erff(v0 * 0.70710678118654752f));
                        v1 = 0.5f*v1*(1.0f + erff(v1 * 0.70710678118654752f));
                        __half* C = reinterpret_cast<__half*>(Cv);
                        *reinterpret_cast<__half2*>(C + (size_t)row*NN + cc) =
                            __floats2half2_rn(v0, v1);
                    } else {   // EPI_BIAS_ADD
                        float* C = reinterpret_cast<float*>(Cv);
                        const float2 a2 = *reinterpret_cast<const float2*>(
                            add + (size_t)row*NN + cc);
                        *reinterpret_cast<float2*>(C + (size_t)row*NN + cc) =
                            make_float2(v[h*2+0] + bias[cc]   + a2.x,
                                        v[h*2+1] + bias[cc+1] + a2.y);
                    }
                }
            }
        }
    }
}

// ---------------- layernorm (D=512), 2 rows/warp (MLP 8), fp16 out -----------
__global__ void ln_warp(const float* __restrict__ x, const float* __restrict__ gw,
                        const float* __restrict__ bw, __half* __restrict__ y)
{
    const int warp = threadIdx.x >> 5, lane = threadIdx.x & 31;
    const int row0 = blockIdx.x*16 + warp*2;
    float4 v[2][4];
    float s0=0.f, q0=0.f, s1=0.f, q1=0.f;
    {
        const float4* xr0 = reinterpret_cast<const float4*>(x + (size_t)row0*CDD);
        const float4* xr1 = reinterpret_cast<const float4*>(x + (size_t)(row0+1)*CDD);
        #pragma unroll
        for (int j=0;j<4;j++){
            v[0][j] = xr0[lane + j*32];
            v[1][j] = xr1[lane + j*32];
        }
        #pragma unroll
        for (int j=0;j<4;j++){
            s0 += (v[0][j].x+v[0][j].y)+(v[0][j].z+v[0][j].w);
            q0 += v[0][j].x*v[0][j].x + v[0][j].y*v[0][j].y
                + v[0][j].z*v[0][j].z + v[0][j].w*v[0][j].w;
            s1 += (v[1][j].x+v[1][j].y)+(v[1][j].z+v[1][j].w);
            q1 += v[1][j].x*v[1][j].x + v[1][j].y*v[1][j].y
                + v[1][j].z*v[1][j].z + v[1][j].w*v[1][j].w;
        }
    }
    #pragma unroll
    for (int o=16;o>0;o>>=1){
        s0 += __shfl_xor_sync(0xffffffffu,s0,o);
        q0 += __shfl_xor_sync(0xffffffffu,q0,o);
        s1 += __shfl_xor_sync(0xffffffffu,s1,o);
        q1 += __shfl_xor_sync(0xffffffffu,q1,o);
    }
    const float m0 = s0*(1.0f/CDD), r0 = rsqrtf(q0*(1.0f/CDD) - m0*m0 + 1e-5f);
    const float m1 = s1*(1.0f/CDD), r1 = rsqrtf(q1*(1.0f/CDD) - m1*m1 + 1e-5f);
    const float4* gr = reinterpret_cast<const float4*>(gw);
    const float4* br = reinterpret_cast<const float4*>(bw);
    uint2* y0 = reinterpret_cast<uint2*>(y + (size_t)row0*CDD);
    uint2* y1 = reinterpret_cast<uint2*>(y + (size_t)(row0+1)*CDD);
    #pragma unroll
    for (int j=0;j<4;j++){
        const float4 gg = gr[lane + j*32];
        const float4 bb = br[lane + j*32];
        {
            const __half2 h0 = __floats2half2_rn((v[0][j].x-m0)*r0*gg.x + bb.x,
                                                 (v[0][j].y-m0)*r0*gg.y + bb.y);
            const __half2 h1 = __floats2half2_rn((v[0][j].z-m0)*r0*gg.z + bb.z,
                                                 (v[0][j].w-m0)*r0*gg.w + bb.w);
            uint2 u;
            u.x = *reinterpret_cast<const uint32_t*>(&h0);
            u.y = *reinterpret_cast<const uint32_t*>(&h1);
            y0[lane + j*32] = u;
        }
        {
            const __half2 h0 = __floats2half2_rn((v[1][j].x-m1)*r1*gg.x + bb.x,
                                                 (v[1][j].y-m1)*r1*gg.y + bb.y);
            const __half2 h1 = __floats2half2_rn((v[1][j].z-m1)*r1*gg.z + bb.z,
                                                 (v[1][j].w-m1)*r1*gg.w + bb.w);
            uint2 u;
            u.x = *reinterpret_cast<const uint32_t*>(&h0);
            u.y = *reinterpret_cast<const uint32_t*>(&h1);
            y1[lane + j*32] = u;
        }
    }
}

// ---------------- carry kernel: chunk prefix ---------------------------------
__global__ void carry_k(const float* __restrict__ P, const float* __restrict__ H,
                        float* __restrict__ Cy)
{
    const int i = blockIdx.x*256 + threadIdx.x;          // 0..CBB*CDI-1
    if (i >= CBB*CDI) return;
    const int b = i / CDI, e = i % CDI;
    float T = 0.5f;                                      // h_0
    #pragma unroll 8
    for (int c=0; c<CNC; c++){
        const int idx = (b*CNC + c)*CDI + e;
        Cy[idx] = T;
        T = fmaf(P[idx], T, H[idx]);
    }
}

// ---------------- scan phase 3 (pure streaming; carry precomputed) -----------
__global__ void scan_phase3(const uint2* __restrict__ av, const float* __restrict__ Cy,
                            __half* __restrict__ hout)
{
    const int e2 = blockIdx.x*128 + threadIdx.x;
    const int c = blockIdx.y, b = blockIdx.z;
    const float2 cv = *reinterpret_cast<const float2*>(
        Cy + (b*CNC + c)*CDI + 2*e2);
    float h0 = cv.x, h1 = cv.y;
    const uint2* base = av + (size_t)(b*CSS + c*CCS)*(CDI/2) + e2;
    __half2* ob = reinterpret_cast<__half2*>(
        hout + (size_t)(b*CSS + c*CCS)*CDI + 2*e2);
    #pragma unroll 8
    for (int s=0; s<CCS; s++){
        const uint2 u = base[(size_t)s*(CDI/2)];
        const float2 f0 = __half22float2(*reinterpret_cast<const __half2*>(&u.x));
        const float2 f1 = __half22float2(*reinterpret_cast<const __half2*>(&u.y));
        h0 = fmaf(f0.x, h0, f0.y);
        h1 = fmaf(f1.x, h1, f1.y);
        ob[(size_t)s*(CDI/2)] = __floats2half2_rn(h0, h1);
    }
}

// ---------------- final LN + 2-logit head, 2 rows/warp -----------------------
__global__ void logits_warp(const float* __restrict__ x, const float* __restrict__ gw,
                            const float* __restrict__ bw, const float* __restrict__ Wl,
                            float* __restrict__ out)
{
    const int warp = threadIdx.x >> 5, lane = threadIdx.x & 31;
    const int row0 = blockIdx.x*16 + warp*2;
    float4 v[2][4];
    float s0=0.f, q0=0.f, s1=0.f, q1=0.f;
    {
        const float4* xr0 = reinterpret_cast<const float4*>(x + (size_t)row0*CDD);
        const float4* xr1 = reinterpret_cast<const float4*>(x + (size_t)(row0+1)*CDD);
        #pragma unroll
        for (int j=0;j<4;j++){
            v[0][j] = xr0[lane + j*32];
            v[1][j] = xr1[lane + j*32];
        }
        #pragma unroll
        for (int j=0;j<4;j++){
            s0 += (v[0][j].x+v[0][j].y)+(v[0][j].z+v[0][j].w);
            q0 += v[0][j].x*v[0][j].x + v[0][j].y*v[0][j].y
                + v[0][j].z*v[0][j].z + v[0][j].w*v[0][j].w;
            s1 += (v[1][j].x+v[1][j].y)+(v[1][j].z+v[1][j].w);
            q1 += v[1][j].x*v[1][j].x + v[1][j].y*v[1][j].y
                + v[1][j].z*v[1][j].z + v[1][j].w*v[1][j].w;
        }
    }
    #pragma unroll
    for (int o=16;o>0;o>>=1){
        s0 += __shfl_xor_sync(0xffffffffu,s0,o);
        q0 += __shfl_xor_sync(0xffffffffu,q0,o);
        s1 += __shfl_xor_sync(0xffffffffu,s1,o);
        q1 += __shfl_xor_sync(0xffffffffu,q1,o);
    }
    const float m0 = s0*(1.0f/CDD), r0 = rsqrtf(q0*(1.0f/CDD) - m0*m0 + 1e-5f);
    const float m1 = s1*(1.0f/CDD), r1 = rsqrtf(q1*(1.0f/CDD) - m1*m1 + 1e-5f);

    const float4* gr = reinterpret_cast<const float4*>(gw);
    const float4* br = reinterpret_cast<const float4*>(bw);
    const float4* w0 = reinterpret_cast<const float4*>(Wl);
    const float4* w1 = reinterpret_cast<const float4*>(Wl + CDD);
    float a0 = 0.f, a1 = 0.f, b0 = 0.f, b1 = 0.f;
    #pragma unroll
    for (int j=0;j<4;j++){
        const int idx = lane + j*32;
        const float4 gg = gr[idx], bb = br[idx];
        const float4 wa = w0[idx], wb = w1[idx];
        {
            const float n0 = (v[0][j].x-m0)*r0*gg.x + bb.x;
            const float n1 = (v[0][j].y-m0)*r0*gg.y + bb.y;
            const float n2 = (v[0][j].z-m0)*r0*gg.z + bb.z;
            const float n3 = (v[0][j].w-m0)*r0*gg.w + bb.w;
            a0 += n0*wa.x + n1*wa.y + n2*wa.z + n3*wa.w;
            a1 += n0*wb.x + n1*wb.y + n2*wb.z + n3*wb.w;
        }
        {
            const float n0 = (v[1][j].x-m1)*r1*gg.x + bb.x;
            const float n1 = (v[1][j].y-m1)*r1*gg.y + bb.y;
            const float n2 = (v[1][j].z-m1)*r1*gg.z + bb.z;
            const float n3 = (v[1][j].w-m1)*r1*gg.w + bb.w;
            b0 += n0*wa.x + n1*wa.y + n2*wa.z + n3*wa.w;
            b1 += n0*wb.x + n1*wb.y + n2*wb.z + n3*wb.w;
        }
    }
    #pragma unroll
    for (int o=16;o>0;o>>=1){
        a0 += __shfl_xor_sync(0xffffffffu,a0,o);
        a1 += __shfl_xor_sync(0xffffffffu,a1,o);
        b0 += __shfl_xor_sync(0xffffffffu,b0,o);
        b1 += __shfl_xor_sync(0xffffffffu,b1,o);
    }
    if (lane == 0){
        out[(size_t)row0*2 + 0] = a0;
        out[(size_t)row0*2 + 1] = a1;
        out[(size_t)(row0+1)*2 + 0] = b0;
        out[(size_t)(row0+1)*2 + 1] = b1;
    }
}

// ---------------- driver ----------------------------------------------------
extern "C" void kernel_launch(void* const* d_in, const int* in_sizes, int n_in,
                              void* d_out, int out_size)
{
    const float* input  = (const float*)d_in[0];
    const float* Whg    = (const float*)d_in[1];
    const float* Wout   = (const float*)d_in[2];
    const float* ln1_g  = (const float*)d_in[3];
    const float* ln1_b  = (const float*)d_in[4];
    const float* ln2_g  = (const float*)d_in[5];
    const float* ln2_b  = (const float*)d_in[6];
    const float* ffW1   = (const float*)d_in[7];
    const float* ffb1   = (const float*)d_in[8];
    const float* ffW2   = (const float*)d_in[9];
    const float* ffb2   = (const float*)d_in[10];
    const float* norm_g = (const float*)d_in[11];
    const float* norm_b = (const float*)d_in[12];
    const float* Wlog   = (const float*)d_in[13];
    float* out = (float*)d_out;

    __half *xn, *h, *ffh, *wh; __half2 *av; float *y, *x, *P, *Hc, *Cy;
    cudaGetSymbolAddress((void**)&xn,  g_xn);
    cudaGetSymbolAddress((void**)&av,  g_av);
    cudaGetSymbolAddress((void**)&h,   g_h);
    cudaGetSymbolAddress((void**)&y,   g_y);
    cudaGetSymbolAddress((void**)&x,   g_x);
    cudaGetSymbolAddress((void**)&ffh, g_ffh);
    cudaGetSymbolAddress((void**)&P,   g_P);
    cudaGetSymbolAddress((void**)&Hc,  g_Hc);
    cudaGetSymbolAddress((void**)&Cy,  g_Cy);
    cudaGetSymbolAddress((void**)&wh,  g_wh);

    __half* w_hg  = wh;
    __half* w_out = w_hg  + W_HG_SZ;
    __half* w_f1  = w_out + W_OUT_SZ;
    __half* w_f2  = w_f1  + W_F1_SZ;

    cudaFuncSetAttribute(gemm_h<EPI_AV, 2*CDI, CDD>,
        cudaFuncAttributeMaxDynamicSharedMemorySize, SMEM_DYN);
    cudaFuncSetAttribute(gemm_h<EPI_ADD, CDD, CDI>,
        cudaFuncAttributeMaxDynamicSharedMemorySize, SMEM_DYN);
    cudaFuncSetAttribute(gemm_h<EPI_BIAS_GELU, CFF, CDD>,
        cudaFuncAttributeMaxDynamicSharedMemorySize, SMEM_DYN);
    cudaFuncSetAttribute(gemm_h<EPI_BIAS_ADD, CDD, CFF>,
        cudaFuncAttributeMaxDynamicSharedMemorySize, SMEM_DYN);

    // weight prepass (2 launches)
    wperm_hg<<<(int)(W_HG_SZ/8 + 255)/256, 256>>>(Whg, w_hg);
    wcvt3<<<4096, 256>>>((const float4*)Wout, (int)(W_OUT_SZ/4),
                         (const float4*)ffW1, (int)(W_F1_SZ/4),
                         (const float4*)ffW2, (int)(W_F2_SZ/4),
                         w_out, w_f1, w_f2);

    const int M = CMM;
    const dim3 scan_grid(3, CNC, CBB);   // 384 uint2 lanes / 128 thr = 3

    for (int i=0; i<CLL; i++){
        const float* cur = (i==0) ? input : x;

        ln_warp<<<M/16, 256>>>(cur, ln1_g + i*CDD, ln1_b + i*CDD, xn);
        // hg GEMM: fused gates + chunk-scan (phase 1) -> av, P, Hc
        gemm_h<EPI_AV, 2*CDI, CDD><<<dim3(2*CDI/GNT, M/GMT), 256, SMEM_DYN>>>(
            xn, w_hg + (size_t)i*2*CDI*CDD, nullptr, nullptr, av, P, Hc);
        carry_k<<<24, 256>>>(P, Hc, Cy);
        scan_phase3<<<scan_grid, 128>>>((const uint2*)av, Cy, h);
        gemm_h<EPI_ADD, CDD, CDI><<<dim3(CDD/GNT, M/GMT), 256, SMEM_DYN>>>(
            h, w_out + (size_t)i*CDD*CDI, nullptr, cur, y, nullptr, nullptr);
        ln_warp<<<M/16, 256>>>(y, ln2_g + i*CDD, ln2_b + i*CDD, xn);
        gemm_h<EPI_BIAS_GELU, CFF, CDD><<<dim3(CFF/GNT, M/GMT), 256, SMEM_DYN>>>(
            xn, w_f1 + (size_t)i*CFF*CDD, ffb1 + i*CFF, nullptr, ffh, nullptr, nullptr);
        gemm_h<EPI_BIAS_ADD, CDD, CFF><<<dim3(CDD/GNT, M/GMT), 256, SMEM_DYN>>>(
            ffh, w_f2 + (size_t)i*CDD*CFF, ffb2 + i*CDD, y, x, nullptr, nullptr);
    }

    logits_warp<<<M/16, 256>>>(x, norm_g, norm_b, Wlog, out);
}

// round 17
// speedup vs baseline: 3.8344x; 1.0163x over previous
#include <cuda_runtime.h>
#include <cuda_fp16.h>
#include <cstdint>
#include <cstddef>

// Problem constants
#define CBB 8
#define CSS 4096
#define CDD 512
#define CLL 4
#define CDI 768
#define CFF 2048
#define CMM (CBB*CSS)          // 32768 rows
#define CNC 64                 // scan chunks
#define CCS (CSS/CNC)          // 64 per chunk

// weight scratch sizes (elements)
#define W_HG_SZ  ((size_t)CLL*2*CDI*CDD)
#define W_OUT_SZ ((size_t)CLL*CDD*CDI)
#define W_F1_SZ  ((size_t)CLL*CFF*CDD)
#define W_F2_SZ  ((size_t)CLL*CDD*CFF)

// GEMM tiling: CTA 128(M) x 128(N), 8 warps (2m x 4n), warp tile 64x32.
// fp16 m16n8k16. K staged 64 halves (128B rows, 8x16B chunks, swizzle c^(row&7)).
// 96KB smem + 128 regs => 2 CTAs per SM.
#define GMT 128
#define GNT 128
#define KC  64                           // halves per stage
#define NST 3
#define STG_A 16384
#define STG_B 16384
#define STG_BYTES (STG_A + STG_B)        // 32768
#define SMEM_DYN (NST*STG_BYTES)         // 98304
#define SPITCH 133                       // fused-scan smem pitch (bank spread)

// ---------------- scratch (device globals; no allocation allowed) ----------
static __device__ __align__(256) __half   g_xn [(size_t)CMM*CDD];   // LN out (fp16)
static __device__ __align__(256) __half2  g_av [(size_t)CMM*CDI];   // (a, v) pairs
static __device__ __align__(256) __half   g_h  [(size_t)CMM*CDI];   // scan out (fp16)
static __device__ __align__(256) float    g_y  [(size_t)CMM*CDD];   // residual (fp32)
static __device__ __align__(256) float    g_x  [(size_t)CMM*CDD];   // layer out (fp32)
static __device__ __align__(256) __half   g_ffh[(size_t)CMM*CFF];   // ff hidden (fp16)
static __device__ __align__(256) __half   g_wh [W_HG_SZ + W_OUT_SZ + W_F1_SZ + W_F2_SZ];
static __device__ __align__(256) float    g_P  [CBB*CNC*CDI];
static __device__ __align__(256) float    g_Hc [CBB*CNC*CDI];
static __device__ __align__(256) float    g_Cy [CBB*CNC*CDI];       // chunk carries

// ---------------- helpers ----------------------------------------------------
__device__ __forceinline__ uint32_t smem_u32(const void* p){
    uint32_t a;
    asm("{ .reg .u64 t; cvta.to.shared.u64 t, %1; cvt.u32.u64 %0, t; }"
        : "=r"(a) : "l"(p));
    return a;
}
__device__ __forceinline__ void cp16(uint32_t saddr, const void* g){
    asm volatile("cp.async.cg.shared.global [%0], [%1], 16;"
                 :: "r"(saddr), "l"(g) : "memory");
}
__device__ __forceinline__ void cp_commit(){
    asm volatile("cp.async.commit_group;" ::: "memory");
}
__device__ __forceinline__ void cp_wait1(){
    asm volatile("cp.async.wait_group 1;" ::: "memory");
}
__device__ __forceinline__ void cp_wait0(){
    asm volatile("cp.async.wait_group 0;" ::: "memory");
}
__device__ __forceinline__ void ldsm_x4(uint32_t& r0, uint32_t& r1, uint32_t& r2,
                                        uint32_t& r3, uint32_t addr){
    asm volatile("ldmatrix.sync.aligned.m8n8.x4.shared.b16 {%0,%1,%2,%3}, [%4];"
                 : "=r"(r0), "=r"(r1), "=r"(r2), "=r"(r3) : "r"(addr));
}
__device__ __forceinline__ void mma_f16(float (&d)[4], const uint32_t (&a)[4],
                                        const uint32_t (&b)[2]){
    asm volatile(
        "mma.sync.aligned.m16n8k16.row.col.f32.f16.f16.f32 "
        "{%0,%1,%2,%3}, {%4,%5,%6,%7}, {%8,%9}, {%0,%1,%2,%3};\n"
        : "+f"(d[0]), "+f"(d[1]), "+f"(d[2]), "+f"(d[3])
        : "r"(a[0]), "r"(a[1]), "r"(a[2]), "r"(a[3]), "r"(b[0]), "r"(b[1]));
}

enum { EPI_AV=0, EPI_ADD=1, EPI_BIAS_GELU=2, EPI_BIAS_ADD=3 };

// ---------------- weight prepass (single kernel) -----------------------------
// Part 1: permute+convert Whg (dst row 2e = hidden_e, 2e+1 = gate_e).
// Parts 2-4: straight fp32->fp16 conversion of the other weight blocks.
__global__ void wprep(const float* __restrict__ whg_src, __half* __restrict__ whg_dst,
                      const float4* __restrict__ s1, int n1,
                      const float4* __restrict__ s2, int n2,
                      const float4* __restrict__ s3, int n3,
                      __half* __restrict__ d1, __half* __restrict__ d2,
                      __half* __restrict__ d3)
{
    const int gid = blockIdx.x*blockDim.x + threadIdx.x;
    const int stride = gridDim.x*blockDim.x;
    const int perlayer = 2*CDI*CDD/8;                     // 98304
    for (int id = gid; id < CLL*perlayer; id += stride){
        const int l = id / perlayer, rem = id % perlayer;
        const int r = rem / (CDD/8), c8 = rem % (CDD/8);
        const int sr = (r & 1) ? (CDI + (r >> 1)) : (r >> 1);
        const float* s = whg_src + ((size_t)l*2*CDI + sr)*CDD + c8*8;
        __half h[8];
        #pragma unroll
        for (int j=0;j<8;j++) h[j] = __float2half_rn(s[j]);
        *reinterpret_cast<uint4*>(whg_dst + ((size_t)l*2*CDI + r)*CDD + c8*8) =
            *reinterpret_cast<uint4*>(h);
    }
    auto conv = [&](const float4* s, __half* d, int n4){
        for (int i=gid; i<n4; i+=stride){
            const float4 v = s[i];
            __half h[4] = {__float2half_rn(v.x), __float2half_rn(v.y),
                           __float2half_rn(v.z), __float2half_rn(v.w)};
            *reinterpret_cast<uint2*>(d + (size_t)i*4) =
                *reinterpret_cast<uint2*>(h);
        }
    };
    conv(s1, d1, n1); conv(s2, d2, n2); conv(s3, d3, n3);
}

// ---------------- GEMM fp16, compile-time shapes + hoisted addressing --------
// C[M,N] = A[M,K] @ W[N,K]^T, fp16 operands, fp32 accumulate.
// EPI_AV additionally performs the chunk-level scan reduction (phase 1) in
// smem and writes P/H.  (Thread/tile shape identical to the R13/R16 kernel;
// load_stage addressing strength-reduced to per-thread base + literals.)
template<int EPI, int NN, int KK>
__global__ __launch_bounds__(256, 2)
void gemm_h(const __half* __restrict__ A, const __half* __restrict__ W,
            const float* __restrict__ bias, const float* __restrict__ add,
            void* __restrict__ Cv, float* __restrict__ Pg, float* __restrict__ Hg)
{
    extern __shared__ __align__(1024) char smem[];
    const uint32_t sb = smem_u32(smem);
    const int tid  = threadIdx.x;
    const int lane = tid & 31;
    const int warp = tid >> 5;
    const int wm   = (warp >> 2) * 64;     // warp M offset (2 warps)
    const int wn   = (warp & 3) * 32;      // warp N offset (4 warps)
    const int g    = lane >> 2;
    const int t    = lane & 3;
    const int bm = blockIdx.y * GMT;
    const int bn = blockIdx.x * GNT;

    const int rowsel = lane & 7;
    const int rowA   = rowsel + ((lane >> 3) & 1) * 8;   // mats 0,1: m; 2,3: k+8
    const int chA    = (lane >> 4) & 1;
    const int rowB   = rowsel + ((lane >> 4) & 1) * 8;   // mats 2,3 -> n+8
    const int chB    = (lane >> 3) & 1;                  // mats 1,3 -> k+8

    // hoisted per-thread load addressing:
    //   row_i = (tid>>3) + 32*i, c = tid&7 (both stable mod 8 across i)
    const int r0 = tid >> 3;                         // 0..31
    const int c0 = tid & 7;
    const uint32_t soff0 = (uint32_t)((r0*8 + (c0 ^ (r0 & 7)))*16);
    const __half* aptr = A + (size_t)(bm + r0)*KK + c0*8;
    const __half* wptr = W + (size_t)(bn + r0)*KK + c0*8;

    float acc[4][4][4];
    #pragma unroll
    for (int i=0;i<4;i++)
        #pragma unroll
        for (int j=0;j<4;j++)
            #pragma unroll
            for (int k=0;k<4;k++) acc[i][j][k] = 0.0f;

    auto load_stage = [&](int s, int slot){
        const uint32_t sA = sb + (uint32_t)(slot*STG_BYTES);
        const __half* ap = aptr + (size_t)s*KC;
        const __half* bp = wptr + (size_t)s*KC;
        #pragma unroll
        for (int i=0;i<4;i++)                        // A: 1024 chunks
            cp16(sA + soff0 + (uint32_t)(i*4096), ap + (size_t)i*32*KK);
        #pragma unroll
        for (int i=0;i<4;i++)                        // B: 1024 chunks
            cp16(sA + STG_A + soff0 + (uint32_t)(i*4096), bp + (size_t)i*32*KK);
    };

    auto compute = [&](int slot){
        const uint32_t sA = sb + (uint32_t)(slot*STG_BYTES);
        const uint32_t sB = sA + STG_A;
        #pragma unroll
        for (int slab=0; slab<4; slab++){            // 4 x (K=16) per stage
            const uint32_t ab = sA +
                (uint32_t)((wm + rowA)*8 + (((slab<<1)|chA) ^ rowsel))*16u;
            const uint32_t bb = sB +
                (uint32_t)((wn + rowB)*8 + (((slab<<1)|chB) ^ rowsel))*16u;
            uint32_t Bf[4][2];
            #pragma unroll
            for (int n2=0; n2<2; n2++)
                ldsm_x4(Bf[2*n2][0], Bf[2*n2][1], Bf[2*n2+1][0], Bf[2*n2+1][1],
                        bb + n2*2048);
            #pragma unroll
            for (int ms=0; ms<4; ms++){
                uint32_t a[4];
                ldsm_x4(a[0], a[1], a[2], a[3], ab + ms*2048);
                #pragma unroll
                for (int ns=0; ns<4; ns++)
                    mma_f16(acc[ms][ns], a, Bf[ns]);
            }
        }
    };

    constexpr int nk = KK / KC;                      // 8 / 12 / 32
    load_stage(0, 0); cp_commit();
    load_stage(1, 1); cp_commit();
    #pragma unroll 1
    for (int base = 0; base < nk; base += 3){
        // step kt = base (slot 0)
        cp_wait1(); __syncthreads();
        if (base+2 < nk) load_stage(base+2, 2);
        cp_commit();
        compute(0);
        if (base+1 < nk){                            // kt = base+1 (slot 1)
            cp_wait1(); __syncthreads();
            if (base+3 < nk) load_stage(base+3, 0);
            cp_commit();
            compute(1);
        }
        if (base+2 < nk){                            // kt = base+2 (slot 2)
            cp_wait1(); __syncthreads();
            if (base+4 < nk) load_stage(base+4, 1);
            cp_commit();
            compute(2);
        }
    }
    cp_wait0();

    // ---------------- epilogue ----------------
    if constexpr (EPI == EPI_AV){
        __syncthreads();
        float* sa = reinterpret_cast<float*>(smem);
        float* sv = sa + 64*SPITCH;
        #pragma unroll
        for (int ms=0; ms<4; ms++){
            #pragma unroll
            for (int ns=0; ns<4; ns++){
                const int cp = (wn >> 1) + ns*4 + t;        // 0..63
                #pragma unroll
                for (int hh=0; hh<2; hh++){
                    const int rl = wm + ms*16 + g + 8*hh;   // 0..127
                    const float hid = acc[ms][ns][hh*2+0];
                    const float gt  = acc[ms][ns][hh*2+1];
                    const float sg = 1.0f / (1.0f + __expf(-gt));
                    const float a  = 1.0f - sg;
                    float gv;
                    if (hid >= 0.0f) gv = hid + 0.5f;
                    else { const float u = __expf(hid); gv = u / (1.0f + u); }
                    const __half2 pair = __floats2half2_rn(a, sg * gv);
                    reinterpret_cast<__half2*>(Cv)[
                        (size_t)(bm+rl)*(NN>>1) + (bn>>1) + cp] = pair;
                    const float2 fr = __half22float2(pair);
                    sa[cp*SPITCH + rl] = fr.x;
                    sv[cp*SPITCH + rl] = fr.y;
                }
            }
        }
        __syncthreads();
        if (tid < 128){
            const int chunk = tid >> 6, cp = tid & 63;
            const float* pa = sa + cp*SPITCH + chunk*64;
            const float* pv = sv + cp*SPITCH + chunk*64;
            float p = 1.0f, h = 0.0f;
            #pragma unroll 8
            for (int s=0; s<CCS; s++){
                const float a = pa[s], v = pv[s];
                h = fmaf(a, h, v);
                p *= a;
            }
            const int b = bm >> 12;
            const int c = ((bm & 4095) >> 6) + chunk;
            const int e = (bn >> 1) + cp;
            const int idx = (b*CNC + c)*CDI + e;
            Pg[idx] = p; Hg[idx] = h;
        }
    } else {
        #pragma unroll
        for (int ms=0; ms<4; ms++){
            const int rr = bm + wm + ms*16 + g;
            #pragma unroll
            for (int ns=0; ns<4; ns++){
                const int cc = bn + wn + ns*8 + 2*t;     // even
                float v[4] = {acc[ms][ns][0], acc[ms][ns][1],
                              acc[ms][ns][2], acc[ms][ns][3]};
                const int rows[2] = {rr, rr+8};
                #pragma unroll
                for (int h=0; h<2; h++){
                    const int row = rows[h];
                    if constexpr (EPI == EPI_ADD){
                        float* C = reinterpret_cast<float*>(Cv);
                        const float2 a2 = *reinterpret_cast<const float2*>(
                            add + (size_t)row*NN + cc);
                        *reinterpret_cast<float2*>(C + (size_t)row*NN + cc) =
                            make_float2(v[h*2+0] + a2.x, v[h*2+1] + a2.y);
                    } else if constexpr (EPI == EPI_BIAS_GELU){
                        float v0 = v[h*2+0] + bias[cc];
                        float v1 = v[h*2+1] + bias[cc+1];
                        v0 = 0.5f*v0*(1.0f + erff(v0 * 0.70710678118654752f));
                        v1 = 0.5f*v1*(1.0f + erff(v1 * 0.70710678118654752f));
                        __half* C = reinterpret_cast<__half*>(Cv);
                        *reinterpret_cast<__half2*>(C + (size_t)row*NN + cc) =
                            __floats2half2_rn(v0, v1);
                    } else {   // EPI_BIAS_ADD
                        float* C = reinterpret_cast<float*>(Cv);
                        const float2 a2 = *reinterpret_cast<const float2*>(
                            add + (size_t)row*NN + cc);
                        *reinterpret_cast<float2*>(C + (size_t)row*NN + cc) =
                            make_float2(v[h*2+0] + bias[cc]   + a2.x,
                                        v[h*2+1] + bias[cc+1] + a2.y);
                    }
                }
            }
        }
    }
}

// ---------------- layernorm (D=512), 2 rows/warp (MLP 8), fp16 out -----------
__global__ void ln_warp(const float* __restrict__ x, const float* __restrict__ gw,
                        const float* __restrict__ bw, __half* __restrict__ y)
{
    const int warp = threadIdx.x >> 5, lane = threadIdx.x & 31;
    const int row0 = blockIdx.x*16 + warp*2;
    float4 v[2][4];
    float s0=0.f, q0=0.f, s1=0.f, q1=0.f;
    {
        const float4* xr0 = reinterpret_cast<const float4*>(x + (size_t)row0*CDD);
        const float4* xr1 = reinterpret_cast<const float4*>(x + (size_t)(row0+1)*CDD);
        #pragma unroll
        for (int j=0;j<4;j++){
            v[0][j] = xr0[lane + j*32];
            v[1][j] = xr1[lane + j*32];
        }
        #pragma unroll
        for (int j=0;j<4;j++){
            s0 += (v[0][j].x+v[0][j].y)+(v[0][j].z+v[0][j].w);
            q0 += v[0][j].x*v[0][j].x + v[0][j].y*v[0][j].y
                + v[0][j].z*v[0][j].z + v[0][j].w*v[0][j].w;
            s1 += (v[1][j].x+v[1][j].y)+(v[1][j].z+v[1][j].w);
            q1 += v[1][j].x*v[1][j].x + v[1][j].y*v[1][j].y
                + v[1][j].z*v[1][j].z + v[1][j].w*v[1][j].w;
        }
    }
    #pragma unroll
    for (int o=16;o>0;o>>=1){
        s0 += __shfl_xor_sync(0xffffffffu,s0,o);
        q0 += __shfl_xor_sync(0xffffffffu,q0,o);
        s1 += __shfl_xor_sync(0xffffffffu,s1,o);
        q1 += __shfl_xor_sync(0xffffffffu,q1,o);
    }
    const float m0 = s0*(1.0f/CDD), r0 = rsqrtf(q0*(1.0f/CDD) - m0*m0 + 1e-5f);
    const float m1 = s1*(1.0f/CDD), r1 = rsqrtf(q1*(1.0f/CDD) - m1*m1 + 1e-5f);
    const float4* gr = reinterpret_cast<const float4*>(gw);
    const float4* br = reinterpret_cast<const float4*>(bw);
    uint2* y0 = reinterpret_cast<uint2*>(y + (size_t)row0*CDD);
    uint2* y1 = reinterpret_cast<uint2*>(y + (size_t)(row0+1)*CDD);
    #pragma unroll
    for (int j=0;j<4;j++){
        const float4 gg = gr[lane + j*32];
        const float4 bb = br[lane + j*32];
        {
            const __half2 h0 = __floats2half2_rn((v[0][j].x-m0)*r0*gg.x + bb.x,
                                                 (v[0][j].y-m0)*r0*gg.y + bb.y);
            const __half2 h1 = __floats2half2_rn((v[0][j].z-m0)*r0*gg.z + bb.z,
                                                 (v[0][j].w-m0)*r0*gg.w + bb.w);
            uint2 u;
            u.x = *reinterpret_cast<const uint32_t*>(&h0);
            u.y = *reinterpret_cast<const uint32_t*>(&h1);
            y0[lane + j*32] = u;
        }
        {
            const __half2 h0 = __floats2half2_rn((v[1][j].x-m1)*r1*gg.x + bb.x,
                                                 (v[1][j].y-m1)*r1*gg.y + bb.y);
            const __half2 h1 = __floats2half2_rn((v[1][j].z-m1)*r1*gg.z + bb.z,
                                                 (v[1][j].w-m1)*r1*gg.w + bb.w);
            uint2 u;
            u.x = *reinterpret_cast<const uint32_t*>(&h0);
            u.y = *reinterpret_cast<const uint32_t*>(&h1);
            y1[lane + j*32] = u;
        }
    }
}

// ---------------- carry kernel: chunk prefix ---------------------------------
__global__ void carry_k(const float* __restrict__ P, const float* __restrict__ H,
                        float* __restrict__ Cy)
{
    const int i = blockIdx.x*256 + threadIdx.x;          // 0..CBB*CDI-1
    if (i >= CBB*CDI) return;
    const int b = i / CDI, e = i % CDI;
    float T = 0.5f;                                      // h_0
    #pragma unroll 8
    for (int c=0; c<CNC; c++){
        const int idx = (b*CNC + c)*CDI + e;
        Cy[idx] = T;
        T = fmaf(P[idx], T, H[idx]);
    }
}

// ---------------- scan phase 3 (pure streaming; carry precomputed) -----------
__global__ void scan_phase3(const uint2* __restrict__ av, const float* __restrict__ Cy,
                            __half* __restrict__ hout)
{
    const int e2 = blockIdx.x*128 + threadIdx.x;
    const int c = blockIdx.y, b = blockIdx.z;
    const float2 cv = *reinterpret_cast<const float2*>(
        Cy + (b*CNC + c)*CDI + 2*e2);
    float h0 = cv.x, h1 = cv.y;
    const uint2* base = av + (size_t)(b*CSS + c*CCS)*(CDI/2) + e2;
    __half2* ob = reinterpret_cast<__half2*>(
        hout + (size_t)(b*CSS + c*CCS)*CDI + 2*e2);
    #pragma unroll 8
    for (int s=0; s<CCS; s++){
        const uint2 u = base[(size_t)s*(CDI/2)];
        const float2 f0 = __half22float2(*reinterpret_cast<const __half2*>(&u.x));
        const float2 f1 = __half22float2(*reinterpret_cast<const __half2*>(&u.y));
        h0 = fmaf(f0.x, h0, f0.y);
        h1 = fmaf(f1.x, h1, f1.y);
        ob[(size_t)s*(CDI/2)] = __floats2half2_rn(h0, h1);
    }
}

// ---------------- final LN + 2-logit head, 2 rows/warp -----------------------
__global__ void logits_warp(const float* __restrict__ x, const float* __restrict__ gw,
                            const float* __restrict__ bw, const float* __restrict__ Wl,
                            float* __restrict__ out)
{
    const int warp = threadIdx.x >> 5, lane = threadIdx.x & 31;
    const int row0 = blockIdx.x*16 + warp*2;
    float4 v[2][4];
    float s0=0.f, q0=0.f, s1=0.f, q1=0.f;
    {
        const float4* xr0 = reinterpret_cast<const float4*>(x + (size_t)row0*CDD);
        const float4* xr1 = reinterpret_cast<const float4*>(x + (size_t)(row0+1)*CDD);
        #pragma unroll
        for (int j=0;j<4;j++){
            v[0][j] = xr0[lane + j*32];
            v[1][j] = xr1[lane + j*32];
        }
        #pragma unroll
        for (int j=0;j<4;j++){
            s0 += (v[0][j].x+v[0][j].y)+(v[0][j].z+v[0][j].w);
            q0 += v[0][j].x*v[0][j].x + v[0][j].y*v[0][j].y
                + v[0][j].z*v[0][j].z + v[0][j].w*v[0][j].w;
            s1 += (v[1][j].x+v[1][j].y)+(v[1][j].z+v[1][j].w);
            q1 += v[1][j].x*v[1][j].x + v[1][j].y*v[1][j].y
                + v[1][j].z*v[1][j].z + v[1][j].w*v[1][j].w;
        }
    }
    #pragma unroll
    for (int o=16;o>0;o>>=1){
        s0 += __shfl_xor_sync(0xffffffffu,s0,o);
        q0 += __shfl_xor_sync(0xffffffffu,q0,o);
        s1 += __shfl_xor_sync(0xffffffffu,s1,o);
        q1 += __shfl_xor_sync(0xffffffffu,q1,o);
    }
    const float m0 = s0*(1.0f/CDD), r0 = rsqrtf(q0*(1.0f/CDD) - m0*m0 + 1e-5f);
    const float m1 = s1*(1.0f/CDD), r1 = rsqrtf(q1*(1.0f/CDD) - m1*m1 + 1e-5f);

    const float4* gr = reinterpret_cast<const float4*>(gw);
    const float4* br = reinterpret_cast<const float4*>(bw);
    const float4* w0 = reinterpret_cast<const float4*>(Wl);
    const float4* w1 = reinterpret_cast<const float4*>(Wl + CDD);
    float a0 = 0.f, a1 = 0.f, b0 = 0.f, b1 = 0.f;
    #pragma unroll
    for (int j=0;j<4;j++){
        const int idx = lane + j*32;
        const float4 gg = gr[idx], bb = br[idx];
        const float4 wa = w0[idx], wb = w1[idx];
        {
            const float n0 = (v[0][j].x-m0)*r0*gg.x + bb.x;
            const float n1 = (v[0][j].y-m0)*r0*gg.y + bb.y;
            const float n2 = (v[0][j].z-m0)*r0*gg.z + bb.z;
            const float n3 = (v[0][j].w-m0)*r0*gg.w + bb.w;
            a0 += n0*wa.x + n1*wa.y + n2*wa.z + n3*wa.w;
            a1 += n0*wb.x + n1*wb.y + n2*wb.z + n3*wb.w;
        }
        {
            const float n0 = (v[1][j].x-m1)*r1*gg.x + bb.x;
            const float n1 = (v[1][j].y-m1)*r1*gg.y + bb.y;
            const float n2 = (v[1][j].z-m1)*r1*gg.z + bb.z;
            const float n3 = (v[1][j].w-m1)*r1*gg.w + bb.w;
            b0 += n0*wa.x + n1*wa.y + n2*wa.z + n3*wa.w;
            b1 += n0*wb.x + n1*wb.y + n2*wb.z + n3*wb.w;
        }
    }
    #pragma unroll
    for (int o=16;o>0;o>>=1){
        a0 += __shfl_xor_sync(0xffffffffu,a0,o);
        a1 += __shfl_xor_sync(0xffffffffu,a1,o);
        b0 += __shfl_xor_sync(0xffffffffu,b0,o);
        b1 += __shfl_xor_sync(0xffffffffu,b1,o);
    }
    if (lane == 0){
        out[(size_t)row0*2 + 0] = a0;
        out[(size_t)row0*2 + 1] = a1;
        out[(size_t)(row0+1)*2 + 0] = b0;
        out[(size_t)(row0+1)*2 + 1] = b1;
    }
}

// ---------------- driver ----------------------------------------------------
extern "C" void kernel_launch(void* const* d_in, const int* in_sizes, int n_in,
                              void* d_out, int out_size)
{
    const float* input  = (const float*)d_in[0];
    const float* Whg    = (const float*)d_in[1];
    const float* Wout   = (const float*)d_in[2];
    const float* ln1_g  = (const float*)d_in[3];
    const float* ln1_b  = (const float*)d_in[4];
    const float* ln2_g  = (const float*)d_in[5];
    const float* ln2_b  = (const float*)d_in[6];
    const float* ffW1   = (const float*)d_in[7];
    const float* ffb1   = (const float*)d_in[8];
    const float* ffW2   = (const float*)d_in[9];
    const float* ffb2   = (const float*)d_in[10];
    const float* norm_g = (const float*)d_in[11];
    const float* norm_b = (const float*)d_in[12];
    const float* Wlog   = (const float*)d_in[13];
    float* out = (float*)d_out;

    __half *xn, *h, *ffh, *wh; __half2 *av; float *y, *x, *P, *Hc, *Cy;
    cudaGetSymbolAddress((void**)&xn,  g_xn);
    cudaGetSymbolAddress((void**)&av,  g_av);
    cudaGetSymbolAddress((void**)&h,   g_h);
    cudaGetSymbolAddress((void**)&y,   g_y);
    cudaGetSymbolAddress((void**)&x,   g_x);
    cudaGetSymbolAddress((void**)&ffh, g_ffh);
    cudaGetSymbolAddress((void**)&P,   g_P);
    cudaGetSymbolAddress((void**)&Hc,  g_Hc);
    cudaGetSymbolAddress((void**)&Cy,  g_Cy);
    cudaGetSymbolAddress((void**)&wh,  g_wh);

    __half* w_hg  = wh;
    __half* w_out = w_hg  + W_HG_SZ;
    __half* w_f1  = w_out + W_OUT_SZ;
    __half* w_f2  = w_f1  + W_F1_SZ;

    cudaFuncSetAttribute(gemm_h<EPI_AV, 2*CDI, CDD>,
        cudaFuncAttributeMaxDynamicSharedMemorySize, SMEM_DYN);
    cudaFuncSetAttribute(gemm_h<EPI_ADD, CDD, CDI>,
        cudaFuncAttributeMaxDynamicSharedMemorySize, SMEM_DYN);
    cudaFuncSetAttribute(gemm_h<EPI_BIAS_GELU, CFF, CDD>,
        cudaFuncAttributeMaxDynamicSharedMemorySize, SMEM_DYN);
    cudaFuncSetAttribute(gemm_h<EPI_BIAS_ADD, CDD, CFF>,
        cudaFuncAttributeMaxDynamicSharedMemorySize, SMEM_DYN);

    // weight prepass (1 launch)
    wprep<<<3072, 256>>>(Whg, w_hg,
                         (const float4*)Wout, (int)(W_OUT_SZ/4),
                         (const float4*)ffW1, (int)(W_F1_SZ/4),
                         (const float4*)ffW2, (int)(W_F2_SZ/4),
                         w_out, w_f1, w_f2);

    const int M = CMM;
    const dim3 scan_grid(3, CNC, CBB);   // 384 uint2 lanes / 128 thr = 3

    for (int i=0; i<CLL; i++){
        const float* cur = (i==0) ? input : x;

        ln_warp<<<M/16, 256>>>(cur, ln1_g + i*CDD, ln1_b + i*CDD, xn);
        // hg GEMM: fused gates + chunk-scan (phase 1) -> av, P, Hc
        gemm_h<EPI_AV, 2*CDI, CDD><<<dim3(2*CDI/GNT, M/GMT), 256, SMEM_DYN>>>(
            xn, w_hg + (size_t)i*2*CDI*CDD, nullptr, nullptr, av, P, Hc);
        carry_k<<<24, 256>>>(P, Hc, Cy);
        scan_phase3<<<scan_grid, 128>>>((const uint2*)av, Cy, h);
        gemm_h<EPI_ADD, CDD, CDI><<<dim3(CDD/GNT, M/GMT), 256, SMEM_DYN>>>(
            h, w_out + (size_t)i*CDD*CDI, nullptr, cur, y, nullptr, nullptr);
        ln_warp<<<M/16, 256>>>(y, ln2_g + i*CDD, ln2_b + i*CDD, xn);
        gemm_h<EPI_BIAS_GELU, CFF, CDD><<<dim3(CFF/GNT, M/GMT), 256, SMEM_DYN>>>(
            xn, w_f1 + (size_t)i*CFF*CDD, ffb1 + i*CFF, nullptr, ffh, nullptr, nullptr);
        gemm_h<EPI_BIAS_ADD, CDD, CFF><<<dim3(CDD/GNT, M/GMT), 256, SMEM_DYN>>>(
            ffh, w_f2 + (size_t)i*CDD*CFF, ffb2 + i*CDD, y, x, nullptr, nullptr);
    }

    logits_warp<<<M/16, 256>>>(x, norm_g, norm_b, Wlog, out);
}